// round 2
// baseline (speedup 1.0000x reference)
#include <cuda_runtime.h>
#include <cstddef>

// Problem constants
constexpr int B_  = 2;
constexpr int S_  = 2048;
constexpr int H_  = 1024;
constexpr int NH_ = 16;
constexpr int HD_ = 64;
constexpr int M_  = B_ * S_;   // 4096 rows for all projections

// Scratch (allocation-free: __device__ globals)
__device__ float g_q[(size_t)M_ * H_];
__device__ float g_k[(size_t)M_ * H_];
__device__ float g_v[(size_t)M_ * H_];
__device__ float g_ctx[(size_t)M_ * H_];
__device__ unsigned char g_mask[B_ * S_];

// ---------------------------------------------------------------------------
// Mask normalization: detect the storage dtype of key_padding_mask at runtime
// and expand to canonical uint8. One block, 1024 threads.
// Safe read set: first 1024 words = 4096 bytes = minimum possible buffer size.
// ---------------------------------------------------------------------------
__global__ void mask_normalize(const unsigned int* __restrict__ w)
{
    __shared__ unsigned int flags;
    const int tid = threadIdx.x;
    if (tid == 0) flags = 0u;
    __syncthreads();

    const unsigned int x = w[tid];
    unsigned int f = 0u;
    if (x != 0u && x != 1u && x != 0x3F800000u) f |= 1u;  // packed-byte signature
    if (x == 0x3F800000u) f |= 2u;                        // float32 1.0
    if (f) atomicOr(&flags, f);
    __syncthreads();

    const unsigned int fl = flags;
    // mode 0: 1-byte bool; mode 1: 4-byte (int32 or float32) — nonzero test is
    // bitwise so int32 and float32 share a path.
    const int byte_mode = (fl & 1u) ? 1 : 0;

    if (byte_mode) {
        const unsigned char* b8 = (const unsigned char*)w;
        for (int i = tid; i < B_ * S_; i += 1024)
            g_mask[i] = (b8[i] != 0);
    } else {
        for (int i = tid; i < B_ * S_; i += 1024)
            g_mask[i] = (w[i] != 0u);
    }
    (void)fl;
}

// ---------------------------------------------------------------------------
// SGEMM (NT): C[M,N] = A[M,K] @ W[N,K]^T + bias[N]
// 128x128 tile, BK=8, 256 threads, 8x8 per thread.
// ---------------------------------------------------------------------------
__global__ __launch_bounds__(256) void sgemm_nt_bias(
    const float* __restrict__ A, const float* __restrict__ W,
    const float* __restrict__ bias, float* __restrict__ C,
    int M, int N, int K)
{
    constexpr int BM = 128, BN = 128, BK = 8;
    __shared__ float As[BK][BM];
    __shared__ float Bs[BK][BN];

    const int tid = threadIdx.x;
    const int m0 = blockIdx.y * BM;
    const int n0 = blockIdx.x * BN;
    const int ty = tid >> 4;       // 0..15
    const int tx = tid & 15;       // 0..15
    const int lr = tid >> 1;       // 0..127 (load row)
    const int lc = (tid & 1) * 4;  // 0 or 4 (load col within BK)

    float acc[8][8];
    #pragma unroll
    for (int i = 0; i < 8; i++)
        #pragma unroll
        for (int j = 0; j < 8; j++) acc[i][j] = 0.0f;

    for (int k0 = 0; k0 < K; k0 += BK) {
        const float4 av = *(const float4*)&A[(size_t)(m0 + lr) * K + k0 + lc];
        const float4 wv = *(const float4*)&W[(size_t)(n0 + lr) * K + k0 + lc];
        __syncthreads();
        As[lc + 0][lr] = av.x; As[lc + 1][lr] = av.y;
        As[lc + 2][lr] = av.z; As[lc + 3][lr] = av.w;
        Bs[lc + 0][lr] = wv.x; Bs[lc + 1][lr] = wv.y;
        Bs[lc + 2][lr] = wv.z; Bs[lc + 3][lr] = wv.w;
        __syncthreads();

        #pragma unroll
        for (int kk = 0; kk < BK; kk++) {
            float a[8], b[8];
            *(float4*)&a[0] = *(const float4*)&As[kk][ty * 8];
            *(float4*)&a[4] = *(const float4*)&As[kk][ty * 8 + 4];
            *(float4*)&b[0] = *(const float4*)&Bs[kk][tx * 8];
            *(float4*)&b[4] = *(const float4*)&Bs[kk][tx * 8 + 4];
            #pragma unroll
            for (int i = 0; i < 8; i++)
                #pragma unroll
                for (int j = 0; j < 8; j++)
                    acc[i][j] += a[i] * b[j];
        }
    }

    #pragma unroll
    for (int i = 0; i < 8; i++) {
        const int m = m0 + ty * 8 + i;
        #pragma unroll
        for (int j = 0; j < 8; j += 4) {
            const int n = n0 + tx * 8 + j;
            float4 o;
            o.x = acc[i][j + 0] + bias[n + 0];
            o.y = acc[i][j + 1] + bias[n + 1];
            o.z = acc[i][j + 2] + bias[n + 2];
            o.w = acc[i][j + 3] + bias[n + 3];
            *(float4*)&C[(size_t)m * N + n] = o;
        }
    }
}

// ---------------------------------------------------------------------------
// Flash-style attention with additive bias and key-padding mask.
// grid = (S/64, NH, B), block = 256 threads.
// q/k/v in [B,S,H] layout (head h occupies columns h*64..h*64+63).
// ctx written back in [B,S,H] layout.
// ---------------------------------------------------------------------------
constexpr int BQ = 64;
constexpr int BKT = 64;
// smem floats: Qs 4096 + Ks 4096 + Vs 4096 + Ps 64*65 + m/l/alpha 192
constexpr int ATTN_SMEM_FLOATS = 4096 * 3 + 64 * 65 + 192;
constexpr int ATTN_SMEM_BYTES = ATTN_SMEM_FLOATS * 4;

__global__ __launch_bounds__(256) void attn_kernel(
    const float* __restrict__ q, const float* __restrict__ k,
    const float* __restrict__ v, const unsigned char* __restrict__ kpm,
    const float* __restrict__ bias, float* __restrict__ ctx)
{
    extern __shared__ float sm[];
    float* Qs   = sm;                    // [d][q]  (transposed), 64x64
    float* Ks   = sm + 4096;             // [d][k]  (transposed), 64x64
    float* Vs   = sm + 8192;             // [k][d]  natural, 64x64
    float* Ps   = sm + 12288;            // [k][q]  padded stride 65
    float* mrow = sm + 12288 + 64 * 65;  // [64]
    float* lrow = mrow + 64;             // [64]
    float* arow = lrow + 64;             // [64]

    const int tid = threadIdx.x;
    const int q0 = blockIdx.x * BQ;
    const int h  = blockIdx.y;
    const int b  = blockIdx.z;
    const float scale = 0.125f;  // 1/sqrt(64)

    // Load Q tile (scaled) transposed into Qs[d][q]
    {
        const int r = tid >> 2;            // query row 0..63
        const int c = (tid & 3) * 16;      // d base
        const float* gq = &q[((size_t)(b * S_ + q0 + r)) * H_ + h * HD_];
        #pragma unroll
        for (int u = 0; u < 4; u++) {
            const float4 val = *(const float4*)&gq[c + u * 4];
            Qs[(c + u * 4 + 0) * 64 + r] = val.x * scale;
            Qs[(c + u * 4 + 1) * 64 + r] = val.y * scale;
            Qs[(c + u * 4 + 2) * 64 + r] = val.z * scale;
            Qs[(c + u * 4 + 3) * 64 + r] = val.w * scale;
        }
    }
    if (tid < 64) { mrow[tid] = -1e30f; lrow[tid] = 0.0f; }

    float acc[4][4];
    #pragma unroll
    for (int i = 0; i < 4; i++)
        #pragma unroll
        for (int j = 0; j < 4; j++) acc[i][j] = 0.0f;

    const int ty = tid >> 4;   // 0..15 (query group)
    const int tx = tid & 15;   // 0..15 (key group / d group)

    for (int kt = 0; kt < S_ / BKT; kt++) {
        const int k0 = kt * BKT;
        __syncthreads();  // protect Ks/Vs overwrite vs previous iteration reads

        // Load K (transposed) and V (natural)
        {
            const int r = tid >> 2;
            const int c = (tid & 3) * 16;
            const float* gk = &k[((size_t)(b * S_ + k0 + r)) * H_ + h * HD_];
            const float* gv = &v[((size_t)(b * S_ + k0 + r)) * H_ + h * HD_];
            #pragma unroll
            for (int u = 0; u < 4; u++) {
                const float4 kv = *(const float4*)&gk[c + u * 4];
                Ks[(c + u * 4 + 0) * 64 + r] = kv.x;
                Ks[(c + u * 4 + 1) * 64 + r] = kv.y;
                Ks[(c + u * 4 + 2) * 64 + r] = kv.z;
                Ks[(c + u * 4 + 3) * 64 + r] = kv.w;
                const float4 vv = *(const float4*)&gv[c + u * 4];
                *(float4*)&Vs[r * 64 + c + u * 4] = vv;
            }
        }
        __syncthreads();

        // Scores: s[i][j] = sum_d Qs[d][ty*4+i] * Ks[d][tx*4+j]
        float s[4][4];
        #pragma unroll
        for (int i = 0; i < 4; i++)
            #pragma unroll
            for (int j = 0; j < 4; j++) s[i][j] = 0.0f;

        #pragma unroll 16
        for (int d = 0; d < 64; d++) {
            float qa[4], ka[4];
            *(float4*)&qa[0] = *(const float4*)&Qs[d * 64 + ty * 4];
            *(float4*)&ka[0] = *(const float4*)&Ks[d * 64 + tx * 4];
            #pragma unroll
            for (int i = 0; i < 4; i++)
                #pragma unroll
                for (int j = 0; j < 4; j++)
                    s[i][j] += qa[i] * ka[j];
        }

        // bias + mask, store transposed into Ps[k][q]
        #pragma unroll
        for (int i = 0; i < 4; i++) {
            const int qg = q0 + ty * 4 + i;
            const float4 bv =
                *(const float4*)&bias[((size_t)h * S_ + qg) * S_ + k0 + tx * 4];
            const float bb[4] = {bv.x, bv.y, bv.z, bv.w};
            #pragma unroll
            for (int j = 0; j < 4; j++) {
                const int kg = k0 + tx * 4 + j;
                float sc = s[i][j] + bb[j];
                if (kpm[b * S_ + kg]) sc = -1e30f;
                Ps[(tx * 4 + j) * 65 + (ty * 4 + i)] = sc;
            }
        }
        __syncthreads();

        // per-row max + alpha
        if (tid < 64) {
            const float mold = mrow[tid];
            float tmax = mold;
            #pragma unroll 8
            for (int kk = 0; kk < 64; kk++)
                tmax = fmaxf(tmax, Ps[kk * 65 + tid]);
            mrow[tid] = tmax;
            arow[tid] = __expf(mold - tmax);
        }
        __syncthreads();

        // exponentiate in place
        {
            const int kk = tid >> 2;
            const int qb = (tid & 3) * 16;
            #pragma unroll
            for (int u = 0; u < 16; u++) {
                const int qq = qb + u;
                Ps[kk * 65 + qq] = __expf(Ps[kk * 65 + qq] - mrow[qq]);
            }
        }
        __syncthreads();

        // l update + rescale acc + PV accumulate
        if (tid < 64) {
            float s2 = 0.0f;
            #pragma unroll 8
            for (int kk = 0; kk < 64; kk++) s2 += Ps[kk * 65 + tid];
            lrow[tid] = lrow[tid] * arow[tid] + s2;
        }
        #pragma unroll
        for (int i = 0; i < 4; i++) {
            const float al = arow[ty * 4 + i];
            #pragma unroll
            for (int j = 0; j < 4; j++) acc[i][j] *= al;
        }
        #pragma unroll 8
        for (int kk = 0; kk < 64; kk++) {
            float vv[4];
            *(float4*)&vv[0] = *(const float4*)&Vs[kk * 64 + tx * 4];
            float pr[4];
            #pragma unroll
            for (int i = 0; i < 4; i++) pr[i] = Ps[kk * 65 + ty * 4 + i];
            #pragma unroll
            for (int i = 0; i < 4; i++)
                #pragma unroll
                for (int j = 0; j < 4; j++)
                    acc[i][j] += pr[i] * vv[j];
        }
    }

    __syncthreads();  // lrow final values visible to all threads

    #pragma unroll
    for (int i = 0; i < 4; i++) {
        const int qg = q0 + ty * 4 + i;
        const float inv = 1.0f / fmaxf(lrow[ty * 4 + i], 1e-6f);
        float4 o;
        o.x = acc[i][0] * inv;
        o.y = acc[i][1] * inv;
        o.z = acc[i][2] * inv;
        o.w = acc[i][3] * inv;
        *(float4*)&ctx[((size_t)(b * S_ + qg)) * H_ + h * HD_ + tx * 4] = o;
    }
}

// ---------------------------------------------------------------------------
// Launch
// ---------------------------------------------------------------------------
extern "C" void kernel_launch(void* const* d_in, const int* in_sizes, int n_in,
                              void* d_out, int out_size)
{
    (void)in_sizes; (void)n_in; (void)out_size;

    const float* query = (const float*)d_in[0];
    const float* key_t = (const float*)d_in[1];
    const float* value = (const float*)d_in[2];
    const unsigned int* kpm_raw = (const unsigned int*)d_in[3];
    const float* bias  = (const float*)d_in[4];
    const float* q_w = (const float*)d_in[5];
    const float* q_b = (const float*)d_in[6];
    const float* k_w = (const float*)d_in[7];
    const float* k_b = (const float*)d_in[8];
    const float* v_w = (const float*)d_in[9];
    const float* v_b = (const float*)d_in[10];
    const float* o_w = (const float*)d_in[11];
    const float* o_b = (const float*)d_in[12];
    float* out = (float*)d_out;

    float *gq, *gk, *gv, *gctx;
    unsigned char* gmask;
    cudaGetSymbolAddress((void**)&gq, g_q);
    cudaGetSymbolAddress((void**)&gk, g_k);
    cudaGetSymbolAddress((void**)&gv, g_v);
    cudaGetSymbolAddress((void**)&gctx, g_ctx);
    cudaGetSymbolAddress((void**)&gmask, g_mask);

    cudaFuncSetAttribute(attn_kernel,
                         cudaFuncAttributeMaxDynamicSharedMemorySize,
                         ATTN_SMEM_BYTES);

    mask_normalize<<<1, 1024>>>(kpm_raw);

    const dim3 gemm_grid(H_ / 128, M_ / 128);  // (8, 32)
    sgemm_nt_bias<<<gemm_grid, 256>>>(query, q_w, q_b, gq, M_, H_, H_);
    sgemm_nt_bias<<<gemm_grid, 256>>>(key_t, k_w, k_b, gk, M_, H_, H_);
    sgemm_nt_bias<<<gemm_grid, 256>>>(value, v_w, v_b, gv, M_, H_, H_);

    attn_kernel<<<dim3(S_ / BQ, NH_, B_), 256, ATTN_SMEM_BYTES>>>(
        gq, gk, gv, gmask, bias, gctx);

    sgemm_nt_bias<<<gemm_grid, 256>>>(gctx, o_w, o_b, out, M_, H_, H_);
}

// round 4
// speedup vs baseline: 1.2752x; 1.2752x over previous
#include <cuda_runtime.h>
#include <cuda_bf16.h>
#include <cstdint>
#include <cstddef>

// Problem constants
constexpr int B_  = 2;
constexpr int S_  = 2048;
constexpr int H_  = 1024;
constexpr int NH_ = 16;
constexpr int HD_ = 64;
constexpr int M_  = B_ * S_;   // 4096

// Scratch (allocation-free: __device__ globals)
__device__ float g_q[(size_t)M_ * H_];
__device__ float g_k[(size_t)M_ * H_];
__device__ float g_v[(size_t)M_ * H_];
__device__ float g_ctx[(size_t)M_ * H_];
__device__ unsigned char g_mask[B_ * S_];
// Split-bf16 operand buffers (reused across the 4 GEMMs)
__device__ __nv_bfloat16 g_ah[(size_t)M_ * H_];
__device__ __nv_bfloat16 g_al[(size_t)M_ * H_];
__device__ __nv_bfloat16 g_wh[(size_t)H_ * H_];
__device__ __nv_bfloat16 g_wl[(size_t)H_ * H_];

// ---------------------------------------------------------------------------
// Warp-MMA helpers (portable tensor-core ISA: works on plain sm_103 target)
// ---------------------------------------------------------------------------
__device__ __forceinline__ uint32_t smem_to_u32(const void* p) {
    uint32_t a;
    asm("{ .reg .u64 t; cvta.to.shared.u64 t, %1; cvt.u32.u64 %0, t; }"
        : "=r"(a) : "l"(p));
    return a;
}
__device__ __forceinline__ void ldsm_x4(uint32_t r[4], uint32_t a) {
    asm volatile("ldmatrix.sync.aligned.m8n8.x4.shared.b16 {%0,%1,%2,%3}, [%4];"
                 : "=r"(r[0]), "=r"(r[1]), "=r"(r[2]), "=r"(r[3]) : "r"(a));
}
__device__ __forceinline__ void ldsm_x2(uint32_t r[2], uint32_t a) {
    asm volatile("ldmatrix.sync.aligned.m8n8.x2.shared.b16 {%0,%1}, [%2];"
                 : "=r"(r[0]), "=r"(r[1]) : "r"(a));
}
__device__ __forceinline__ void mma_bf16(float c[4], const uint32_t a[4],
                                         const uint32_t b[2]) {
    asm volatile(
        "mma.sync.aligned.m16n8k16.row.col.f32.bf16.bf16.f32 "
        "{%0,%1,%2,%3}, {%4,%5,%6,%7}, {%8,%9}, {%0,%1,%2,%3};"
        : "+f"(c[0]), "+f"(c[1]), "+f"(c[2]), "+f"(c[3])
        : "r"(a[0]), "r"(a[1]), "r"(a[2]), "r"(a[3]), "r"(b[0]), "r"(b[1]));
}

// ---------------------------------------------------------------------------
// Mask normalization (validated in R2)
// ---------------------------------------------------------------------------
__global__ void mask_normalize(const unsigned int* __restrict__ w)
{
    __shared__ unsigned int flags;
    const int tid = threadIdx.x;
    if (tid == 0) flags = 0u;
    __syncthreads();
    const unsigned int x = w[tid];
    unsigned int f = 0u;
    if (x != 0u && x != 1u && x != 0x3F800000u) f |= 1u;
    if (x == 0x3F800000u) f |= 2u;
    if (f) atomicOr(&flags, f);
    __syncthreads();
    const int byte_mode = (flags & 1u) ? 1 : 0;
    if (byte_mode) {
        const unsigned char* b8 = (const unsigned char*)w;
        for (int i = tid; i < B_ * S_; i += 1024) g_mask[i] = (b8[i] != 0);
    } else {
        for (int i = tid; i < B_ * S_; i += 1024) g_mask[i] = (w[i] != 0u);
    }
}

// ---------------------------------------------------------------------------
// fp32 -> (bf16 hi, bf16 lo) split
// ---------------------------------------------------------------------------
__global__ __launch_bounds__(256) void split_hilo(
    const float* __restrict__ x, __nv_bfloat16* __restrict__ hi,
    __nv_bfloat16* __restrict__ lo, int n)
{
    const int base = (blockIdx.x * 256 + threadIdx.x) * 4;
    if (base >= n) return;
    const float4 v = *(const float4*)&x[base];
    __nv_bfloat16 h[4], l[4];
    const float xs[4] = {v.x, v.y, v.z, v.w};
    #pragma unroll
    for (int i = 0; i < 4; i++) {
        h[i] = __float2bfloat16(xs[i]);
        l[i] = __float2bfloat16(xs[i] - __bfloat162float(h[i]));
    }
    *(uint2*)&hi[base] = *(uint2*)h;
    *(uint2*)&lo[base] = *(uint2*)l;
}

// ---------------------------------------------------------------------------
// Split-bf16 HMMA GEMM (NT): C[M,1024] = Ah·Wh^T + Ah·Wl^T + Al·Wh^T + bias
// 128x128 CTA tile, BK=32, 8 warps (2x4), warp tile 64x32 (4x4 m16n8k16).
// Double-buffered smem, register prefetch. grid=(N/128, M/128), 256 thr.
// ---------------------------------------------------------------------------
constexpr int GSTRIDE = 40;                       // bf16 elems per smem row
constexpr int GTILEB  = 128 * GSTRIDE * 2;        // 10240 B per tile
constexpr int GBUFB   = 4 * GTILEB;               // Ah,Al,Wh,Wl per stage
constexpr int GEMM_SMEM = 2 * GBUFB;              // 81920 B

__global__ __launch_bounds__(256, 1) void gemm_mma(
    const __nv_bfloat16* __restrict__ Ah, const __nv_bfloat16* __restrict__ Al,
    const __nv_bfloat16* __restrict__ Wh, const __nv_bfloat16* __restrict__ Wl,
    const float* __restrict__ bias, float* __restrict__ C, int K)
{
    extern __shared__ char smem[];
    const uint32_t smem_u = smem_to_u32(smem);
    const int tid  = threadIdx.x;
    const int wid  = tid >> 5;
    const int lane = tid & 31;
    const int warp_m = wid >> 2;     // 0..1
    const int warp_n = wid & 3;      // 0..3
    const int m0 = blockIdx.y * 128;
    const int n0 = blockIdx.x * 128;

    float c[4][4][4];
    #pragma unroll
    for (int i = 0; i < 4; i++)
        #pragma unroll
        for (int j = 0; j < 4; j++)
            #pragma unroll
            for (int r = 0; r < 4; r++) c[i][j][r] = 0.0f;

    const int NS = K / 32;   // 32 stages

    // Per-thread load mapping: 8 x uint4 per stage.
    // idx -> tile (0 Ah,1 Al,2 Wh,3 Wl), row (0..127), chunk (0..3, 16B each)
    uint4 pre[8];
    auto load_stage = [&](int s) {
        const int k0 = s * 32;
        #pragma unroll
        for (int t = 0; t < 8; t++) {
            const int idx = t * 256 + tid;
            const int tile = idx >> 9;
            const int within = idx & 511;
            const int row = within >> 2;
            const int ch = within & 3;
            const __nv_bfloat16* src;
            if (tile == 0)      src = Ah + (size_t)(m0 + row) * K;
            else if (tile == 1) src = Al + (size_t)(m0 + row) * K;
            else if (tile == 2) src = Wh + (size_t)(n0 + row) * K;
            else                src = Wl + (size_t)(n0 + row) * K;
            pre[t] = *(const uint4*)(src + k0 + ch * 8);
        }
    };
    auto store_stage = [&](int buf) {
        #pragma unroll
        for (int t = 0; t < 8; t++) {
            const int idx = t * 256 + tid;
            const int tile = idx >> 9;
            const int within = idx & 511;
            const int row = within >> 2;
            const int ch = within & 3;
            *(uint4*)(smem + buf * GBUFB + tile * GTILEB +
                      row * (GSTRIDE * 2) + ch * 16) = pre[t];
        }
    };

    load_stage(0);
    store_stage(0);
    __syncthreads();

    // lane-local ldmatrix offsets (within a tile, bytes)
    const uint32_t a_rowoff = (uint32_t)(lane & 15) * (GSTRIDE * 2);
    const uint32_t a_koff   = (uint32_t)(lane >> 4) * 16;          // 8 bf16
    const uint32_t b_rowoff = (uint32_t)(lane & 7) * (GSTRIDE * 2);
    const uint32_t b_koff   = (uint32_t)((lane >> 3) & 1) * 16;

    for (int s = 0; s < NS; s++) {
        if (s + 1 < NS) load_stage(s + 1);

        const uint32_t base = smem_u + (s & 1) * GBUFB;
        const uint32_t sAh = base;
        const uint32_t sAl = base + GTILEB;
        const uint32_t sWh = base + 2 * GTILEB;
        const uint32_t sWl = base + 3 * GTILEB;

        #pragma unroll
        for (int ks = 0; ks < 2; ks++) {
            const uint32_t kb = ks * 32;   // 16 bf16 = 32 bytes
            uint32_t ah[4][4], al[4][4], wh[4][2], wl[4][2];
            #pragma unroll
            for (int i = 0; i < 4; i++)
                ldsm_x4(ah[i], sAh + (warp_m * 64 + i * 16) * (GSTRIDE * 2) +
                               a_rowoff + kb + a_koff);
            #pragma unroll
            for (int j = 0; j < 4; j++)
                ldsm_x2(wh[j], sWh + (warp_n * 32 + j * 8) * (GSTRIDE * 2) +
                               b_rowoff + kb + b_koff);
            #pragma unroll
            for (int i = 0; i < 4; i++)
                #pragma unroll
                for (int j = 0; j < 4; j++)
                    mma_bf16(c[i][j], ah[i], wh[j]);

            #pragma unroll
            for (int j = 0; j < 4; j++)
                ldsm_x2(wl[j], sWl + (warp_n * 32 + j * 8) * (GSTRIDE * 2) +
                               b_rowoff + kb + b_koff);
            #pragma unroll
            for (int i = 0; i < 4; i++)
                #pragma unroll
                for (int j = 0; j < 4; j++)
                    mma_bf16(c[i][j], ah[i], wl[j]);

            #pragma unroll
            for (int i = 0; i < 4; i++)
                ldsm_x4(al[i], sAl + (warp_m * 64 + i * 16) * (GSTRIDE * 2) +
                               a_rowoff + kb + a_koff);
            #pragma unroll
            for (int i = 0; i < 4; i++)
                #pragma unroll
                for (int j = 0; j < 4; j++)
                    mma_bf16(c[i][j], al[i], wh[j]);
        }

        __syncthreads();
        if (s + 1 < NS) {
            store_stage((s + 1) & 1);
            __syncthreads();
        }
    }

    // Epilogue: c[i][j] tile at rows m0+warp_m*64+i*16+{t/4, t/4+8},
    // cols n0+warp_n*32+j*8+2*(t%4)+{0,1}
    const int trow = lane >> 2;
    const int tcol = (lane & 3) * 2;
    #pragma unroll
    for (int i = 0; i < 4; i++) {
        const int r0 = m0 + warp_m * 64 + i * 16 + trow;
        #pragma unroll
        for (int j = 0; j < 4; j++) {
            const int cc = n0 + warp_n * 32 + j * 8 + tcol;
            const float b0 = bias[cc];
            const float b1 = bias[cc + 1];
            float2 o0 = make_float2(c[i][j][0] + b0, c[i][j][1] + b1);
            float2 o1 = make_float2(c[i][j][2] + b0, c[i][j][3] + b1);
            *(float2*)&C[(size_t)r0 * 1024 + cc] = o0;
            *(float2*)&C[(size_t)(r0 + 8) * 1024 + cc] = o1;
        }
    }
}

// ---------------------------------------------------------------------------
// Flash-style attention (unchanged from passing R2 kernel)
// ---------------------------------------------------------------------------
constexpr int BQ = 64;
constexpr int BKT = 64;
constexpr int ATTN_SMEM_FLOATS = 4096 * 3 + 64 * 65 + 192;
constexpr int ATTN_SMEM_BYTES = ATTN_SMEM_FLOATS * 4;

__global__ __launch_bounds__(256) void attn_kernel(
    const float* __restrict__ q, const float* __restrict__ k,
    const float* __restrict__ v, const unsigned char* __restrict__ kpm,
    const float* __restrict__ bias, float* __restrict__ ctx)
{
    extern __shared__ float sm[];
    float* Qs   = sm;
    float* Ks   = sm + 4096;
    float* Vs   = sm + 8192;
    float* Ps   = sm + 12288;
    float* mrow = sm + 12288 + 64 * 65;
    float* lrow = mrow + 64;
    float* arow = lrow + 64;

    const int tid = threadIdx.x;
    const int q0 = blockIdx.x * BQ;
    const int h  = blockIdx.y;
    const int b  = blockIdx.z;
    const float scale = 0.125f;

    {
        const int r = tid >> 2;
        const int c = (tid & 3) * 16;
        const float* gq = &q[((size_t)(b * S_ + q0 + r)) * H_ + h * HD_];
        #pragma unroll
        for (int u = 0; u < 4; u++) {
            const float4 val = *(const float4*)&gq[c + u * 4];
            Qs[(c + u * 4 + 0) * 64 + r] = val.x * scale;
            Qs[(c + u * 4 + 1) * 64 + r] = val.y * scale;
            Qs[(c + u * 4 + 2) * 64 + r] = val.z * scale;
            Qs[(c + u * 4 + 3) * 64 + r] = val.w * scale;
        }
    }
    if (tid < 64) { mrow[tid] = -1e30f; lrow[tid] = 0.0f; }

    float acc[4][4];
    #pragma unroll
    for (int i = 0; i < 4; i++)
        #pragma unroll
        for (int j = 0; j < 4; j++) acc[i][j] = 0.0f;

    const int ty = tid >> 4;
    const int tx = tid & 15;

    for (int kt = 0; kt < S_ / BKT; kt++) {
        const int k0 = kt * BKT;
        __syncthreads();
        {
            const int r = tid >> 2;
            const int c = (tid & 3) * 16;
            const float* gk = &k[((size_t)(b * S_ + k0 + r)) * H_ + h * HD_];
            const float* gv = &v[((size_t)(b * S_ + k0 + r)) * H_ + h * HD_];
            #pragma unroll
            for (int u = 0; u < 4; u++) {
                const float4 kv = *(const float4*)&gk[c + u * 4];
                Ks[(c + u * 4 + 0) * 64 + r] = kv.x;
                Ks[(c + u * 4 + 1) * 64 + r] = kv.y;
                Ks[(c + u * 4 + 2) * 64 + r] = kv.z;
                Ks[(c + u * 4 + 3) * 64 + r] = kv.w;
                const float4 vv = *(const float4*)&gv[c + u * 4];
                *(float4*)&Vs[r * 64 + c + u * 4] = vv;
            }
        }
        __syncthreads();

        float s[4][4];
        #pragma unroll
        for (int i = 0; i < 4; i++)
            #pragma unroll
            for (int j = 0; j < 4; j++) s[i][j] = 0.0f;

        #pragma unroll 16
        for (int d = 0; d < 64; d++) {
            float qa[4], ka[4];
            *(float4*)&qa[0] = *(const float4*)&Qs[d * 64 + ty * 4];
            *(float4*)&ka[0] = *(const float4*)&Ks[d * 64 + tx * 4];
            #pragma unroll
            for (int i = 0; i < 4; i++)
                #pragma unroll
                for (int j = 0; j < 4; j++)
                    s[i][j] += qa[i] * ka[j];
        }

        #pragma unroll
        for (int i = 0; i < 4; i++) {
            const int qg = q0 + ty * 4 + i;
            const float4 bv =
                *(const float4*)&bias[((size_t)h * S_ + qg) * S_ + k0 + tx * 4];
            const float bb[4] = {bv.x, bv.y, bv.z, bv.w};
            #pragma unroll
            for (int j = 0; j < 4; j++) {
                const int kg = k0 + tx * 4 + j;
                float sc = s[i][j] + bb[j];
                if (kpm[b * S_ + kg]) sc = -1e30f;
                Ps[(tx * 4 + j) * 65 + (ty * 4 + i)] = sc;
            }
        }
        __syncthreads();

        if (tid < 64) {
            const float mold = mrow[tid];
            float tmax = mold;
            #pragma unroll 8
            for (int kk = 0; kk < 64; kk++)
                tmax = fmaxf(tmax, Ps[kk * 65 + tid]);
            mrow[tid] = tmax;
            arow[tid] = __expf(mold - tmax);
        }
        __syncthreads();

        {
            const int kk = tid >> 2;
            const int qb = (tid & 3) * 16;
            #pragma unroll
            for (int u = 0; u < 16; u++) {
                const int qq = qb + u;
                Ps[kk * 65 + qq] = __expf(Ps[kk * 65 + qq] - mrow[qq]);
            }
        }
        __syncthreads();

        if (tid < 64) {
            float s2 = 0.0f;
            #pragma unroll 8
            for (int kk = 0; kk < 64; kk++) s2 += Ps[kk * 65 + tid];
            lrow[tid] = lrow[tid] * arow[tid] + s2;
        }
        #pragma unroll
        for (int i = 0; i < 4; i++) {
            const float al = arow[ty * 4 + i];
            #pragma unroll
            for (int j = 0; j < 4; j++) acc[i][j] *= al;
        }
        #pragma unroll 8
        for (int kk = 0; kk < 64; kk++) {
            float vv[4];
            *(float4*)&vv[0] = *(const float4*)&Vs[kk * 64 + tx * 4];
            float pr[4];
            #pragma unroll
            for (int i = 0; i < 4; i++) pr[i] = Ps[kk * 65 + ty * 4 + i];
            #pragma unroll
            for (int i = 0; i < 4; i++)
                #pragma unroll
                for (int j = 0; j < 4; j++)
                    acc[i][j] += pr[i] * vv[j];
        }
    }

    __syncthreads();

    #pragma unroll
    for (int i = 0; i < 4; i++) {
        const int qg = q0 + ty * 4 + i;
        const float inv = 1.0f / fmaxf(lrow[ty * 4 + i], 1e-6f);
        float4 o;
        o.x = acc[i][0] * inv;
        o.y = acc[i][1] * inv;
        o.z = acc[i][2] * inv;
        o.w = acc[i][3] * inv;
        *(float4*)&ctx[((size_t)(b * S_ + qg)) * H_ + h * HD_ + tx * 4] = o;
    }
}

// ---------------------------------------------------------------------------
// Launch
// ---------------------------------------------------------------------------
extern "C" void kernel_launch(void* const* d_in, const int* in_sizes, int n_in,
                              void* d_out, int out_size)
{
    (void)in_sizes; (void)n_in; (void)out_size;

    const float* query = (const float*)d_in[0];
    const float* key_t = (const float*)d_in[1];
    const float* value = (const float*)d_in[2];
    const unsigned int* kpm_raw = (const unsigned int*)d_in[3];
    const float* bias  = (const float*)d_in[4];
    const float* q_w = (const float*)d_in[5];
    const float* q_b = (const float*)d_in[6];
    const float* k_w = (const float*)d_in[7];
    const float* k_b = (const float*)d_in[8];
    const float* v_w = (const float*)d_in[9];
    const float* v_b = (const float*)d_in[10];
    const float* o_w = (const float*)d_in[11];
    const float* o_b = (const float*)d_in[12];
    float* out = (float*)d_out;

    float *gq, *gk, *gv, *gctx;
    unsigned char* gmask;
    __nv_bfloat16 *gah, *gal, *gwh, *gwl;
    cudaGetSymbolAddress((void**)&gq, g_q);
    cudaGetSymbolAddress((void**)&gk, g_k);
    cudaGetSymbolAddress((void**)&gv, g_v);
    cudaGetSymbolAddress((void**)&gctx, g_ctx);
    cudaGetSymbolAddress((void**)&gmask, g_mask);
    cudaGetSymbolAddress((void**)&gah, g_ah);
    cudaGetSymbolAddress((void**)&gal, g_al);
    cudaGetSymbolAddress((void**)&gwh, g_wh);
    cudaGetSymbolAddress((void**)&gwl, g_wl);

    cudaFuncSetAttribute(attn_kernel,
                         cudaFuncAttributeMaxDynamicSharedMemorySize,
                         ATTN_SMEM_BYTES);
    cudaFuncSetAttribute(gemm_mma,
                         cudaFuncAttributeMaxDynamicSharedMemorySize,
                         GEMM_SMEM);

    mask_normalize<<<1, 1024>>>(kpm_raw);

    const int nA = M_ * H_;      // 4M elems
    const int nW = H_ * H_;      // 1M elems
    const dim3 gemm_grid(H_ / 128, M_ / 128);   // (8, 32)

    // Q projection
    split_hilo<<<nA / 1024, 256>>>(query, gah, gal, nA);
    split_hilo<<<nW / 1024, 256>>>(q_w, gwh, gwl, nW);
    gemm_mma<<<gemm_grid, 256, GEMM_SMEM>>>(gah, gal, gwh, gwl, q_b, gq, H_);
    // K projection
    split_hilo<<<nA / 1024, 256>>>(key_t, gah, gal, nA);
    split_hilo<<<nW / 1024, 256>>>(k_w, gwh, gwl, nW);
    gemm_mma<<<gemm_grid, 256, GEMM_SMEM>>>(gah, gal, gwh, gwl, k_b, gk, H_);
    // V projection
    split_hilo<<<nA / 1024, 256>>>(value, gah, gal, nA);
    split_hilo<<<nW / 1024, 256>>>(v_w, gwh, gwl, nW);
    gemm_mma<<<gemm_grid, 256, GEMM_SMEM>>>(gah, gal, gwh, gwl, v_b, gv, H_);

    attn_kernel<<<dim3(S_ / BQ, NH_, B_), 256, ATTN_SMEM_BYTES>>>(
        gq, gk, gv, gmask, bias, gctx);

    // Output projection
    split_hilo<<<nA / 1024, 256>>>(gctx, gah, gal, nA);
    split_hilo<<<nW / 1024, 256>>>(o_w, gwh, gwl, nW);
    gemm_mma<<<gemm_grid, 256, GEMM_SMEM>>>(gah, gal, gwh, gwl, o_b, out, H_);
}

// round 5
// speedup vs baseline: 3.0589x; 2.3988x over previous
#include <cuda_runtime.h>
#include <cuda_bf16.h>
#include <cuda_fp16.h>
#include <cstdint>
#include <cstddef>

// Problem constants
constexpr int B_  = 2;
constexpr int S_  = 2048;
constexpr int H_  = 1024;
constexpr int NH_ = 16;
constexpr int HD_ = 64;
constexpr int M_  = B_ * S_;   // 4096

// Scratch (allocation-free: __device__ globals)
__device__ unsigned char g_mask[B_ * S_];
__device__ float g_maskf[B_ * S_];
__device__ __nv_bfloat16 g_ah[(size_t)M_ * H_];
__device__ __nv_bfloat16 g_al[(size_t)M_ * H_];
__device__ __nv_bfloat16 g_wh[(size_t)H_ * H_];
__device__ __nv_bfloat16 g_wl[(size_t)H_ * H_];
__device__ __nv_bfloat16 g_qh[(size_t)M_ * H_];
__device__ __nv_bfloat16 g_ql[(size_t)M_ * H_];
__device__ __nv_bfloat16 g_kh[(size_t)M_ * H_];
__device__ __nv_bfloat16 g_kl[(size_t)M_ * H_];
__device__ __half        g_vh[(size_t)M_ * H_];
__device__ __nv_bfloat16 g_cth[(size_t)M_ * H_];
__device__ __nv_bfloat16 g_ctl[(size_t)M_ * H_];

// ---------------------------------------------------------------------------
// Warp-MMA helpers (portable ISA, works on plain sm_103 target)
// ---------------------------------------------------------------------------
__device__ __forceinline__ uint32_t smem_to_u32(const void* p) {
    uint32_t a;
    asm("{ .reg .u64 t; cvta.to.shared.u64 t, %1; cvt.u32.u64 %0, t; }"
        : "=r"(a) : "l"(p));
    return a;
}
__device__ __forceinline__ void ldsm_x4(uint32_t r[4], uint32_t a) {
    asm volatile("ldmatrix.sync.aligned.m8n8.x4.shared.b16 {%0,%1,%2,%3}, [%4];"
                 : "=r"(r[0]), "=r"(r[1]), "=r"(r[2]), "=r"(r[3]) : "r"(a));
}
__device__ __forceinline__ void ldsm_x2(uint32_t r[2], uint32_t a) {
    asm volatile("ldmatrix.sync.aligned.m8n8.x2.shared.b16 {%0,%1}, [%2];"
                 : "=r"(r[0]), "=r"(r[1]) : "r"(a));
}
__device__ __forceinline__ void ldsm_x2_trans(uint32_t r[2], uint32_t a) {
    asm volatile("ldmatrix.sync.aligned.m8n8.x2.trans.shared.b16 {%0,%1}, [%2];"
                 : "=r"(r[0]), "=r"(r[1]) : "r"(a));
}
__device__ __forceinline__ void mma_bf16(float c[4], const uint32_t a[4],
                                         const uint32_t b[2]) {
    asm volatile(
        "mma.sync.aligned.m16n8k16.row.col.f32.bf16.bf16.f32 "
        "{%0,%1,%2,%3}, {%4,%5,%6,%7}, {%8,%9}, {%0,%1,%2,%3};"
        : "+f"(c[0]), "+f"(c[1]), "+f"(c[2]), "+f"(c[3])
        : "r"(a[0]), "r"(a[1]), "r"(a[2]), "r"(a[3]), "r"(b[0]), "r"(b[1]));
}
__device__ __forceinline__ void mma_f16(float c[4], const uint32_t a[4],
                                        const uint32_t b[2]) {
    asm volatile(
        "mma.sync.aligned.m16n8k16.row.col.f32.f16.f16.f32 "
        "{%0,%1,%2,%3}, {%4,%5,%6,%7}, {%8,%9}, {%0,%1,%2,%3};"
        : "+f"(c[0]), "+f"(c[1]), "+f"(c[2]), "+f"(c[3])
        : "r"(a[0]), "r"(a[1]), "r"(a[2]), "r"(a[3]), "r"(b[0]), "r"(b[1]));
}

// ---------------------------------------------------------------------------
// Mask normalization: canonical uint8 + float (-1e30 / 0) forms
// ---------------------------------------------------------------------------
__global__ void mask_normalize(const unsigned int* __restrict__ w)
{
    __shared__ unsigned int flags;
    const int tid = threadIdx.x;
    if (tid == 0) flags = 0u;
    __syncthreads();
    const unsigned int x = w[tid];
    unsigned int f = 0u;
    if (x != 0u && x != 1u && x != 0x3F800000u) f |= 1u;
    if (x == 0x3F800000u) f |= 2u;
    if (f) atomicOr(&flags, f);
    __syncthreads();
    const int byte_mode = (flags & 1u) ? 1 : 0;
    if (byte_mode) {
        const unsigned char* b8 = (const unsigned char*)w;
        for (int i = tid; i < B_ * S_; i += 1024) {
            const unsigned char m = (b8[i] != 0);
            g_mask[i] = m;
            g_maskf[i] = m ? -1e30f : 0.0f;
        }
    } else {
        for (int i = tid; i < B_ * S_; i += 1024) {
            const unsigned char m = (w[i] != 0u);
            g_mask[i] = m;
            g_maskf[i] = m ? -1e30f : 0.0f;
        }
    }
}

// ---------------------------------------------------------------------------
// fp32 -> (bf16 hi, bf16 lo) split
// ---------------------------------------------------------------------------
__global__ __launch_bounds__(256) void split_hilo(
    const float* __restrict__ x, __nv_bfloat16* __restrict__ hi,
    __nv_bfloat16* __restrict__ lo, int n)
{
    const int base = (blockIdx.x * 256 + threadIdx.x) * 4;
    if (base >= n) return;
    const float4 v = *(const float4*)&x[base];
    __nv_bfloat16 h[4], l[4];
    const float xs[4] = {v.x, v.y, v.z, v.w};
    #pragma unroll
    for (int i = 0; i < 4; i++) {
        h[i] = __float2bfloat16(xs[i]);
        l[i] = __float2bfloat16(xs[i] - __bfloat162float(h[i]));
    }
    *(uint2*)&hi[base] = *(uint2*)h;
    *(uint2*)&lo[base] = *(uint2*)l;
}

// ---------------------------------------------------------------------------
// Split-bf16 HMMA GEMM (NT): acc = Ah·Wh^T + Ah·Wl^T + Al·Wh^T (+ bias)
// 128x128 CTA tile, BK=32, 8 warps (2x4), warp tile 64x32.
// Epilogue modes: 0 = fp32 to C; 1 = bf16 hi/lo (scaled) to Oh/Ol;
//                 2 = fp16 to Of.
// ---------------------------------------------------------------------------
constexpr int GSTRIDE = 40;                       // bf16 elems per smem row
constexpr int GTILEB  = 128 * GSTRIDE * 2;        // 10240 B per tile
constexpr int GBUFB   = 4 * GTILEB;
constexpr int GEMM_SMEM = 2 * GBUFB;              // 81920 B

__global__ __launch_bounds__(256, 1) void gemm_mma(
    const __nv_bfloat16* __restrict__ Ah, const __nv_bfloat16* __restrict__ Al,
    const __nv_bfloat16* __restrict__ Wh, const __nv_bfloat16* __restrict__ Wl,
    const float* __restrict__ bias, float* __restrict__ C,
    __nv_bfloat16* __restrict__ Oh, __nv_bfloat16* __restrict__ Ol,
    __half* __restrict__ Of, int mode, float scale, int K)
{
    extern __shared__ char smem[];
    const uint32_t smem_u = smem_to_u32(smem);
    const int tid  = threadIdx.x;
    const int wid  = tid >> 5;
    const int lane = tid & 31;
    const int warp_m = wid >> 2;
    const int warp_n = wid & 3;
    const int m0 = blockIdx.y * 128;
    const int n0 = blockIdx.x * 128;

    float c[4][4][4];
    #pragma unroll
    for (int i = 0; i < 4; i++)
        #pragma unroll
        for (int j = 0; j < 4; j++)
            #pragma unroll
            for (int r = 0; r < 4; r++) c[i][j][r] = 0.0f;

    const int NS = K / 32;

    uint4 pre[8];
    auto load_stage = [&](int s) {
        const int k0 = s * 32;
        #pragma unroll
        for (int t = 0; t < 8; t++) {
            const int idx = t * 256 + tid;
            const int tile = idx >> 9;
            const int within = idx & 511;
            const int row = within >> 2;
            const int ch = within & 3;
            const __nv_bfloat16* src;
            if (tile == 0)      src = Ah + (size_t)(m0 + row) * K;
            else if (tile == 1) src = Al + (size_t)(m0 + row) * K;
            else if (tile == 2) src = Wh + (size_t)(n0 + row) * K;
            else                src = Wl + (size_t)(n0 + row) * K;
            pre[t] = *(const uint4*)(src + k0 + ch * 8);
        }
    };
    auto store_stage = [&](int buf) {
        #pragma unroll
        for (int t = 0; t < 8; t++) {
            const int idx = t * 256 + tid;
            const int tile = idx >> 9;
            const int within = idx & 511;
            const int row = within >> 2;
            const int ch = within & 3;
            *(uint4*)(smem + buf * GBUFB + tile * GTILEB +
                      row * (GSTRIDE * 2) + ch * 16) = pre[t];
        }
    };

    load_stage(0);
    store_stage(0);
    __syncthreads();

    const uint32_t a_rowoff = (uint32_t)(lane & 15) * (GSTRIDE * 2);
    const uint32_t a_koff   = (uint32_t)(lane >> 4) * 16;
    const uint32_t b_rowoff = (uint32_t)(lane & 7) * (GSTRIDE * 2);
    const uint32_t b_koff   = (uint32_t)((lane >> 3) & 1) * 16;

    for (int s = 0; s < NS; s++) {
        if (s + 1 < NS) load_stage(s + 1);

        const uint32_t base = smem_u + (s & 1) * GBUFB;
        const uint32_t sAh = base;
        const uint32_t sAl = base + GTILEB;
        const uint32_t sWh = base + 2 * GTILEB;
        const uint32_t sWl = base + 3 * GTILEB;

        #pragma unroll
        for (int ks = 0; ks < 2; ks++) {
            const uint32_t kb = ks * 32;
            uint32_t ah[4][4], al[4][4], wh[4][2], wl[4][2];
            #pragma unroll
            for (int i = 0; i < 4; i++)
                ldsm_x4(ah[i], sAh + (warp_m * 64 + i * 16) * (GSTRIDE * 2) +
                               a_rowoff + kb + a_koff);
            #pragma unroll
            for (int j = 0; j < 4; j++)
                ldsm_x2(wh[j], sWh + (warp_n * 32 + j * 8) * (GSTRIDE * 2) +
                               b_rowoff + kb + b_koff);
            #pragma unroll
            for (int i = 0; i < 4; i++)
                #pragma unroll
                for (int j = 0; j < 4; j++)
                    mma_bf16(c[i][j], ah[i], wh[j]);

            #pragma unroll
            for (int j = 0; j < 4; j++)
                ldsm_x2(wl[j], sWl + (warp_n * 32 + j * 8) * (GSTRIDE * 2) +
                               b_rowoff + kb + b_koff);
            #pragma unroll
            for (int i = 0; i < 4; i++)
                #pragma unroll
                for (int j = 0; j < 4; j++)
                    mma_bf16(c[i][j], ah[i], wl[j]);

            #pragma unroll
            for (int i = 0; i < 4; i++)
                ldsm_x4(al[i], sAl + (warp_m * 64 + i * 16) * (GSTRIDE * 2) +
                               a_rowoff + kb + a_koff);
            #pragma unroll
            for (int i = 0; i < 4; i++)
                #pragma unroll
                for (int j = 0; j < 4; j++)
                    mma_bf16(c[i][j], al[i], wh[j]);
        }

        __syncthreads();
        if (s + 1 < NS) {
            store_stage((s + 1) & 1);
            __syncthreads();
        }
    }

    const int trow = lane >> 2;
    const int tcol = (lane & 3) * 2;
    #pragma unroll
    for (int i = 0; i < 4; i++) {
        const int r0 = m0 + warp_m * 64 + i * 16 + trow;
        #pragma unroll
        for (int j = 0; j < 4; j++) {
            const int cc = n0 + warp_n * 32 + j * 8 + tcol;
            const float b0 = bias[cc];
            const float b1 = bias[cc + 1];
            float v00 = c[i][j][0] + b0, v01 = c[i][j][1] + b1;
            float v10 = c[i][j][2] + b0, v11 = c[i][j][3] + b1;
            const size_t p0 = (size_t)r0 * 1024 + cc;
            const size_t p1 = (size_t)(r0 + 8) * 1024 + cc;
            if (mode == 0) {
                *(float2*)&C[p0] = make_float2(v00, v01);
                *(float2*)&C[p1] = make_float2(v10, v11);
            } else if (mode == 1) {
                v00 *= scale; v01 *= scale; v10 *= scale; v11 *= scale;
                const __nv_bfloat16 h00 = __float2bfloat16(v00);
                const __nv_bfloat16 h01 = __float2bfloat16(v01);
                const __nv_bfloat16 h10 = __float2bfloat16(v10);
                const __nv_bfloat16 h11 = __float2bfloat16(v11);
                *(__nv_bfloat162*)&Oh[p0] = __nv_bfloat162(h00, h01);
                *(__nv_bfloat162*)&Oh[p1] = __nv_bfloat162(h10, h11);
                *(__nv_bfloat162*)&Ol[p0] = __nv_bfloat162(
                    __float2bfloat16(v00 - __bfloat162float(h00)),
                    __float2bfloat16(v01 - __bfloat162float(h01)));
                *(__nv_bfloat162*)&Ol[p1] = __nv_bfloat162(
                    __float2bfloat16(v10 - __bfloat162float(h10)),
                    __float2bfloat16(v11 - __bfloat162float(h11)));
            } else {
                *(__half2*)&Of[p0] = __floats2half2_rn(v00, v01);
                *(__half2*)&Of[p1] = __floats2half2_rn(v10, v11);
            }
        }
    }
}

// ---------------------------------------------------------------------------
// Tensor-core FlashAttention: BQ=64, BK=64, 4 warps (16 q-rows each).
// S = Q·K^T via split-bf16 (3 MMAs), P·V via fp16. P stays in registers.
// ---------------------------------------------------------------------------
constexpr int ASTR  = 72;                 // halves per smem row (144 B)
constexpr int ATILE = 64 * ASTR * 2;      // 9216 B
constexpr int SQH = 0;
constexpr int SQL = ATILE;
constexpr int SKH = 2 * ATILE;
constexpr int SKL = 3 * ATILE;
constexpr int SVV = 4 * ATILE;
constexpr int ATTN_SMEM = 5 * ATILE;      // 46080 B

__global__ __launch_bounds__(128) void attn_mma(
    const __nv_bfloat16* __restrict__ qh, const __nv_bfloat16* __restrict__ ql,
    const __nv_bfloat16* __restrict__ kh, const __nv_bfloat16* __restrict__ kl,
    const __half* __restrict__ vv, const float* __restrict__ maskf,
    const float* __restrict__ bias,
    __nv_bfloat16* __restrict__ cth, __nv_bfloat16* __restrict__ ctl)
{
    extern __shared__ char smem[];
    const uint32_t su = smem_to_u32(smem);
    const int tid = threadIdx.x;
    const int wid = tid >> 5;
    const int lane = tid & 31;
    const int g = lane >> 2;
    const int tig = lane & 3;
    const int q0 = blockIdx.x * 64;
    const int h = blockIdx.y;
    const int b = blockIdx.z;

    // Load Q hi/lo tiles: 2 x 64 rows x 8 chunks = 1024 chunks, 8/thread
    #pragma unroll
    for (int t = 0; t < 8; t++) {
        const int idx = t * 128 + tid;
        const int half_sel = idx >> 9;
        const int within = idx & 511;
        const int row = within >> 3;
        const int ch = within & 7;
        const __nv_bfloat16* src =
            (half_sel ? ql : qh) + ((size_t)(b * S_ + q0 + row)) * H_ +
            h * HD_ + ch * 8;
        *(uint4*)(smem + (half_sel ? SQL : SQH) + row * (ASTR * 2) + ch * 16) =
            *(const uint4*)src;
    }

    float ctx[8][4];
    #pragma unroll
    for (int j = 0; j < 8; j++)
        #pragma unroll
        for (int r = 0; r < 4; r++) ctx[j][r] = 0.0f;
    float m0_ = -1e30f, m1_ = -1e30f, l0_ = 0.0f, l1_ = 0.0f;

    const uint32_t a_rowoff = (uint32_t)(wid * 16 + (lane & 15)) * (ASTR * 2);
    const uint32_t a_koff   = (uint32_t)(lane >> 4) * 16;
    const uint32_t b_rowoff = (uint32_t)(lane & 7) * (ASTR * 2);
    const uint32_t b_koff   = (uint32_t)((lane >> 3) & 1) * 16;
    const uint32_t v_rowoff = (uint32_t)(lane & 15) * (ASTR * 2);

    const int qg0 = q0 + wid * 16 + g;
    const size_t bias_row0 = ((size_t)h * S_ + qg0) * S_ + 2 * tig;
    const size_t bias_row1 = bias_row0 + 8 * S_;

    for (int kt = 0; kt < S_ / 64; kt++) {
        const int k0 = kt * 64;
        __syncthreads();
        // Load Kh, Kl, V tiles: 3 x 512 chunks, 12/thread
        #pragma unroll
        for (int t = 0; t < 12; t++) {
            const int idx = t * 128 + tid;
            const int tile = idx >> 9;
            const int within = idx & 511;
            const int row = within >> 3;
            const int ch = within & 7;
            const size_t goff = ((size_t)(b * S_ + k0 + row)) * H_ + h * HD_ + ch * 8;
            uint4 val;
            if (tile == 0)      val = *(const uint4*)(kh + goff);
            else if (tile == 1) val = *(const uint4*)(kl + goff);
            else                val = *(const uint4*)(vv + goff);
            *(uint4*)(smem + SKH + tile * ATILE + row * (ASTR * 2) + ch * 16) = val;
        }
        __syncthreads();

        // ---- S = Q·K^T (split-bf16, 3 terms) ----
        float c[8][4];
        #pragma unroll
        for (int j = 0; j < 8; j++)
            #pragma unroll
            for (int r = 0; r < 4; r++) c[j][r] = 0.0f;

        #pragma unroll
        for (int ks = 0; ks < 4; ks++) {
            const uint32_t kb = ks * 32;
            uint32_t ah[4], al[4];
            ldsm_x4(ah, su + SQH + a_rowoff + a_koff + kb);
            ldsm_x4(al, su + SQL + a_rowoff + a_koff + kb);
            #pragma unroll
            for (int j = 0; j < 8; j++) {
                uint32_t bh[2], bl[2];
                const uint32_t boff = (uint32_t)(j * 8) * (ASTR * 2) +
                                      b_rowoff + b_koff + kb;
                ldsm_x2(bh, su + SKH + boff);
                ldsm_x2(bl, su + SKL + boff);
                mma_bf16(c[j], ah, bh);
                mma_bf16(c[j], ah, bl);
                mma_bf16(c[j], al, bh);
            }
        }

        // ---- bias + mask ----
        #pragma unroll
        for (int j = 0; j < 8; j++) {
            const float2 mk = *(const float2*)&maskf[b * S_ + k0 + j * 8 + 2 * tig];
            const float2 b0 = *(const float2*)&bias[bias_row0 + k0 + j * 8];
            const float2 b1 = *(const float2*)&bias[bias_row1 + k0 + j * 8];
            c[j][0] += b0.x + mk.x;
            c[j][1] += b0.y + mk.y;
            c[j][2] += b1.x + mk.x;
            c[j][3] += b1.y + mk.y;
        }

        // ---- online softmax ----
        float mx0 = -1e30f, mx1 = -1e30f;
        #pragma unroll
        for (int j = 0; j < 8; j++) {
            mx0 = fmaxf(mx0, fmaxf(c[j][0], c[j][1]));
            mx1 = fmaxf(mx1, fmaxf(c[j][2], c[j][3]));
        }
        mx0 = fmaxf(mx0, __shfl_xor_sync(0xffffffffu, mx0, 1));
        mx0 = fmaxf(mx0, __shfl_xor_sync(0xffffffffu, mx0, 2));
        mx1 = fmaxf(mx1, __shfl_xor_sync(0xffffffffu, mx1, 1));
        mx1 = fmaxf(mx1, __shfl_xor_sync(0xffffffffu, mx1, 2));

        const float mo0 = m0_, mo1 = m1_;
        m0_ = fmaxf(m0_, mx0);
        m1_ = fmaxf(m1_, mx1);
        const float alpha0 = __expf(mo0 - m0_);
        const float alpha1 = __expf(mo1 - m1_);

        float sum0 = 0.0f, sum1 = 0.0f;
        uint32_t ap[4][4];
        #pragma unroll
        for (int j = 0; j < 8; j++) {
            c[j][0] = __expf(c[j][0] - m0_);
            c[j][1] = __expf(c[j][1] - m0_);
            c[j][2] = __expf(c[j][2] - m1_);
            c[j][3] = __expf(c[j][3] - m1_);
            sum0 += c[j][0] + c[j][1];
            sum1 += c[j][2] + c[j][3];
        }
        l0_ = l0_ * alpha0 + sum0;
        l1_ = l1_ * alpha1 + sum1;

        #pragma unroll
        for (int t = 0; t < 4; t++) {
            __half2 h0 = __floats2half2_rn(c[2 * t][0], c[2 * t][1]);
            __half2 h1 = __floats2half2_rn(c[2 * t][2], c[2 * t][3]);
            __half2 h2 = __floats2half2_rn(c[2 * t + 1][0], c[2 * t + 1][1]);
            __half2 h3 = __floats2half2_rn(c[2 * t + 1][2], c[2 * t + 1][3]);
            ap[t][0] = *(uint32_t*)&h0;
            ap[t][1] = *(uint32_t*)&h1;
            ap[t][2] = *(uint32_t*)&h2;
            ap[t][3] = *(uint32_t*)&h3;
        }

        #pragma unroll
        for (int j = 0; j < 8; j++) {
            ctx[j][0] *= alpha0;
            ctx[j][1] *= alpha0;
            ctx[j][2] *= alpha1;
            ctx[j][3] *= alpha1;
        }

        // ---- ctx += P·V (fp16) ----
        #pragma unroll
        for (int t = 0; t < 4; t++) {
            const uint32_t vbase = su + SVV + (uint32_t)(t * 16) * (ASTR * 2) + v_rowoff;
            #pragma unroll
            for (int jd = 0; jd < 8; jd++) {
                uint32_t bv[2];
                ldsm_x2_trans(bv, vbase + jd * 16);
                mma_f16(ctx[jd], ap[t], bv);
            }
        }
    }

    // Final: normalize and write ctx hi/lo bf16
    l0_ += __shfl_xor_sync(0xffffffffu, l0_, 1);
    l0_ += __shfl_xor_sync(0xffffffffu, l0_, 2);
    l1_ += __shfl_xor_sync(0xffffffffu, l1_, 1);
    l1_ += __shfl_xor_sync(0xffffffffu, l1_, 2);
    const float inv0 = 1.0f / fmaxf(l0_, 1e-6f);
    const float inv1 = 1.0f / fmaxf(l1_, 1e-6f);

    const size_t orow0 = ((size_t)(b * S_ + qg0)) * H_ + h * HD_ + 2 * tig;
    const size_t orow1 = orow0 + 8 * H_;
    #pragma unroll
    for (int jd = 0; jd < 8; jd++) {
        const float v00 = ctx[jd][0] * inv0, v01 = ctx[jd][1] * inv0;
        const float v10 = ctx[jd][2] * inv1, v11 = ctx[jd][3] * inv1;
        const __nv_bfloat16 h00 = __float2bfloat16(v00);
        const __nv_bfloat16 h01 = __float2bfloat16(v01);
        const __nv_bfloat16 h10 = __float2bfloat16(v10);
        const __nv_bfloat16 h11 = __float2bfloat16(v11);
        *(__nv_bfloat162*)&cth[orow0 + jd * 8] = __nv_bfloat162(h00, h01);
        *(__nv_bfloat162*)&cth[orow1 + jd * 8] = __nv_bfloat162(h10, h11);
        *(__nv_bfloat162*)&ctl[orow0 + jd * 8] = __nv_bfloat162(
            __float2bfloat16(v00 - __bfloat162float(h00)),
            __float2bfloat16(v01 - __bfloat162float(h01)));
        *(__nv_bfloat162*)&ctl[orow1 + jd * 8] = __nv_bfloat162(
            __float2bfloat16(v10 - __bfloat162float(h10)),
            __float2bfloat16(v11 - __bfloat162float(h11)));
    }
}

// ---------------------------------------------------------------------------
// Launch
// ---------------------------------------------------------------------------
extern "C" void kernel_launch(void* const* d_in, const int* in_sizes, int n_in,
                              void* d_out, int out_size)
{
    (void)in_sizes; (void)n_in; (void)out_size;

    const float* query = (const float*)d_in[0];
    const float* key_t = (const float*)d_in[1];
    const float* value = (const float*)d_in[2];
    const unsigned int* kpm_raw = (const unsigned int*)d_in[3];
    const float* bias  = (const float*)d_in[4];
    const float* q_w = (const float*)d_in[5];
    const float* q_b = (const float*)d_in[6];
    const float* k_w = (const float*)d_in[7];
    const float* k_b = (const float*)d_in[8];
    const float* v_w = (const float*)d_in[9];
    const float* v_b = (const float*)d_in[10];
    const float* o_w = (const float*)d_in[11];
    const float* o_b = (const float*)d_in[12];
    float* out = (float*)d_out;

    __nv_bfloat16 *gah, *gal, *gwh, *gwl, *gqh, *gql, *gkh, *gkl, *gcth, *gctl;
    __half* gvh;
    float* gmaskf;
    cudaGetSymbolAddress((void**)&gah, g_ah);
    cudaGetSymbolAddress((void**)&gal, g_al);
    cudaGetSymbolAddress((void**)&gwh, g_wh);
    cudaGetSymbolAddress((void**)&gwl, g_wl);
    cudaGetSymbolAddress((void**)&gqh, g_qh);
    cudaGetSymbolAddress((void**)&gql, g_ql);
    cudaGetSymbolAddress((void**)&gkh, g_kh);
    cudaGetSymbolAddress((void**)&gkl, g_kl);
    cudaGetSymbolAddress((void**)&gvh, g_vh);
    cudaGetSymbolAddress((void**)&gcth, g_cth);
    cudaGetSymbolAddress((void**)&gctl, g_ctl);
    cudaGetSymbolAddress((void**)&gmaskf, g_maskf);

    cudaFuncSetAttribute(gemm_mma,
                         cudaFuncAttributeMaxDynamicSharedMemorySize, GEMM_SMEM);
    cudaFuncSetAttribute(attn_mma,
                         cudaFuncAttributeMaxDynamicSharedMemorySize, ATTN_SMEM);

    mask_normalize<<<1, 1024>>>(kpm_raw);

    const int nA = M_ * H_;
    const int nW = H_ * H_;
    const dim3 gemm_grid(H_ / 128, M_ / 128);

    // Q projection -> bf16 hi/lo, pre-scaled by 1/sqrt(HD)
    split_hilo<<<nA / 1024, 256>>>(query, gah, gal, nA);
    split_hilo<<<nW / 1024, 256>>>(q_w, gwh, gwl, nW);
    gemm_mma<<<gemm_grid, 256, GEMM_SMEM>>>(gah, gal, gwh, gwl, q_b,
                                            nullptr, gqh, gql, nullptr,
                                            1, 0.125f, H_);
    // K projection -> bf16 hi/lo
    split_hilo<<<nA / 1024, 256>>>(key_t, gah, gal, nA);
    split_hilo<<<nW / 1024, 256>>>(k_w, gwh, gwl, nW);
    gemm_mma<<<gemm_grid, 256, GEMM_SMEM>>>(gah, gal, gwh, gwl, k_b,
                                            nullptr, gkh, gkl, nullptr,
                                            1, 1.0f, H_);
    // V projection -> fp16
    split_hilo<<<nA / 1024, 256>>>(value, gah, gal, nA);
    split_hilo<<<nW / 1024, 256>>>(v_w, gwh, gwl, nW);
    gemm_mma<<<gemm_grid, 256, GEMM_SMEM>>>(gah, gal, gwh, gwl, v_b,
                                            nullptr, nullptr, nullptr, gvh,
                                            2, 1.0f, H_);

    attn_mma<<<dim3(S_ / 64, NH_, B_), 128, ATTN_SMEM>>>(
        gqh, gql, gkh, gkl, gvh, gmaskf, bias, gcth, gctl);

    // Output projection (ctx already split by attention epilogue)
    split_hilo<<<nW / 1024, 256>>>(o_w, gwh, gwl, nW);
    gemm_mma<<<gemm_grid, 256, GEMM_SMEM>>>(gcth, gctl, gwh, gwl, o_b,
                                            out, nullptr, nullptr, nullptr,
                                            0, 1.0f, H_);
}

// round 6
// speedup vs baseline: 3.1597x; 1.0330x over previous
#include <cuda_runtime.h>
#include <cuda_bf16.h>
#include <cuda_fp16.h>
#include <cstdint>
#include <cstddef>

// Problem constants
constexpr int B_  = 2;
constexpr int S_  = 2048;
constexpr int H_  = 1024;
constexpr int NH_ = 16;
constexpr int HD_ = 64;
constexpr int M_  = B_ * S_;   // 4096

// Scratch (allocation-free: __device__ globals)
__device__ float g_maskf[B_ * S_];
__device__ __nv_bfloat16 g_qh[(size_t)M_ * H_];
__device__ __nv_bfloat16 g_ql[(size_t)M_ * H_];
__device__ __nv_bfloat16 g_kh[(size_t)M_ * H_];
__device__ __nv_bfloat16 g_kl[(size_t)M_ * H_];
__device__ __half        g_vh[(size_t)M_ * H_];
__device__ __nv_bfloat16 g_cth[(size_t)M_ * H_];
__device__ __nv_bfloat16 g_ctl[(size_t)M_ * H_];

// ---------------------------------------------------------------------------
// Warp-MMA helpers (portable ISA, works on plain sm_103 target)
// ---------------------------------------------------------------------------
__device__ __forceinline__ uint32_t smem_to_u32(const void* p) {
    uint32_t a;
    asm("{ .reg .u64 t; cvta.to.shared.u64 t, %1; cvt.u32.u64 %0, t; }"
        : "=r"(a) : "l"(p));
    return a;
}
__device__ __forceinline__ void ldsm_x4(uint32_t r[4], uint32_t a) {
    asm volatile("ldmatrix.sync.aligned.m8n8.x4.shared.b16 {%0,%1,%2,%3}, [%4];"
                 : "=r"(r[0]), "=r"(r[1]), "=r"(r[2]), "=r"(r[3]) : "r"(a));
}
__device__ __forceinline__ void ldsm_x2(uint32_t r[2], uint32_t a) {
    asm volatile("ldmatrix.sync.aligned.m8n8.x2.shared.b16 {%0,%1}, [%2];"
                 : "=r"(r[0]), "=r"(r[1]) : "r"(a));
}
__device__ __forceinline__ void ldsm_x2_trans(uint32_t r[2], uint32_t a) {
    asm volatile("ldmatrix.sync.aligned.m8n8.x2.trans.shared.b16 {%0,%1}, [%2];"
                 : "=r"(r[0]), "=r"(r[1]) : "r"(a));
}
__device__ __forceinline__ void mma_bf16(float c[4], const uint32_t a[4],
                                         const uint32_t b[2]) {
    asm volatile(
        "mma.sync.aligned.m16n8k16.row.col.f32.bf16.bf16.f32 "
        "{%0,%1,%2,%3}, {%4,%5,%6,%7}, {%8,%9}, {%0,%1,%2,%3};"
        : "+f"(c[0]), "+f"(c[1]), "+f"(c[2]), "+f"(c[3])
        : "r"(a[0]), "r"(a[1]), "r"(a[2]), "r"(a[3]), "r"(b[0]), "r"(b[1]));
}
__device__ __forceinline__ void mma_f16(float c[4], const uint32_t a[4],
                                        const uint32_t b[2]) {
    asm volatile(
        "mma.sync.aligned.m16n8k16.row.col.f32.f16.f16.f32 "
        "{%0,%1,%2,%3}, {%4,%5,%6,%7}, {%8,%9}, {%0,%1,%2,%3};"
        : "+f"(c[0]), "+f"(c[1]), "+f"(c[2]), "+f"(c[3])
        : "r"(a[0]), "r"(a[1]), "r"(a[2]), "r"(a[3]), "r"(b[0]), "r"(b[1]));
}
__device__ __forceinline__ void cvt_split(float4 v, uint2& hi, uint2& lo) {
    __nv_bfloat16 h[4], l[4];
    const float xs[4] = {v.x, v.y, v.z, v.w};
    #pragma unroll
    for (int i = 0; i < 4; i++) {
        h[i] = __float2bfloat16(xs[i]);
        l[i] = __float2bfloat16(xs[i] - __bfloat162float(h[i]));
    }
    hi = *(uint2*)h;
    lo = *(uint2*)l;
}

// ---------------------------------------------------------------------------
// Mask normalization -> float (-1e30 / 0) form
// ---------------------------------------------------------------------------
__global__ void mask_normalize(const unsigned int* __restrict__ w)
{
    __shared__ unsigned int flags;
    const int tid = threadIdx.x;
    if (tid == 0) flags = 0u;
    __syncthreads();
    const unsigned int x = w[tid];
    unsigned int f = 0u;
    if (x != 0u && x != 1u && x != 0x3F800000u) f |= 1u;
    if (x == 0x3F800000u) f |= 2u;
    if (f) atomicOr(&flags, f);
    __syncthreads();
    const int byte_mode = (flags & 1u) ? 1 : 0;
    if (byte_mode) {
        const unsigned char* b8 = (const unsigned char*)w;
        for (int i = tid; i < B_ * S_; i += 1024)
            g_maskf[i] = (b8[i] != 0) ? -1e30f : 0.0f;
    } else {
        for (int i = tid; i < B_ * S_; i += 1024)
            g_maskf[i] = (w[i] != 0u) ? -1e30f : 0.0f;
    }
}

// ---------------------------------------------------------------------------
// Split-bf16 HMMA GEMM (NT) with fused fp32->hi/lo conversion on load.
//   acc = Ah·Wh^T + Ah·Wl^T + Al·Wh^T  (+ bias)
// A source: fp32 (presplit=0, converted inline) or bf16 hi/lo (presplit=1).
// W source: always fp32, converted inline.
// 128x128 CTA tile, BK=32, 8 warps (2x4), warp tile 64x32.
// Single __syncthreads per stage (store targets the non-read buffer).
// Epilogue modes: 0 = fp32 C; 1 = bf16 hi/lo (scaled); 2 = fp16.
// ---------------------------------------------------------------------------
constexpr int GSTRIDE = 40;                       // bf16 elems per smem row
constexpr int GTILEB  = 128 * GSTRIDE * 2;        // 10240 B per tile
constexpr int GBUFB   = 4 * GTILEB;               // Ah,Al,Wh,Wl
constexpr int GEMM_SMEM = 2 * GBUFB;              // 81920 B

__global__ __launch_bounds__(256, 1) void gemm_mma(
    const float* __restrict__ A,
    const __nv_bfloat16* __restrict__ Ah_in,
    const __nv_bfloat16* __restrict__ Al_in,
    const float* __restrict__ W,
    const float* __restrict__ bias, float* __restrict__ C,
    __nv_bfloat16* __restrict__ Oh, __nv_bfloat16* __restrict__ Ol,
    __half* __restrict__ Of, int presplit, int mode, float scale, int K)
{
    extern __shared__ char smem[];
    const uint32_t smem_u = smem_to_u32(smem);
    const int tid  = threadIdx.x;
    const int wid  = tid >> 5;
    const int lane = tid & 31;
    const int warp_m = wid >> 2;
    const int warp_n = wid & 3;
    const int m0 = blockIdx.y * 128;
    const int n0 = blockIdx.x * 128;

    float c[4][4][4];
    #pragma unroll
    for (int i = 0; i < 4; i++)
        #pragma unroll
        for (int j = 0; j < 4; j++)
            #pragma unroll
            for (int r = 0; r < 4; r++) c[i][j][r] = 0.0f;

    const int NS = K / 32;

    float4 pre[8];
    auto load_stage = [&](int s) {
        const int k0 = s * 32;
        if (!presplit) {
            #pragma unroll
            for (int t = 0; t < 8; t++) {
                const int idx = t * 256 + tid;
                const int tile = idx >> 10;          // 0=A, 1=W
                const int within = idx & 1023;
                const int row = within >> 3;
                const int ch = within & 7;           // float4 within 32 floats
                const float* src = tile ? (W + (size_t)(n0 + row) * K)
                                        : (A + (size_t)(m0 + row) * K);
                pre[t] = *(const float4*)(src + k0 + ch * 4);
            }
        } else {
            #pragma unroll
            for (int t = 0; t < 4; t++) {            // Ah / Al bf16 direct
                const int idx = t * 256 + tid;
                const int tile = idx >> 9;           // 0=Ah, 1=Al
                const int within = idx & 511;
                const int row = within >> 2;
                const int ch = within & 3;           // 16B chunk of 64B row
                const __nv_bfloat16* src =
                    (tile ? Al_in : Ah_in) + (size_t)(m0 + row) * K + k0;
                pre[t] = *(const float4*)(src + ch * 8);
            }
            #pragma unroll
            for (int t = 4; t < 8; t++) {            // W fp32
                const int idx = (t - 4) * 256 + tid;
                const int row = idx >> 3;
                const int ch = idx & 7;
                pre[t] = *(const float4*)(W + (size_t)(n0 + row) * K + k0 + ch * 4);
            }
        }
    };
    auto store_stage = [&](int buf) {
        char* base = smem + buf * GBUFB;
        if (!presplit) {
            #pragma unroll
            for (int t = 0; t < 8; t++) {
                const int idx = t * 256 + tid;
                const int tile = idx >> 10;          // 0=A, 1=W
                const int within = idx & 1023;
                const int row = within >> 3;
                const int ch = within & 7;
                uint2 hi, lo;
                cvt_split(pre[t], hi, lo);
                char* th = base + (tile ? 2 : 0) * GTILEB;
                *(uint2*)(th + row * (GSTRIDE * 2) + ch * 8) = hi;
                *(uint2*)(th + GTILEB + row * (GSTRIDE * 2) + ch * 8) = lo;
            }
        } else {
            #pragma unroll
            for (int t = 0; t < 4; t++) {
                const int idx = t * 256 + tid;
                const int tile = idx >> 9;
                const int within = idx & 511;
                const int row = within >> 2;
                const int ch = within & 3;
                *(uint4*)(base + tile * GTILEB + row * (GSTRIDE * 2) + ch * 16) =
                    *(uint4*)&pre[t];
            }
            #pragma unroll
            for (int t = 4; t < 8; t++) {
                const int idx = (t - 4) * 256 + tid;
                const int row = idx >> 3;
                const int ch = idx & 7;
                uint2 hi, lo;
                cvt_split(pre[t], hi, lo);
                *(uint2*)(base + 2 * GTILEB + row * (GSTRIDE * 2) + ch * 8) = hi;
                *(uint2*)(base + 3 * GTILEB + row * (GSTRIDE * 2) + ch * 8) = lo;
            }
        }
    };

    load_stage(0);
    store_stage(0);
    __syncthreads();

    const uint32_t a_rowoff = (uint32_t)(lane & 15) * (GSTRIDE * 2);
    const uint32_t a_koff   = (uint32_t)(lane >> 4) * 16;
    const uint32_t b_rowoff = (uint32_t)(lane & 7) * (GSTRIDE * 2);
    const uint32_t b_koff   = (uint32_t)((lane >> 3) & 1) * 16;

    for (int s = 0; s < NS; s++) {
        if (s + 1 < NS) load_stage(s + 1);

        const uint32_t base = smem_u + (s & 1) * GBUFB;
        const uint32_t sAh = base;
        const uint32_t sAl = base + GTILEB;
        const uint32_t sWh = base + 2 * GTILEB;
        const uint32_t sWl = base + 3 * GTILEB;

        #pragma unroll
        for (int ks = 0; ks < 2; ks++) {
            const uint32_t kb = ks * 32;
            uint32_t ah[4][4], al[4][4], wh[4][2], wl[4][2];
            #pragma unroll
            for (int i = 0; i < 4; i++)
                ldsm_x4(ah[i], sAh + (warp_m * 64 + i * 16) * (GSTRIDE * 2) +
                               a_rowoff + kb + a_koff);
            #pragma unroll
            for (int j = 0; j < 4; j++)
                ldsm_x2(wh[j], sWh + (warp_n * 32 + j * 8) * (GSTRIDE * 2) +
                               b_rowoff + kb + b_koff);
            #pragma unroll
            for (int i = 0; i < 4; i++)
                #pragma unroll
                for (int j = 0; j < 4; j++)
                    mma_bf16(c[i][j], ah[i], wh[j]);

            #pragma unroll
            for (int j = 0; j < 4; j++)
                ldsm_x2(wl[j], sWl + (warp_n * 32 + j * 8) * (GSTRIDE * 2) +
                               b_rowoff + kb + b_koff);
            #pragma unroll
            for (int i = 0; i < 4; i++)
                #pragma unroll
                for (int j = 0; j < 4; j++)
                    mma_bf16(c[i][j], ah[i], wl[j]);

            #pragma unroll
            for (int i = 0; i < 4; i++)
                ldsm_x4(al[i], sAl + (warp_m * 64 + i * 16) * (GSTRIDE * 2) +
                               a_rowoff + kb + a_koff);
            #pragma unroll
            for (int i = 0; i < 4; i++)
                #pragma unroll
                for (int j = 0; j < 4; j++)
                    mma_bf16(c[i][j], al[i], wh[j]);
        }

        // Store next stage into the buffer NOT read this iteration.
        // Prior readers of that buffer completed before last __syncthreads.
        if (s + 1 < NS) store_stage((s + 1) & 1);
        __syncthreads();
    }

    const int trow = lane >> 2;
    const int tcol = (lane & 3) * 2;
    #pragma unroll
    for (int i = 0; i < 4; i++) {
        const int r0 = m0 + warp_m * 64 + i * 16 + trow;
        #pragma unroll
        for (int j = 0; j < 4; j++) {
            const int cc = n0 + warp_n * 32 + j * 8 + tcol;
            const float b0 = bias[cc];
            const float b1 = bias[cc + 1];
            float v00 = c[i][j][0] + b0, v01 = c[i][j][1] + b1;
            float v10 = c[i][j][2] + b0, v11 = c[i][j][3] + b1;
            const size_t p0 = (size_t)r0 * 1024 + cc;
            const size_t p1 = (size_t)(r0 + 8) * 1024 + cc;
            if (mode == 0) {
                *(float2*)&C[p0] = make_float2(v00, v01);
                *(float2*)&C[p1] = make_float2(v10, v11);
            } else if (mode == 1) {
                v00 *= scale; v01 *= scale; v10 *= scale; v11 *= scale;
                const __nv_bfloat16 h00 = __float2bfloat16(v00);
                const __nv_bfloat16 h01 = __float2bfloat16(v01);
                const __nv_bfloat16 h10 = __float2bfloat16(v10);
                const __nv_bfloat16 h11 = __float2bfloat16(v11);
                *(__nv_bfloat162*)&Oh[p0] = __nv_bfloat162(h00, h01);
                *(__nv_bfloat162*)&Oh[p1] = __nv_bfloat162(h10, h11);
                *(__nv_bfloat162*)&Ol[p0] = __nv_bfloat162(
                    __float2bfloat16(v00 - __bfloat162float(h00)),
                    __float2bfloat16(v01 - __bfloat162float(h01)));
                *(__nv_bfloat162*)&Ol[p1] = __nv_bfloat162(
                    __float2bfloat16(v10 - __bfloat162float(h10)),
                    __float2bfloat16(v11 - __bfloat162float(h11)));
            } else {
                *(__half2*)&Of[p0] = __floats2half2_rn(v00, v01);
                *(__half2*)&Of[p1] = __floats2half2_rn(v10, v11);
            }
        }
    }
}

// ---------------------------------------------------------------------------
// Tensor-core FlashAttention: BQ=64, BK=64, 4 warps (16 q-rows each).
// S = Q·K^T via split-bf16 (3 MMAs), P·V via fp16. P stays in registers.
// ---------------------------------------------------------------------------
constexpr int ASTR  = 72;                 // halves per smem row (144 B)
constexpr int ATILE = 64 * ASTR * 2;      // 9216 B
constexpr int SQH = 0;
constexpr int SQL = ATILE;
constexpr int SKH = 2 * ATILE;
constexpr int SKL = 3 * ATILE;
constexpr int SVV = 4 * ATILE;
constexpr int ATTN_SMEM = 5 * ATILE;      // 46080 B

__global__ __launch_bounds__(128) void attn_mma(
    const __nv_bfloat16* __restrict__ qh, const __nv_bfloat16* __restrict__ ql,
    const __nv_bfloat16* __restrict__ kh, const __nv_bfloat16* __restrict__ kl,
    const __half* __restrict__ vv, const float* __restrict__ maskf,
    const float* __restrict__ bias,
    __nv_bfloat16* __restrict__ cth, __nv_bfloat16* __restrict__ ctl)
{
    extern __shared__ char smem[];
    const uint32_t su = smem_to_u32(smem);
    const int tid = threadIdx.x;
    const int wid = tid >> 5;
    const int lane = tid & 31;
    const int g = lane >> 2;
    const int tig = lane & 3;
    const int q0 = blockIdx.x * 64;
    const int h = blockIdx.y;
    const int b = blockIdx.z;

    #pragma unroll
    for (int t = 0; t < 8; t++) {
        const int idx = t * 128 + tid;
        const int half_sel = idx >> 9;
        const int within = idx & 511;
        const int row = within >> 3;
        const int ch = within & 7;
        const __nv_bfloat16* src =
            (half_sel ? ql : qh) + ((size_t)(b * S_ + q0 + row)) * H_ +
            h * HD_ + ch * 8;
        *(uint4*)(smem + (half_sel ? SQL : SQH) + row * (ASTR * 2) + ch * 16) =
            *(const uint4*)src;
    }

    float ctx[8][4];
    #pragma unroll
    for (int j = 0; j < 8; j++)
        #pragma unroll
        for (int r = 0; r < 4; r++) ctx[j][r] = 0.0f;
    float m0_ = -1e30f, m1_ = -1e30f, l0_ = 0.0f, l1_ = 0.0f;

    const uint32_t a_rowoff = (uint32_t)(wid * 16 + (lane & 15)) * (ASTR * 2);
    const uint32_t a_koff   = (uint32_t)(lane >> 4) * 16;
    const uint32_t b_rowoff = (uint32_t)(lane & 7) * (ASTR * 2);
    const uint32_t b_koff   = (uint32_t)((lane >> 3) & 1) * 16;
    const uint32_t v_rowoff = (uint32_t)(lane & 15) * (ASTR * 2);

    const int qg0 = q0 + wid * 16 + g;
    const size_t bias_row0 = ((size_t)h * S_ + qg0) * S_ + 2 * tig;
    const size_t bias_row1 = bias_row0 + 8 * S_;

    for (int kt = 0; kt < S_ / 64; kt++) {
        const int k0 = kt * 64;
        __syncthreads();
        #pragma unroll
        for (int t = 0; t < 12; t++) {
            const int idx = t * 128 + tid;
            const int tile = idx >> 9;
            const int within = idx & 511;
            const int row = within >> 3;
            const int ch = within & 7;
            const size_t goff = ((size_t)(b * S_ + k0 + row)) * H_ + h * HD_ + ch * 8;
            uint4 val;
            if (tile == 0)      val = *(const uint4*)(kh + goff);
            else if (tile == 1) val = *(const uint4*)(kl + goff);
            else                val = *(const uint4*)(vv + goff);
            *(uint4*)(smem + SKH + tile * ATILE + row * (ASTR * 2) + ch * 16) = val;
        }
        __syncthreads();

        float c[8][4];
        #pragma unroll
        for (int j = 0; j < 8; j++)
            #pragma unroll
            for (int r = 0; r < 4; r++) c[j][r] = 0.0f;

        #pragma unroll
        for (int ks = 0; ks < 4; ks++) {
            const uint32_t kb = ks * 32;
            uint32_t ah[4], al[4];
            ldsm_x4(ah, su + SQH + a_rowoff + a_koff + kb);
            ldsm_x4(al, su + SQL + a_rowoff + a_koff + kb);
            #pragma unroll
            for (int j = 0; j < 8; j++) {
                uint32_t bh[2], bl[2];
                const uint32_t boff = (uint32_t)(j * 8) * (ASTR * 2) +
                                      b_rowoff + b_koff + kb;
                ldsm_x2(bh, su + SKH + boff);
                ldsm_x2(bl, su + SKL + boff);
                mma_bf16(c[j], ah, bh);
                mma_bf16(c[j], ah, bl);
                mma_bf16(c[j], al, bh);
            }
        }

        #pragma unroll
        for (int j = 0; j < 8; j++) {
            const float2 mk = *(const float2*)&maskf[b * S_ + k0 + j * 8 + 2 * tig];
            const float2 b0 = *(const float2*)&bias[bias_row0 + k0 + j * 8];
            const float2 b1 = *(const float2*)&bias[bias_row1 + k0 + j * 8];
            c[j][0] += b0.x + mk.x;
            c[j][1] += b0.y + mk.y;
            c[j][2] += b1.x + mk.x;
            c[j][3] += b1.y + mk.y;
        }

        float mx0 = -1e30f, mx1 = -1e30f;
        #pragma unroll
        for (int j = 0; j < 8; j++) {
            mx0 = fmaxf(mx0, fmaxf(c[j][0], c[j][1]));
            mx1 = fmaxf(mx1, fmaxf(c[j][2], c[j][3]));
        }
        mx0 = fmaxf(mx0, __shfl_xor_sync(0xffffffffu, mx0, 1));
        mx0 = fmaxf(mx0, __shfl_xor_sync(0xffffffffu, mx0, 2));
        mx1 = fmaxf(mx1, __shfl_xor_sync(0xffffffffu, mx1, 1));
        mx1 = fmaxf(mx1, __shfl_xor_sync(0xffffffffu, mx1, 2));

        const float mo0 = m0_, mo1 = m1_;
        m0_ = fmaxf(m0_, mx0);
        m1_ = fmaxf(m1_, mx1);
        const float alpha0 = __expf(mo0 - m0_);
        const float alpha1 = __expf(mo1 - m1_);

        float sum0 = 0.0f, sum1 = 0.0f;
        uint32_t ap[4][4];
        #pragma unroll
        for (int j = 0; j < 8; j++) {
            c[j][0] = __expf(c[j][0] - m0_);
            c[j][1] = __expf(c[j][1] - m0_);
            c[j][2] = __expf(c[j][2] - m1_);
            c[j][3] = __expf(c[j][3] - m1_);
            sum0 += c[j][0] + c[j][1];
            sum1 += c[j][2] + c[j][3];
        }
        l0_ = l0_ * alpha0 + sum0;
        l1_ = l1_ * alpha1 + sum1;

        #pragma unroll
        for (int t = 0; t < 4; t++) {
            __half2 h0 = __floats2half2_rn(c[2 * t][0], c[2 * t][1]);
            __half2 h1 = __floats2half2_rn(c[2 * t][2], c[2 * t][3]);
            __half2 h2 = __floats2half2_rn(c[2 * t + 1][0], c[2 * t + 1][1]);
            __half2 h3 = __floats2half2_rn(c[2 * t + 1][2], c[2 * t + 1][3]);
            ap[t][0] = *(uint32_t*)&h0;
            ap[t][1] = *(uint32_t*)&h1;
            ap[t][2] = *(uint32_t*)&h2;
            ap[t][3] = *(uint32_t*)&h3;
        }

        #pragma unroll
        for (int j = 0; j < 8; j++) {
            ctx[j][0] *= alpha0;
            ctx[j][1] *= alpha0;
            ctx[j][2] *= alpha1;
            ctx[j][3] *= alpha1;
        }

        #pragma unroll
        for (int t = 0; t < 4; t++) {
            const uint32_t vbase = su + SVV + (uint32_t)(t * 16) * (ASTR * 2) + v_rowoff;
            #pragma unroll
            for (int jd = 0; jd < 8; jd++) {
                uint32_t bv[2];
                ldsm_x2_trans(bv, vbase + jd * 16);
                mma_f16(ctx[jd], ap[t], bv);
            }
        }
    }

    l0_ += __shfl_xor_sync(0xffffffffu, l0_, 1);
    l0_ += __shfl_xor_sync(0xffffffffu, l0_, 2);
    l1_ += __shfl_xor_sync(0xffffffffu, l1_, 1);
    l1_ += __shfl_xor_sync(0xffffffffu, l1_, 2);
    const float inv0 = 1.0f / fmaxf(l0_, 1e-6f);
    const float inv1 = 1.0f / fmaxf(l1_, 1e-6f);

    const size_t orow0 = ((size_t)(b * S_ + qg0)) * H_ + h * HD_ + 2 * tig;
    const size_t orow1 = orow0 + 8 * H_;
    #pragma unroll
    for (int jd = 0; jd < 8; jd++) {
        const float v00 = ctx[jd][0] * inv0, v01 = ctx[jd][1] * inv0;
        const float v10 = ctx[jd][2] * inv1, v11 = ctx[jd][3] * inv1;
        const __nv_bfloat16 h00 = __float2bfloat16(v00);
        const __nv_bfloat16 h01 = __float2bfloat16(v01);
        const __nv_bfloat16 h10 = __float2bfloat16(v10);
        const __nv_bfloat16 h11 = __float2bfloat16(v11);
        *(__nv_bfloat162*)&cth[orow0 + jd * 8] = __nv_bfloat162(h00, h01);
        *(__nv_bfloat162*)&cth[orow1 + jd * 8] = __nv_bfloat162(h10, h11);
        *(__nv_bfloat162*)&ctl[orow0 + jd * 8] = __nv_bfloat162(
            __float2bfloat16(v00 - __bfloat162float(h00)),
            __float2bfloat16(v01 - __bfloat162float(h01)));
        *(__nv_bfloat162*)&ctl[orow1 + jd * 8] = __nv_bfloat162(
            __float2bfloat16(v10 - __bfloat162float(h10)),
            __float2bfloat16(v11 - __bfloat162float(h11)));
    }
}

// ---------------------------------------------------------------------------
// Launch
// ---------------------------------------------------------------------------
extern "C" void kernel_launch(void* const* d_in, const int* in_sizes, int n_in,
                              void* d_out, int out_size)
{
    (void)in_sizes; (void)n_in; (void)out_size;

    const float* query = (const float*)d_in[0];
    const float* key_t = (const float*)d_in[1];
    const float* value = (const float*)d_in[2];
    const unsigned int* kpm_raw = (const unsigned int*)d_in[3];
    const float* bias  = (const float*)d_in[4];
    const float* q_w = (const float*)d_in[5];
    const float* q_b = (const float*)d_in[6];
    const float* k_w = (const float*)d_in[7];
    const float* k_b = (const float*)d_in[8];
    const float* v_w = (const float*)d_in[9];
    const float* v_b = (const float*)d_in[10];
    const float* o_w = (const float*)d_in[11];
    const float* o_b = (const float*)d_in[12];
    float* out = (float*)d_out;

    __nv_bfloat16 *gqh, *gql, *gkh, *gkl, *gcth, *gctl;
    __half* gvh;
    float* gmaskf;
    cudaGetSymbolAddress((void**)&gqh, g_qh);
    cudaGetSymbolAddress((void**)&gql, g_ql);
    cudaGetSymbolAddress((void**)&gkh, g_kh);
    cudaGetSymbolAddress((void**)&gkl, g_kl);
    cudaGetSymbolAddress((void**)&gvh, g_vh);
    cudaGetSymbolAddress((void**)&gcth, g_cth);
    cudaGetSymbolAddress((void**)&gctl, g_ctl);
    cudaGetSymbolAddress((void**)&gmaskf, g_maskf);

    cudaFuncSetAttribute(gemm_mma,
                         cudaFuncAttributeMaxDynamicSharedMemorySize, GEMM_SMEM);
    cudaFuncSetAttribute(attn_mma,
                         cudaFuncAttributeMaxDynamicSharedMemorySize, ATTN_SMEM);

    mask_normalize<<<1, 1024>>>(kpm_raw);

    const dim3 gemm_grid(H_ / 128, M_ / 128);   // (8, 32)

    // Q projection -> bf16 hi/lo, pre-scaled by 1/sqrt(HD)
    gemm_mma<<<gemm_grid, 256, GEMM_SMEM>>>(query, nullptr, nullptr, q_w, q_b,
                                            nullptr, gqh, gql, nullptr,
                                            0, 1, 0.125f, H_);
    // K projection -> bf16 hi/lo
    gemm_mma<<<gemm_grid, 256, GEMM_SMEM>>>(key_t, nullptr, nullptr, k_w, k_b,
                                            nullptr, gkh, gkl, nullptr,
                                            0, 1, 1.0f, H_);
    // V projection -> fp16
    gemm_mma<<<gemm_grid, 256, GEMM_SMEM>>>(value, nullptr, nullptr, v_w, v_b,
                                            nullptr, nullptr, nullptr, gvh,
                                            0, 2, 1.0f, H_);

    attn_mma<<<dim3(S_ / 64, NH_, B_), 128, ATTN_SMEM>>>(
        gqh, gql, gkh, gkl, gvh, gmaskf, bias, gcth, gctl);

    // Output projection (ctx pre-split by attention epilogue)
    gemm_mma<<<gemm_grid, 256, GEMM_SMEM>>>(nullptr, gcth, gctl, o_w, o_b,
                                            out, nullptr, nullptr, nullptr,
                                            1, 0, 1.0f, H_);
}

// round 8
// speedup vs baseline: 3.5456x; 1.1221x over previous
#include <cuda_runtime.h>
#include <cuda_bf16.h>
#include <cuda_fp16.h>
#include <cstdint>
#include <cstddef>

// Problem constants
constexpr int B_  = 2;
constexpr int S_  = 2048;
constexpr int H_  = 1024;
constexpr int NH_ = 16;
constexpr int HD_ = 64;
constexpr int M_  = B_ * S_;   // 4096

// Scratch (allocation-free: __device__ globals)
__device__ float g_maskf[B_ * S_];
__device__ float g_qf[(size_t)M_ * H_];
__device__ float g_kf[(size_t)M_ * H_];
__device__ __half g_vh[(size_t)M_ * H_];
__device__ float g_ctx[(size_t)M_ * H_];

// ---------------------------------------------------------------------------
// Warp-MMA helpers (portable ISA, plain sm_103 target)
// ---------------------------------------------------------------------------
__device__ __forceinline__ uint32_t smem_to_u32(const void* p) {
    uint32_t a;
    asm("{ .reg .u64 t; cvta.to.shared.u64 t, %1; cvt.u32.u64 %0, t; }"
        : "=r"(a) : "l"(p));
    return a;
}
__device__ __forceinline__ void ldsm_x4(uint32_t r[4], uint32_t a) {
    asm volatile("ldmatrix.sync.aligned.m8n8.x4.shared.b16 {%0,%1,%2,%3}, [%4];"
                 : "=r"(r[0]), "=r"(r[1]), "=r"(r[2]), "=r"(r[3]) : "r"(a));
}
__device__ __forceinline__ void ldsm_x2(uint32_t r[2], uint32_t a) {
    asm volatile("ldmatrix.sync.aligned.m8n8.x2.shared.b16 {%0,%1}, [%2];"
                 : "=r"(r[0]), "=r"(r[1]) : "r"(a));
}
__device__ __forceinline__ void ldsm_x2_trans(uint32_t r[2], uint32_t a) {
    asm volatile("ldmatrix.sync.aligned.m8n8.x2.trans.shared.b16 {%0,%1}, [%2];"
                 : "=r"(r[0]), "=r"(r[1]) : "r"(a));
}
// mma m16n8k8 tf32: A row-major (4 b32), B col-major (2 b32)
__device__ __forceinline__ void mma_tf32(float c[4], const uint32_t a[4],
                                         const uint32_t b[2]) {
    asm volatile(
        "mma.sync.aligned.m16n8k8.row.col.f32.tf32.tf32.f32 "
        "{%0,%1,%2,%3}, {%4,%5,%6,%7}, {%8,%9}, {%0,%1,%2,%3};"
        : "+f"(c[0]), "+f"(c[1]), "+f"(c[2]), "+f"(c[3])
        : "r"(a[0]), "r"(a[1]), "r"(a[2]), "r"(a[3]), "r"(b[0]), "r"(b[1]));
}
__device__ __forceinline__ void mma_f16(float c[4], const uint32_t a[4],
                                        const uint32_t b[2]) {
    asm volatile(
        "mma.sync.aligned.m16n8k16.row.col.f32.f16.f16.f32 "
        "{%0,%1,%2,%3}, {%4,%5,%6,%7}, {%8,%9}, {%0,%1,%2,%3};"
        : "+f"(c[0]), "+f"(c[1]), "+f"(c[2]), "+f"(c[3])
        : "r"(a[0]), "r"(a[1]), "r"(a[2]), "r"(a[3]), "r"(b[0]), "r"(b[1]));
}
__device__ __forceinline__ uint32_t to_tf32(float f) {
    uint32_t r;
    asm("cvt.rna.tf32.f32 %0, %1;" : "=r"(r) : "f"(f));
    return r;
}
__device__ __forceinline__ uint4 tf32x4(float4 v) {
    uint4 o;
    o.x = to_tf32(v.x); o.y = to_tf32(v.y);
    o.z = to_tf32(v.z); o.w = to_tf32(v.w);
    return o;
}

// ---------------------------------------------------------------------------
// Mask normalization -> float (-1e30 / 0) form
// ---------------------------------------------------------------------------
__global__ void mask_normalize(const unsigned int* __restrict__ w)
{
    __shared__ unsigned int flags;
    const int tid = threadIdx.x;
    if (tid == 0) flags = 0u;
    __syncthreads();
    const unsigned int x = w[tid];
    unsigned int f = 0u;
    if (x != 0u && x != 1u && x != 0x3F800000u) f |= 1u;
    if (x == 0x3F800000u) f |= 2u;
    if (f) atomicOr(&flags, f);
    __syncthreads();
    const int byte_mode = (flags & 1u) ? 1 : 0;
    if (byte_mode) {
        const unsigned char* b8 = (const unsigned char*)w;
        for (int i = tid; i < B_ * S_; i += 1024)
            g_maskf[i] = (b8[i] != 0) ? -1e30f : 0.0f;
    } else {
        for (int i = tid; i < B_ * S_; i += 1024)
            g_maskf[i] = (w[i] != 0u) ? -1e30f : 0.0f;
    }
}

// ---------------------------------------------------------------------------
// TF32 HMMA GEMM (NT): C[M,N] = A[M,K] @ W[N,K]^T + bias
// 128x128 CTA tile, BK=32, 8 warps (2x4), warp tile 64x32 (4 m16 x 4 n8).
// fp32 operands cvt.rna to tf32 at smem staging. Double-buffered, 1 sync/stage.
// Modes: 0 = fp32*scale to C; 2 = fp16 to Of.
// Row stride 144 B; rows hold 32 floats = 128 B <= 144 OK.
// ---------------------------------------------------------------------------
constexpr int GSTR = 36;                     // floats per smem row (144 B)
constexpr int GTILEF = 128 * GSTR * 4;       // 18432 B per tile
constexpr int GBUFB = 2 * GTILEF;            // A + W per stage
constexpr int GEMM_SMEM = 2 * GBUFB;         // 73728 B

__global__ __launch_bounds__(256, 1) void gemm_tf32(
    const float* __restrict__ A, const float* __restrict__ W,
    const float* __restrict__ bias, float* __restrict__ C,
    __half* __restrict__ Of, int mode, float scale, int K)
{
    extern __shared__ char smem[];
    const uint32_t smem_u = smem_to_u32(smem);
    const int tid  = threadIdx.x;
    const int wid  = tid >> 5;
    const int lane = tid & 31;
    const int warp_m = wid >> 2;
    const int warp_n = wid & 3;
    const int m0 = blockIdx.y * 128;
    const int n0 = blockIdx.x * 128;

    float c[4][4][4];
    #pragma unroll
    for (int i = 0; i < 4; i++)
        #pragma unroll
        for (int j = 0; j < 4; j++)
            #pragma unroll
            for (int r = 0; r < 4; r++) c[i][j][r] = 0.0f;

    const int NS = K / 32;

    float4 pre[8];
    auto load_stage = [&](int s) {
        const int k0 = s * 32;
        #pragma unroll
        for (int t = 0; t < 8; t++) {
            const int idx = t * 256 + tid;
            const int tile = idx >> 10;            // 0=A, 1=W
            const int within = idx & 1023;
            const int row = within >> 3;
            const int ch = within & 7;
            const float* src = tile ? (W + (size_t)(n0 + row) * K)
                                    : (A + (size_t)(m0 + row) * K);
            pre[t] = *(const float4*)(src + k0 + ch * 4);
        }
    };
    auto store_stage = [&](int buf) {
        char* base = smem + buf * GBUFB;
        #pragma unroll
        for (int t = 0; t < 8; t++) {
            const int idx = t * 256 + tid;
            const int tile = idx >> 10;
            const int within = idx & 1023;
            const int row = within >> 3;
            const int ch = within & 7;
            *(uint4*)(base + tile * GTILEF + row * (GSTR * 4) + ch * 16) =
                tf32x4(pre[t]);
        }
    };

    load_stage(0);
    store_stage(0);
    __syncthreads();

    const uint32_t a_rowoff = (uint32_t)(lane & 15) * (GSTR * 4);
    const uint32_t a_koff   = (uint32_t)(lane >> 4) * 16;
    const uint32_t b_rowoff = (uint32_t)(lane & 7) * (GSTR * 4);
    const uint32_t b_koff   = (uint32_t)((lane >> 3) & 1) * 16;

    for (int s = 0; s < NS; s++) {
        if (s + 1 < NS) load_stage(s + 1);

        const uint32_t base = smem_u + (s & 1) * GBUFB;
        const uint32_t sA = base;
        const uint32_t sW = base + GTILEF;

        #pragma unroll
        for (int ks = 0; ks < 4; ks++) {
            const uint32_t kb = ks * 32;           // 8 floats
            uint32_t a[4][4], b[4][2];
            #pragma unroll
            for (int i = 0; i < 4; i++)
                ldsm_x4(a[i], sA + (warp_m * 64 + i * 16) * (GSTR * 4) +
                              a_rowoff + kb + a_koff);
            #pragma unroll
            for (int j = 0; j < 4; j++)
                ldsm_x2(b[j], sW + (warp_n * 32 + j * 8) * (GSTR * 4) +
                              b_rowoff + kb + b_koff);
            #pragma unroll
            for (int i = 0; i < 4; i++)
                #pragma unroll
                for (int j = 0; j < 4; j++)
                    mma_tf32(c[i][j], a[i], b[j]);
        }

        if (s + 1 < NS) store_stage((s + 1) & 1);
        __syncthreads();
    }

    const int trow = lane >> 2;
    const int tcol = (lane & 3) * 2;
    #pragma unroll
    for (int i = 0; i < 4; i++) {
        const int r0 = m0 + warp_m * 64 + i * 16 + trow;
        #pragma unroll
        for (int j = 0; j < 4; j++) {
            const int cc = n0 + warp_n * 32 + j * 8 + tcol;
            const float b0 = bias[cc];
            const float b1 = bias[cc + 1];
            const float v00 = (c[i][j][0] + b0) * scale;
            const float v01 = (c[i][j][1] + b1) * scale;
            const float v10 = (c[i][j][2] + b0) * scale;
            const float v11 = (c[i][j][3] + b1) * scale;
            const size_t p0 = (size_t)r0 * 1024 + cc;
            const size_t p1 = (size_t)(r0 + 8) * 1024 + cc;
            if (mode == 0) {
                *(float2*)&C[p0] = make_float2(v00, v01);
                *(float2*)&C[p1] = make_float2(v10, v11);
            } else {
                *(__half2*)&Of[p0] = __floats2half2_rn(v00, v01);
                *(__half2*)&Of[p1] = __floats2half2_rn(v10, v11);
            }
        }
    }
}

// ---------------------------------------------------------------------------
// TF32 FlashAttention: BQ=64, BK=64, 4 warps (16 q-rows each).
// S = Q·K^T single-pass tf32, P·V fp16. P stays in registers.
// Q/K tiles are fp32: 64 floats/row = 256 B -> row stride 272 B (padded).
// V tile fp16: 128 B/row -> stride 144 B.
// ---------------------------------------------------------------------------
constexpr int QKSTRB = 272;               // bytes per Q/K smem row
constexpr int VSTRB  = 144;               // bytes per V smem row
constexpr int QKTILE = 64 * QKSTRB;       // 17408 B
constexpr int VTILE  = 64 * VSTRB;        // 9216 B
constexpr int SQ = 0;
constexpr int SK = QKTILE;
constexpr int SV = 2 * QKTILE;
constexpr int ATTN_SMEM = 2 * QKTILE + VTILE;   // 44032 B

__global__ __launch_bounds__(128) void attn_tf32(
    const float* __restrict__ qf, const float* __restrict__ kf,
    const __half* __restrict__ vv, const float* __restrict__ maskf,
    const float* __restrict__ bias, float* __restrict__ ctxo)
{
    extern __shared__ char smem[];
    const uint32_t su = smem_to_u32(smem);
    const int tid = threadIdx.x;
    const int wid = tid >> 5;
    const int lane = tid & 31;
    const int g = lane >> 2;
    const int tig = lane & 3;
    const int q0 = blockIdx.x * 64;
    const int h = blockIdx.y;
    const int b = blockIdx.z;

    // Stage Q (fp32 -> tf32): 64 rows x 16 float4 = 1024 chunks, 8/thread
    #pragma unroll
    for (int t = 0; t < 8; t++) {
        const int idx = t * 128 + tid;
        const int row = idx >> 4;
        const int ch = idx & 15;
        const float4 v = *(const float4*)
            &qf[((size_t)(b * S_ + q0 + row)) * H_ + h * HD_ + ch * 4];
        *(uint4*)(smem + SQ + row * QKSTRB + ch * 16) = tf32x4(v);
    }

    float ctx[8][4];
    #pragma unroll
    for (int j = 0; j < 8; j++)
        #pragma unroll
        for (int r = 0; r < 4; r++) ctx[j][r] = 0.0f;
    float m0_ = -1e30f, m1_ = -1e30f, l0_ = 0.0f, l1_ = 0.0f;

    const uint32_t a_rowoff = (uint32_t)(wid * 16 + (lane & 15)) * QKSTRB;
    const uint32_t a_koff   = (uint32_t)(lane >> 4) * 16;
    const uint32_t b_rowoff = (uint32_t)(lane & 7) * QKSTRB;
    const uint32_t b_koff   = (uint32_t)((lane >> 3) & 1) * 16;
    const uint32_t v_rowoff = (uint32_t)(lane & 15) * VSTRB;

    const int qg0 = q0 + wid * 16 + g;
    const size_t bias_row0 = ((size_t)h * S_ + qg0) * S_ + 2 * tig;
    const size_t bias_row1 = bias_row0 + 8 * S_;

    for (int kt = 0; kt < S_ / 64; kt++) {
        const int k0 = kt * 64;
        __syncthreads();
        // K fp32->tf32 (1024 chunks) + V fp16 raw (512 chunks): 12/thread
        #pragma unroll
        for (int t = 0; t < 12; t++) {
            const int idx = t * 128 + tid;
            if (idx < 1024) {
                const int row = idx >> 4;
                const int ch = idx & 15;
                const float4 v = *(const float4*)
                    &kf[((size_t)(b * S_ + k0 + row)) * H_ + h * HD_ + ch * 4];
                *(uint4*)(smem + SK + row * QKSTRB + ch * 16) = tf32x4(v);
            } else {
                const int w = idx - 1024;
                const int row = w >> 3;
                const int ch = w & 7;
                *(uint4*)(smem + SV + row * VSTRB + ch * 16) =
                    *(const uint4*)
                    &vv[((size_t)(b * S_ + k0 + row)) * H_ + h * HD_ + ch * 8];
            }
        }
        __syncthreads();

        // ---- S = Q·K^T (tf32, single pass) ----
        float c[8][4];
        #pragma unroll
        for (int j = 0; j < 8; j++)
            #pragma unroll
            for (int r = 0; r < 4; r++) c[j][r] = 0.0f;

        #pragma unroll
        for (int ks = 0; ks < 8; ks++) {
            const uint32_t kb = ks * 32;           // 8 floats
            uint32_t aq[4];
            ldsm_x4(aq, su + SQ + a_rowoff + kb + a_koff);
            #pragma unroll
            for (int j = 0; j < 8; j++) {
                uint32_t bk[2];
                ldsm_x2(bk, su + SK + (uint32_t)(j * 8) * QKSTRB +
                            b_rowoff + kb + b_koff);
                mma_tf32(c[j], aq, bk);
            }
        }

        // ---- bias + mask ----
        #pragma unroll
        for (int j = 0; j < 8; j++) {
            const float2 mk = *(const float2*)&maskf[b * S_ + k0 + j * 8 + 2 * tig];
            const float2 b0 = *(const float2*)&bias[bias_row0 + k0 + j * 8];
            const float2 b1 = *(const float2*)&bias[bias_row1 + k0 + j * 8];
            c[j][0] += b0.x + mk.x;
            c[j][1] += b0.y + mk.y;
            c[j][2] += b1.x + mk.x;
            c[j][3] += b1.y + mk.y;
        }

        // ---- online softmax ----
        float mx0 = -1e30f, mx1 = -1e30f;
        #pragma unroll
        for (int j = 0; j < 8; j++) {
            mx0 = fmaxf(mx0, fmaxf(c[j][0], c[j][1]));
            mx1 = fmaxf(mx1, fmaxf(c[j][2], c[j][3]));
        }
        mx0 = fmaxf(mx0, __shfl_xor_sync(0xffffffffu, mx0, 1));
        mx0 = fmaxf(mx0, __shfl_xor_sync(0xffffffffu, mx0, 2));
        mx1 = fmaxf(mx1, __shfl_xor_sync(0xffffffffu, mx1, 1));
        mx1 = fmaxf(mx1, __shfl_xor_sync(0xffffffffu, mx1, 2));

        const float mo0 = m0_, mo1 = m1_;
        m0_ = fmaxf(m0_, mx0);
        m1_ = fmaxf(m1_, mx1);
        const float alpha0 = __expf(mo0 - m0_);
        const float alpha1 = __expf(mo1 - m1_);

        float sum0 = 0.0f, sum1 = 0.0f;
        uint32_t ap[4][4];
        #pragma unroll
        for (int j = 0; j < 8; j++) {
            c[j][0] = __expf(c[j][0] - m0_);
            c[j][1] = __expf(c[j][1] - m0_);
            c[j][2] = __expf(c[j][2] - m1_);
            c[j][3] = __expf(c[j][3] - m1_);
            sum0 += c[j][0] + c[j][1];
            sum1 += c[j][2] + c[j][3];
        }
        l0_ = l0_ * alpha0 + sum0;
        l1_ = l1_ * alpha1 + sum1;

        #pragma unroll
        for (int t = 0; t < 4; t++) {
            __half2 h0 = __floats2half2_rn(c[2 * t][0], c[2 * t][1]);
            __half2 h1 = __floats2half2_rn(c[2 * t][2], c[2 * t][3]);
            __half2 h2 = __floats2half2_rn(c[2 * t + 1][0], c[2 * t + 1][1]);
            __half2 h3 = __floats2half2_rn(c[2 * t + 1][2], c[2 * t + 1][3]);
            ap[t][0] = *(uint32_t*)&h0;
            ap[t][1] = *(uint32_t*)&h1;
            ap[t][2] = *(uint32_t*)&h2;
            ap[t][3] = *(uint32_t*)&h3;
        }

        #pragma unroll
        for (int j = 0; j < 8; j++) {
            ctx[j][0] *= alpha0;
            ctx[j][1] *= alpha0;
            ctx[j][2] *= alpha1;
            ctx[j][3] *= alpha1;
        }

        // ---- ctx += P·V (fp16) ----
        #pragma unroll
        for (int t = 0; t < 4; t++) {
            const uint32_t vbase = su + SV + (uint32_t)(t * 16) * VSTRB + v_rowoff;
            #pragma unroll
            for (int jd = 0; jd < 8; jd++) {
                uint32_t bv[2];
                ldsm_x2_trans(bv, vbase + jd * 16);
                mma_f16(ctx[jd], ap[t], bv);
            }
        }
    }

    l0_ += __shfl_xor_sync(0xffffffffu, l0_, 1);
    l0_ += __shfl_xor_sync(0xffffffffu, l0_, 2);
    l1_ += __shfl_xor_sync(0xffffffffu, l1_, 1);
    l1_ += __shfl_xor_sync(0xffffffffu, l1_, 2);
    const float inv0 = 1.0f / fmaxf(l0_, 1e-6f);
    const float inv1 = 1.0f / fmaxf(l1_, 1e-6f);

    const size_t orow0 = ((size_t)(b * S_ + qg0)) * H_ + h * HD_ + 2 * tig;
    const size_t orow1 = orow0 + 8 * H_;
    #pragma unroll
    for (int jd = 0; jd < 8; jd++) {
        *(float2*)&ctxo[orow0 + jd * 8] =
            make_float2(ctx[jd][0] * inv0, ctx[jd][1] * inv0);
        *(float2*)&ctxo[orow1 + jd * 8] =
            make_float2(ctx[jd][2] * inv1, ctx[jd][3] * inv1);
    }
}

// ---------------------------------------------------------------------------
// Launch
// ---------------------------------------------------------------------------
extern "C" void kernel_launch(void* const* d_in, const int* in_sizes, int n_in,
                              void* d_out, int out_size)
{
    (void)in_sizes; (void)n_in; (void)out_size;

    const float* query = (const float*)d_in[0];
    const float* key_t = (const float*)d_in[1];
    const float* value = (const float*)d_in[2];
    const unsigned int* kpm_raw = (const unsigned int*)d_in[3];
    const float* bias  = (const float*)d_in[4];
    const float* q_w = (const float*)d_in[5];
    const float* q_b = (const float*)d_in[6];
    const float* k_w = (const float*)d_in[7];
    const float* k_b = (const float*)d_in[8];
    const float* v_w = (const float*)d_in[9];
    const float* v_b = (const float*)d_in[10];
    const float* o_w = (const float*)d_in[11];
    const float* o_b = (const float*)d_in[12];
    float* out = (float*)d_out;

    float *gqf, *gkf, *gctx, *gmaskf;
    __half* gvh;
    cudaGetSymbolAddress((void**)&gqf, g_qf);
    cudaGetSymbolAddress((void**)&gkf, g_kf);
    cudaGetSymbolAddress((void**)&gvh, g_vh);
    cudaGetSymbolAddress((void**)&gctx, g_ctx);
    cudaGetSymbolAddress((void**)&gmaskf, g_maskf);

    cudaFuncSetAttribute(gemm_tf32,
                         cudaFuncAttributeMaxDynamicSharedMemorySize, GEMM_SMEM);
    cudaFuncSetAttribute(attn_tf32,
                         cudaFuncAttributeMaxDynamicSharedMemorySize, ATTN_SMEM);

    mask_normalize<<<1, 1024>>>(kpm_raw);

    const dim3 gemm_grid(H_ / 128, M_ / 128);   // (8, 32)

    // Q projection -> fp32 (pre-scaled by 1/sqrt(HD))
    gemm_tf32<<<gemm_grid, 256, GEMM_SMEM>>>(query, q_w, q_b, gqf, nullptr,
                                             0, 0.125f, H_);
    // K projection -> fp32
    gemm_tf32<<<gemm_grid, 256, GEMM_SMEM>>>(key_t, k_w, k_b, gkf, nullptr,
                                             0, 1.0f, H_);
    // V projection -> fp16
    gemm_tf32<<<gemm_grid, 256, GEMM_SMEM>>>(value, v_w, v_b, nullptr, gvh,
                                             2, 1.0f, H_);

    attn_tf32<<<dim3(S_ / 64, NH_, B_), 128, ATTN_SMEM>>>(
        gqf, gkf, gvh, gmaskf, bias, gctx);

    // Output projection
    gemm_tf32<<<gemm_grid, 256, GEMM_SMEM>>>(gctx, o_w, o_b, out, nullptr,
                                             0, 1.0f, H_);
}

// round 9
// speedup vs baseline: 3.6872x; 1.0400x over previous
#include <cuda_runtime.h>
#include <cuda_bf16.h>
#include <cuda_fp16.h>
#include <cstdint>
#include <cstddef>

// Problem constants
constexpr int B_  = 2;
constexpr int S_  = 2048;
constexpr int H_  = 1024;
constexpr int NH_ = 16;
constexpr int HD_ = 64;
constexpr int M_  = B_ * S_;   // 4096

// Scratch (allocation-free: __device__ globals)
__device__ float g_maskf[B_ * S_];
__device__ float g_qf[(size_t)M_ * H_];
__device__ float g_kf[(size_t)M_ * H_];
__device__ __half g_vh[(size_t)M_ * H_];
__device__ float g_ctx[(size_t)M_ * H_];

// ---------------------------------------------------------------------------
// Warp-MMA helpers (portable ISA, plain sm_103 target)
// ---------------------------------------------------------------------------
__device__ __forceinline__ uint32_t smem_to_u32(const void* p) {
    uint32_t a;
    asm("{ .reg .u64 t; cvta.to.shared.u64 t, %1; cvt.u32.u64 %0, t; }"
        : "=r"(a) : "l"(p));
    return a;
}
__device__ __forceinline__ void ldsm_x4(uint32_t r[4], uint32_t a) {
    asm volatile("ldmatrix.sync.aligned.m8n8.x4.shared.b16 {%0,%1,%2,%3}, [%4];"
                 : "=r"(r[0]), "=r"(r[1]), "=r"(r[2]), "=r"(r[3]) : "r"(a));
}
__device__ __forceinline__ void ldsm_x2(uint32_t r[2], uint32_t a) {
    asm volatile("ldmatrix.sync.aligned.m8n8.x2.shared.b16 {%0,%1}, [%2];"
                 : "=r"(r[0]), "=r"(r[1]) : "r"(a));
}
__device__ __forceinline__ void ldsm_x2_trans(uint32_t r[2], uint32_t a) {
    asm volatile("ldmatrix.sync.aligned.m8n8.x2.trans.shared.b16 {%0,%1}, [%2];"
                 : "=r"(r[0]), "=r"(r[1]) : "r"(a));
}
__device__ __forceinline__ void mma_tf32(float c[4], const uint32_t a[4],
                                         const uint32_t b[2]) {
    asm volatile(
        "mma.sync.aligned.m16n8k8.row.col.f32.tf32.tf32.f32 "
        "{%0,%1,%2,%3}, {%4,%5,%6,%7}, {%8,%9}, {%0,%1,%2,%3};"
        : "+f"(c[0]), "+f"(c[1]), "+f"(c[2]), "+f"(c[3])
        : "r"(a[0]), "r"(a[1]), "r"(a[2]), "r"(a[3]), "r"(b[0]), "r"(b[1]));
}
__device__ __forceinline__ void mma_f16(float c[4], const uint32_t a[4],
                                        const uint32_t b[2]) {
    asm volatile(
        "mma.sync.aligned.m16n8k16.row.col.f32.f16.f16.f32 "
        "{%0,%1,%2,%3}, {%4,%5,%6,%7}, {%8,%9}, {%0,%1,%2,%3};"
        : "+f"(c[0]), "+f"(c[1]), "+f"(c[2]), "+f"(c[3])
        : "r"(a[0]), "r"(a[1]), "r"(a[2]), "r"(a[3]), "r"(b[0]), "r"(b[1]));
}
__device__ __forceinline__ uint32_t to_tf32(float f) {
    uint32_t r;
    asm("cvt.rna.tf32.f32 %0, %1;" : "=r"(r) : "f"(f));
    return r;
}
__device__ __forceinline__ uint4 tf32x4(float4 v) {
    uint4 o;
    o.x = to_tf32(v.x); o.y = to_tf32(v.y);
    o.z = to_tf32(v.z); o.w = to_tf32(v.w);
    return o;
}
__device__ __forceinline__ void cp_async16(uint32_t saddr, const void* gptr) {
    asm volatile("cp.async.cg.shared.global [%0], [%1], 16;"
                 :: "r"(saddr), "l"(gptr));
}
#define CP_COMMIT() asm volatile("cp.async.commit_group;" ::: "memory")
#define CP_WAIT1()  asm volatile("cp.async.wait_group 1;" ::: "memory")

// ---------------------------------------------------------------------------
// Mask normalization -> float (-1e30 / 0) form
// ---------------------------------------------------------------------------
__global__ void mask_normalize(const unsigned int* __restrict__ w)
{
    __shared__ unsigned int flags;
    const int tid = threadIdx.x;
    if (tid == 0) flags = 0u;
    __syncthreads();
    const unsigned int x = w[tid];
    unsigned int f = 0u;
    if (x != 0u && x != 1u && x != 0x3F800000u) f |= 1u;
    if (x == 0x3F800000u) f |= 2u;
    if (f) atomicOr(&flags, f);
    __syncthreads();
    const int byte_mode = (flags & 1u) ? 1 : 0;
    if (byte_mode) {
        const unsigned char* b8 = (const unsigned char*)w;
        for (int i = tid; i < B_ * S_; i += 1024)
            g_maskf[i] = (b8[i] != 0) ? -1e30f : 0.0f;
    } else {
        for (int i = tid; i < B_ * S_; i += 1024)
            g_maskf[i] = (w[i] != 0u) ? -1e30f : 0.0f;
    }
}

// ---------------------------------------------------------------------------
// TF32 HMMA GEMM (NT): C[M,N] = A[M,K] @ W[N,K]^T + bias
// Modes: 0 = fp32*scale; 2 = fp16; 3 = fp32*scale rounded to tf32 (for Q/K).
// ---------------------------------------------------------------------------
constexpr int GSTR = 36;                     // floats per smem row (144 B)
constexpr int GTILEF = 128 * GSTR * 4;       // 18432 B per tile
constexpr int GBUFB = 2 * GTILEF;
constexpr int GEMM_SMEM = 2 * GBUFB;         // 73728 B

__global__ __launch_bounds__(256, 1) void gemm_tf32(
    const float* __restrict__ A, const float* __restrict__ W,
    const float* __restrict__ bias, float* __restrict__ C,
    __half* __restrict__ Of, int mode, float scale, int K)
{
    extern __shared__ char smem[];
    const uint32_t smem_u = smem_to_u32(smem);
    const int tid  = threadIdx.x;
    const int wid  = tid >> 5;
    const int lane = tid & 31;
    const int warp_m = wid >> 2;
    const int warp_n = wid & 3;
    const int m0 = blockIdx.y * 128;
    const int n0 = blockIdx.x * 128;

    float c[4][4][4];
    #pragma unroll
    for (int i = 0; i < 4; i++)
        #pragma unroll
        for (int j = 0; j < 4; j++)
            #pragma unroll
            for (int r = 0; r < 4; r++) c[i][j][r] = 0.0f;

    const int NS = K / 32;

    float4 pre[8];
    auto load_stage = [&](int s) {
        const int k0 = s * 32;
        #pragma unroll
        for (int t = 0; t < 8; t++) {
            const int idx = t * 256 + tid;
            const int tile = idx >> 10;
            const int within = idx & 1023;
            const int row = within >> 3;
            const int ch = within & 7;
            const float* src = tile ? (W + (size_t)(n0 + row) * K)
                                    : (A + (size_t)(m0 + row) * K);
            pre[t] = *(const float4*)(src + k0 + ch * 4);
        }
    };
    auto store_stage = [&](int buf) {
        char* base = smem + buf * GBUFB;
        #pragma unroll
        for (int t = 0; t < 8; t++) {
            const int idx = t * 256 + tid;
            const int tile = idx >> 10;
            const int within = idx & 1023;
            const int row = within >> 3;
            const int ch = within & 7;
            *(uint4*)(base + tile * GTILEF + row * (GSTR * 4) + ch * 16) =
                tf32x4(pre[t]);
        }
    };

    load_stage(0);
    store_stage(0);
    __syncthreads();

    const uint32_t a_rowoff = (uint32_t)(lane & 15) * (GSTR * 4);
    const uint32_t a_koff   = (uint32_t)(lane >> 4) * 16;
    const uint32_t b_rowoff = (uint32_t)(lane & 7) * (GSTR * 4);
    const uint32_t b_koff   = (uint32_t)((lane >> 3) & 1) * 16;

    for (int s = 0; s < NS; s++) {
        if (s + 1 < NS) load_stage(s + 1);

        const uint32_t base = smem_u + (s & 1) * GBUFB;
        const uint32_t sA = base;
        const uint32_t sW = base + GTILEF;

        #pragma unroll
        for (int ks = 0; ks < 4; ks++) {
            const uint32_t kb = ks * 32;
            uint32_t a[4][4], b[4][2];
            #pragma unroll
            for (int i = 0; i < 4; i++)
                ldsm_x4(a[i], sA + (warp_m * 64 + i * 16) * (GSTR * 4) +
                              a_rowoff + kb + a_koff);
            #pragma unroll
            for (int j = 0; j < 4; j++)
                ldsm_x2(b[j], sW + (warp_n * 32 + j * 8) * (GSTR * 4) +
                              b_rowoff + kb + b_koff);
            #pragma unroll
            for (int i = 0; i < 4; i++)
                #pragma unroll
                for (int j = 0; j < 4; j++)
                    mma_tf32(c[i][j], a[i], b[j]);
        }

        if (s + 1 < NS) store_stage((s + 1) & 1);
        __syncthreads();
    }

    const int trow = lane >> 2;
    const int tcol = (lane & 3) * 2;
    #pragma unroll
    for (int i = 0; i < 4; i++) {
        const int r0 = m0 + warp_m * 64 + i * 16 + trow;
        #pragma unroll
        for (int j = 0; j < 4; j++) {
            const int cc = n0 + warp_n * 32 + j * 8 + tcol;
            const float b0 = bias[cc];
            const float b1 = bias[cc + 1];
            const float v00 = (c[i][j][0] + b0) * scale;
            const float v01 = (c[i][j][1] + b1) * scale;
            const float v10 = (c[i][j][2] + b0) * scale;
            const float v11 = (c[i][j][3] + b1) * scale;
            const size_t p0 = (size_t)r0 * 1024 + cc;
            const size_t p1 = (size_t)(r0 + 8) * 1024 + cc;
            if (mode == 0) {
                *(float2*)&C[p0] = make_float2(v00, v01);
                *(float2*)&C[p1] = make_float2(v10, v11);
            } else if (mode == 3) {
                // fp32 pre-rounded to tf32 (consumed raw by attention)
                uint2 o0 = make_uint2(to_tf32(v00), to_tf32(v01));
                uint2 o1 = make_uint2(to_tf32(v10), to_tf32(v11));
                *(uint2*)&C[p0] = o0;
                *(uint2*)&C[p1] = o1;
            } else {
                *(__half2*)&Of[p0] = __floats2half2_rn(v00, v01);
                *(__half2*)&Of[p1] = __floats2half2_rn(v10, v11);
            }
        }
    }
}

// ---------------------------------------------------------------------------
// TF32 FlashAttention: BQ=128, BK=64, 8 warps (16 q-rows each).
// Q staged once (pre-rounded tf32 bits). K/V double-buffered via cp.async.
// S = Q·K^T tf32, P·V fp16, P in registers.
// ---------------------------------------------------------------------------
constexpr int QKSTRB = 272;               // bytes per Q/K smem row
constexpr int VSTRB  = 144;               // bytes per V smem row
constexpr int QTILE  = 128 * QKSTRB;      // 34816 B
constexpr int KTILE  = 64 * QKSTRB;       // 17408 B
constexpr int VTILE  = 64 * VSTRB;        // 9216 B
constexpr int KVBUF  = KTILE + VTILE;     // 26624 B
constexpr int SQ  = 0;
constexpr int SKV = QTILE;
constexpr int ATTN_SMEM = QTILE + 2 * KVBUF;   // 88064 B

__global__ __launch_bounds__(256) void attn_tf32(
    const float* __restrict__ qf, const float* __restrict__ kf,
    const __half* __restrict__ vv, const float* __restrict__ maskf,
    const float* __restrict__ bias, float* __restrict__ ctxo)
{
    extern __shared__ char smem[];
    const uint32_t su = smem_to_u32(smem);
    const int tid = threadIdx.x;
    const int wid = tid >> 5;
    const int lane = tid & 31;
    const int g = lane >> 2;
    const int tig = lane & 3;
    const int q0 = blockIdx.x * 128;
    const int h = blockIdx.y;
    const int b = blockIdx.z;

    // Issue K/V stage 0 via cp.async: 1536 16B chunks, 6 per thread
    auto issue_kv = [&](int kt, int buf) {
        const int k0 = kt * 64;
        const uint32_t kbase = su + SKV + buf * KVBUF;
        #pragma unroll
        for (int t = 0; t < 6; t++) {
            const int idx = t * 256 + tid;
            if (idx < 1024) {
                const int row = idx >> 4;
                const int ch = idx & 15;
                cp_async16(kbase + row * QKSTRB + ch * 16,
                           kf + ((size_t)(b * S_ + k0 + row)) * H_ +
                           h * HD_ + ch * 4);
            } else {
                const int w2 = idx - 1024;
                const int row = w2 >> 3;
                const int ch = w2 & 7;
                cp_async16(kbase + KTILE + row * VSTRB + ch * 16,
                           vv + ((size_t)(b * S_ + k0 + row)) * H_ +
                           h * HD_ + ch * 8);
            }
        }
    };

    issue_kv(0, 0);
    CP_COMMIT();

    // Stage Q (pre-rounded tf32 bits, raw copy): 2048 chunks, 8/thread
    #pragma unroll
    for (int t = 0; t < 8; t++) {
        const int idx = t * 256 + tid;
        const int row = idx >> 4;
        const int ch = idx & 15;
        *(uint4*)(smem + SQ + row * QKSTRB + ch * 16) =
            *(const uint4*)
            &qf[((size_t)(b * S_ + q0 + row)) * H_ + h * HD_ + ch * 4];
    }

    float ctx[8][4];
    #pragma unroll
    for (int j = 0; j < 8; j++)
        #pragma unroll
        for (int r = 0; r < 4; r++) ctx[j][r] = 0.0f;
    float m0_ = -1e30f, m1_ = -1e30f, l0_ = 0.0f, l1_ = 0.0f;

    const uint32_t a_rowoff = (uint32_t)(wid * 16 + (lane & 15)) * QKSTRB;
    const uint32_t a_koff   = (uint32_t)(lane >> 4) * 16;
    const uint32_t b_rowoff = (uint32_t)(lane & 7) * QKSTRB;
    const uint32_t b_koff   = (uint32_t)((lane >> 3) & 1) * 16;
    const uint32_t v_rowoff = (uint32_t)(lane & 15) * VSTRB;

    const int qg0 = q0 + wid * 16 + g;
    const size_t bias_row0 = ((size_t)h * S_ + qg0) * S_ + 2 * tig;
    const size_t bias_row1 = bias_row0 + 8 * S_;

    constexpr int NT = S_ / 64;   // 32
    for (int kt = 0; kt < NT; kt++) {
        const int k0 = kt * 64;
        __syncthreads();                    // all warps done with buf (kt+1)&1
        if (kt + 1 < NT) issue_kv(kt + 1, (kt + 1) & 1);
        CP_COMMIT();
        CP_WAIT1();                          // stage kt complete
        __syncthreads();                     // visible to all warps

        const uint32_t sk = su + SKV + (kt & 1) * KVBUF;
        const uint32_t sv = sk + KTILE;

        // ---- S = Q·K^T (tf32) ----
        float c[8][4];
        #pragma unroll
        for (int j = 0; j < 8; j++)
            #pragma unroll
            for (int r = 0; r < 4; r++) c[j][r] = 0.0f;

        #pragma unroll
        for (int ks = 0; ks < 8; ks++) {
            const uint32_t kb = ks * 32;
            uint32_t aq[4];
            ldsm_x4(aq, su + SQ + a_rowoff + kb + a_koff);
            #pragma unroll
            for (int j = 0; j < 8; j++) {
                uint32_t bk[2];
                ldsm_x2(bk, sk + (uint32_t)(j * 8) * QKSTRB +
                            b_rowoff + kb + b_koff);
                mma_tf32(c[j], aq, bk);
            }
        }

        // ---- bias + mask ----
        #pragma unroll
        for (int j = 0; j < 8; j++) {
            const float2 mk = *(const float2*)&maskf[b * S_ + k0 + j * 8 + 2 * tig];
            const float2 b0 = *(const float2*)&bias[bias_row0 + k0 + j * 8];
            const float2 b1 = *(const float2*)&bias[bias_row1 + k0 + j * 8];
            c[j][0] += b0.x + mk.x;
            c[j][1] += b0.y + mk.y;
            c[j][2] += b1.x + mk.x;
            c[j][3] += b1.y + mk.y;
        }

        // ---- online softmax ----
        float mx0 = -1e30f, mx1 = -1e30f;
        #pragma unroll
        for (int j = 0; j < 8; j++) {
            mx0 = fmaxf(mx0, fmaxf(c[j][0], c[j][1]));
            mx1 = fmaxf(mx1, fmaxf(c[j][2], c[j][3]));
        }
        mx0 = fmaxf(mx0, __shfl_xor_sync(0xffffffffu, mx0, 1));
        mx0 = fmaxf(mx0, __shfl_xor_sync(0xffffffffu, mx0, 2));
        mx1 = fmaxf(mx1, __shfl_xor_sync(0xffffffffu, mx1, 1));
        mx1 = fmaxf(mx1, __shfl_xor_sync(0xffffffffu, mx1, 2));

        const float mo0 = m0_, mo1 = m1_;
        m0_ = fmaxf(m0_, mx0);
        m1_ = fmaxf(m1_, mx1);
        const float alpha0 = __expf(mo0 - m0_);
        const float alpha1 = __expf(mo1 - m1_);

        float sum0 = 0.0f, sum1 = 0.0f;
        uint32_t ap[4][4];
        #pragma unroll
        for (int j = 0; j < 8; j++) {
            c[j][0] = __expf(c[j][0] - m0_);
            c[j][1] = __expf(c[j][1] - m0_);
            c[j][2] = __expf(c[j][2] - m1_);
            c[j][3] = __expf(c[j][3] - m1_);
            sum0 += c[j][0] + c[j][1];
            sum1 += c[j][2] + c[j][3];
        }
        l0_ = l0_ * alpha0 + sum0;
        l1_ = l1_ * alpha1 + sum1;

        #pragma unroll
        for (int t = 0; t < 4; t++) {
            __half2 h0 = __floats2half2_rn(c[2 * t][0], c[2 * t][1]);
            __half2 h1 = __floats2half2_rn(c[2 * t][2], c[2 * t][3]);
            __half2 h2 = __floats2half2_rn(c[2 * t + 1][0], c[2 * t + 1][1]);
            __half2 h3 = __floats2half2_rn(c[2 * t + 1][2], c[2 * t + 1][3]);
            ap[t][0] = *(uint32_t*)&h0;
            ap[t][1] = *(uint32_t*)&h1;
            ap[t][2] = *(uint32_t*)&h2;
            ap[t][3] = *(uint32_t*)&h3;
        }

        #pragma unroll
        for (int j = 0; j < 8; j++) {
            ctx[j][0] *= alpha0;
            ctx[j][1] *= alpha0;
            ctx[j][2] *= alpha1;
            ctx[j][3] *= alpha1;
        }

        // ---- ctx += P·V (fp16) ----
        #pragma unroll
        for (int t = 0; t < 4; t++) {
            const uint32_t vbase = sv + (uint32_t)(t * 16) * VSTRB + v_rowoff;
            #pragma unroll
            for (int jd = 0; jd < 8; jd++) {
                uint32_t bv[2];
                ldsm_x2_trans(bv, vbase + jd * 16);
                mma_f16(ctx[jd], ap[t], bv);
            }
        }
    }

    l0_ += __shfl_xor_sync(0xffffffffu, l0_, 1);
    l0_ += __shfl_xor_sync(0xffffffffu, l0_, 2);
    l1_ += __shfl_xor_sync(0xffffffffu, l1_, 1);
    l1_ += __shfl_xor_sync(0xffffffffu, l1_, 2);
    const float inv0 = 1.0f / fmaxf(l0_, 1e-6f);
    const float inv1 = 1.0f / fmaxf(l1_, 1e-6f);

    const size_t orow0 = ((size_t)(b * S_ + qg0)) * H_ + h * HD_ + 2 * tig;
    const size_t orow1 = orow0 + 8 * H_;
    #pragma unroll
    for (int jd = 0; jd < 8; jd++) {
        *(float2*)&ctxo[orow0 + jd * 8] =
            make_float2(ctx[jd][0] * inv0, ctx[jd][1] * inv0);
        *(float2*)&ctxo[orow1 + jd * 8] =
            make_float2(ctx[jd][2] * inv1, ctx[jd][3] * inv1);
    }
}

// ---------------------------------------------------------------------------
// Launch
// ---------------------------------------------------------------------------
extern "C" void kernel_launch(void* const* d_in, const int* in_sizes, int n_in,
                              void* d_out, int out_size)
{
    (void)in_sizes; (void)n_in; (void)out_size;

    const float* query = (const float*)d_in[0];
    const float* key_t = (const float*)d_in[1];
    const float* value = (const float*)d_in[2];
    const unsigned int* kpm_raw = (const unsigned int*)d_in[3];
    const float* bias  = (const float*)d_in[4];
    const float* q_w = (const float*)d_in[5];
    const float* q_b = (const float*)d_in[6];
    const float* k_w = (const float*)d_in[7];
    const float* k_b = (const float*)d_in[8];
    const float* v_w = (const float*)d_in[9];
    const float* v_b = (const float*)d_in[10];
    const float* o_w = (const float*)d_in[11];
    const float* o_b = (const float*)d_in[12];
    float* out = (float*)d_out;

    float *gqf, *gkf, *gctx, *gmaskf;
    __half* gvh;
    cudaGetSymbolAddress((void**)&gqf, g_qf);
    cudaGetSymbolAddress((void**)&gkf, g_kf);
    cudaGetSymbolAddress((void**)&gvh, g_vh);
    cudaGetSymbolAddress((void**)&gctx, g_ctx);
    cudaGetSymbolAddress((void**)&gmaskf, g_maskf);

    cudaFuncSetAttribute(gemm_tf32,
                         cudaFuncAttributeMaxDynamicSharedMemorySize, GEMM_SMEM);
    cudaFuncSetAttribute(attn_tf32,
                         cudaFuncAttributeMaxDynamicSharedMemorySize, ATTN_SMEM);

    mask_normalize<<<1, 1024>>>(kpm_raw);

    const dim3 gemm_grid(H_ / 128, M_ / 128);   // (8, 32)

    // Q projection -> fp32 pre-rounded tf32 (scaled by 1/sqrt(HD))
    gemm_tf32<<<gemm_grid, 256, GEMM_SMEM>>>(query, q_w, q_b, gqf, nullptr,
                                             3, 0.125f, H_);
    // K projection -> fp32 pre-rounded tf32
    gemm_tf32<<<gemm_grid, 256, GEMM_SMEM>>>(key_t, k_w, k_b, gkf, nullptr,
                                             3, 1.0f, H_);
    // V projection -> fp16
    gemm_tf32<<<gemm_grid, 256, GEMM_SMEM>>>(value, v_w, v_b, nullptr, gvh,
                                             2, 1.0f, H_);

    attn_tf32<<<dim3(S_ / 128, NH_, B_), 256, ATTN_SMEM>>>(
        gqf, gkf, gvh, gmaskf, bias, gctx);

    // Output projection
    gemm_tf32<<<gemm_grid, 256, GEMM_SMEM>>>(gctx, o_w, o_b, out, nullptr,
                                             0, 1.0f, H_);
}

// round 10
// speedup vs baseline: 3.9649x; 1.0753x over previous
#include <cuda_runtime.h>
#include <cuda_bf16.h>
#include <cuda_fp16.h>
#include <cstdint>
#include <cstddef>

// Problem constants
constexpr int B_  = 2;
constexpr int S_  = 2048;
constexpr int H_  = 1024;
constexpr int NH_ = 16;
constexpr int HD_ = 64;
constexpr int M_  = B_ * S_;   // 4096

// Scratch (allocation-free: __device__ globals)
__device__ float g_maskf[B_ * S_];
__device__ float g_qf[(size_t)M_ * H_];
__device__ float g_kf[(size_t)M_ * H_];
__device__ __half g_vh[(size_t)M_ * H_];
__device__ float g_ctx[(size_t)M_ * H_];
// tf32-pre-rounded operands
__device__ float g_rq[(size_t)M_ * H_];
__device__ float g_rk[(size_t)M_ * H_];
__device__ float g_rv[(size_t)M_ * H_];
__device__ float g_rwq[(size_t)H_ * H_];
__device__ float g_rwk[(size_t)H_ * H_];
__device__ float g_rwv[(size_t)H_ * H_];
__device__ float g_rwo[(size_t)H_ * H_];

// ---------------------------------------------------------------------------
// Warp-MMA helpers (portable ISA, plain sm_103 target)
// ---------------------------------------------------------------------------
__device__ __forceinline__ uint32_t smem_to_u32(const void* p) {
    uint32_t a;
    asm("{ .reg .u64 t; cvta.to.shared.u64 t, %1; cvt.u32.u64 %0, t; }"
        : "=r"(a) : "l"(p));
    return a;
}
__device__ __forceinline__ void ldsm_x4(uint32_t r[4], uint32_t a) {
    asm volatile("ldmatrix.sync.aligned.m8n8.x4.shared.b16 {%0,%1,%2,%3}, [%4];"
                 : "=r"(r[0]), "=r"(r[1]), "=r"(r[2]), "=r"(r[3]) : "r"(a));
}
__device__ __forceinline__ void ldsm_x2(uint32_t r[2], uint32_t a) {
    asm volatile("ldmatrix.sync.aligned.m8n8.x2.shared.b16 {%0,%1}, [%2];"
                 : "=r"(r[0]), "=r"(r[1]) : "r"(a));
}
__device__ __forceinline__ void ldsm_x2_trans(uint32_t r[2], uint32_t a) {
    asm volatile("ldmatrix.sync.aligned.m8n8.x2.trans.shared.b16 {%0,%1}, [%2];"
                 : "=r"(r[0]), "=r"(r[1]) : "r"(a));
}
__device__ __forceinline__ void mma_tf32(float c[4], const uint32_t a[4],
                                         const uint32_t b[2]) {
    asm volatile(
        "mma.sync.aligned.m16n8k8.row.col.f32.tf32.tf32.f32 "
        "{%0,%1,%2,%3}, {%4,%5,%6,%7}, {%8,%9}, {%0,%1,%2,%3};"
        : "+f"(c[0]), "+f"(c[1]), "+f"(c[2]), "+f"(c[3])
        : "r"(a[0]), "r"(a[1]), "r"(a[2]), "r"(a[3]), "r"(b[0]), "r"(b[1]));
}
__device__ __forceinline__ void mma_f16(float c[4], const uint32_t a[4],
                                        const uint32_t b[2]) {
    asm volatile(
        "mma.sync.aligned.m16n8k16.row.col.f32.f16.f16.f32 "
        "{%0,%1,%2,%3}, {%4,%5,%6,%7}, {%8,%9}, {%0,%1,%2,%3};"
        : "+f"(c[0]), "+f"(c[1]), "+f"(c[2]), "+f"(c[3])
        : "r"(a[0]), "r"(a[1]), "r"(a[2]), "r"(a[3]), "r"(b[0]), "r"(b[1]));
}
__device__ __forceinline__ uint32_t to_tf32(float f) {
    uint32_t r;
    asm("cvt.rna.tf32.f32 %0, %1;" : "=r"(r) : "f"(f));
    return r;
}
__device__ __forceinline__ void cp_async16(uint32_t saddr, const void* gptr) {
    asm volatile("cp.async.cg.shared.global [%0], [%1], 16;"
                 :: "r"(saddr), "l"(gptr));
}
#define CP_COMMIT() asm volatile("cp.async.commit_group;" ::: "memory")
#define CP_WAIT1()  asm volatile("cp.async.wait_group 1;" ::: "memory")
#define CP_WAIT0()  asm volatile("cp.async.wait_group 0;" ::: "memory")

// ---------------------------------------------------------------------------
// Mask normalization -> float (-1e30 / 0) form
// ---------------------------------------------------------------------------
__global__ void mask_normalize(const unsigned int* __restrict__ w)
{
    __shared__ unsigned int flags;
    const int tid = threadIdx.x;
    if (tid == 0) flags = 0u;
    __syncthreads();
    const unsigned int x = w[tid];
    unsigned int f = 0u;
    if (x != 0u && x != 1u && x != 0x3F800000u) f |= 1u;
    if (x == 0x3F800000u) f |= 2u;
    if (f) atomicOr(&flags, f);
    __syncthreads();
    const int byte_mode = (flags & 1u) ? 1 : 0;
    if (byte_mode) {
        const unsigned char* b8 = (const unsigned char*)w;
        for (int i = tid; i < B_ * S_; i += 1024)
            g_maskf[i] = (b8[i] != 0) ? -1e30f : 0.0f;
    } else {
        for (int i = tid; i < B_ * S_; i += 1024)
            g_maskf[i] = (w[i] != 0u) ? -1e30f : 0.0f;
    }
}

// ---------------------------------------------------------------------------
// Pre-round all GEMM operands to tf32 bits (single launch).
// Segments (1024 elems per block): 3 x 4096 blocks (q,k,v) + 4 x 1024 (weights)
// ---------------------------------------------------------------------------
__global__ __launch_bounds__(256) void round_all(
    const float* __restrict__ q, const float* __restrict__ k,
    const float* __restrict__ v, const float* __restrict__ wq,
    const float* __restrict__ wk, const float* __restrict__ wv,
    const float* __restrict__ wo)
{
    const int blk = blockIdx.x;
    const float* src;
    float* dst;
    int base;
    if (blk < 4096)        { src = q;  dst = g_rq;  base = blk; }
    else if (blk < 8192)   { src = k;  dst = g_rk;  base = blk - 4096; }
    else if (blk < 12288)  { src = v;  dst = g_rv;  base = blk - 8192; }
    else if (blk < 13312)  { src = wq; dst = g_rwq; base = blk - 12288; }
    else if (blk < 14336)  { src = wk; dst = g_rwk; base = blk - 13312; }
    else if (blk < 15360)  { src = wv; dst = g_rwv; base = blk - 14336; }
    else                   { src = wo; dst = g_rwo; base = blk - 15360; }

    const int i = (base * 256 + threadIdx.x) * 4;
    const float4 x = *(const float4*)&src[i];
    uint4 o;
    o.x = to_tf32(x.x); o.y = to_tf32(x.y);
    o.z = to_tf32(x.z); o.w = to_tf32(x.w);
    *(uint4*)&dst[i] = o;
}

// ---------------------------------------------------------------------------
// TF32 HMMA GEMM (NT): C[M,N] = A[M,K] @ W[N,K]^T + bias
// Operands pre-rounded tf32 bits in gmem -> cp.async raw staging (no cvt).
// 128x128 CTA tile, BK=32, 8 warps (2x4), double-buffered, 2 CTAs/SM target.
// Modes: 0 = fp32*scale; 2 = fp16; 3 = fp32*scale rounded to tf32.
// ---------------------------------------------------------------------------
constexpr int GSTR = 36;                     // floats per smem row (144 B)
constexpr int GTILEF = 128 * GSTR * 4;       // 18432 B per tile
constexpr int GBUFB = 2 * GTILEF;
constexpr int GEMM_SMEM = 2 * GBUFB;         // 73728 B

__global__ __launch_bounds__(256, 2) void gemm_tf32(
    const float* __restrict__ A, const float* __restrict__ W,
    const float* __restrict__ bias, float* __restrict__ C,
    __half* __restrict__ Of, int mode, float scale, int K)
{
    extern __shared__ char smem[];
    const uint32_t smem_u = smem_to_u32(smem);
    const int tid  = threadIdx.x;
    const int wid  = tid >> 5;
    const int lane = tid & 31;
    const int warp_m = wid >> 2;
    const int warp_n = wid & 3;
    const int m0 = blockIdx.y * 128;
    const int n0 = blockIdx.x * 128;

    float c[4][4][4];
    #pragma unroll
    for (int i = 0; i < 4; i++)
        #pragma unroll
        for (int j = 0; j < 4; j++)
            #pragma unroll
            for (int r = 0; r < 4; r++) c[i][j][r] = 0.0f;

    const int NS = K / 32;

    // cp.async staging: 2048 16B chunks per stage, 8 per thread
    auto issue_stage = [&](int s, int buf) {
        const int k0 = s * 32;
        const uint32_t base = smem_u + buf * GBUFB;
        #pragma unroll
        for (int t = 0; t < 8; t++) {
            const int idx = t * 256 + tid;
            const int tile = idx >> 10;            // 0=A, 1=W
            const int within = idx & 1023;
            const int row = within >> 3;
            const int ch = within & 7;
            const float* src = tile ? (W + (size_t)(n0 + row) * K)
                                    : (A + (size_t)(m0 + row) * K);
            cp_async16(base + tile * GTILEF + row * (GSTR * 4) + ch * 16,
                       src + k0 + ch * 4);
        }
    };

    issue_stage(0, 0);
    CP_COMMIT();

    const uint32_t a_rowoff = (uint32_t)(lane & 15) * (GSTR * 4);
    const uint32_t a_koff   = (uint32_t)(lane >> 4) * 16;
    const uint32_t b_rowoff = (uint32_t)(lane & 7) * (GSTR * 4);
    const uint32_t b_koff   = (uint32_t)((lane >> 3) & 1) * 16;

    for (int s = 0; s < NS; s++) {
        if (s + 1 < NS) {
            issue_stage(s + 1, (s + 1) & 1);
            CP_COMMIT();
            CP_WAIT1();
        } else {
            CP_WAIT0();
        }
        __syncthreads();

        const uint32_t base = smem_u + (s & 1) * GBUFB;
        const uint32_t sA = base;
        const uint32_t sW = base + GTILEF;

        #pragma unroll
        for (int ks = 0; ks < 4; ks++) {
            const uint32_t kb = ks * 32;
            uint32_t a[4][4], b[4][2];
            #pragma unroll
            for (int i = 0; i < 4; i++)
                ldsm_x4(a[i], sA + (warp_m * 64 + i * 16) * (GSTR * 4) +
                              a_rowoff + kb + a_koff);
            #pragma unroll
            for (int j = 0; j < 4; j++)
                ldsm_x2(b[j], sW + (warp_n * 32 + j * 8) * (GSTR * 4) +
                              b_rowoff + kb + b_koff);
            #pragma unroll
            for (int i = 0; i < 4; i++)
                #pragma unroll
                for (int j = 0; j < 4; j++)
                    mma_tf32(c[i][j], a[i], b[j]);
        }
        __syncthreads();   // all warps done with buf s&1 before overwrite
    }

    const int trow = lane >> 2;
    const int tcol = (lane & 3) * 2;
    #pragma unroll
    for (int i = 0; i < 4; i++) {
        const int r0 = m0 + warp_m * 64 + i * 16 + trow;
        #pragma unroll
        for (int j = 0; j < 4; j++) {
            const int cc = n0 + warp_n * 32 + j * 8 + tcol;
            const float b0 = bias[cc];
            const float b1 = bias[cc + 1];
            const float v00 = (c[i][j][0] + b0) * scale;
            const float v01 = (c[i][j][1] + b1) * scale;
            const float v10 = (c[i][j][2] + b0) * scale;
            const float v11 = (c[i][j][3] + b1) * scale;
            const size_t p0 = (size_t)r0 * 1024 + cc;
            const size_t p1 = (size_t)(r0 + 8) * 1024 + cc;
            if (mode == 0) {
                *(float2*)&C[p0] = make_float2(v00, v01);
                *(float2*)&C[p1] = make_float2(v10, v11);
            } else if (mode == 3) {
                uint2 o0 = make_uint2(to_tf32(v00), to_tf32(v01));
                uint2 o1 = make_uint2(to_tf32(v10), to_tf32(v11));
                *(uint2*)&C[p0] = o0;
                *(uint2*)&C[p1] = o1;
            } else {
                *(__half2*)&Of[p0] = __floats2half2_rn(v00, v01);
                *(__half2*)&Of[p1] = __floats2half2_rn(v10, v11);
            }
        }
    }
}

// ---------------------------------------------------------------------------
// TF32 FlashAttention: BQ=128, BK=64, 8 warps (16 q-rows each).
// Q staged once (pre-rounded tf32 bits). K/V double-buffered via cp.async.
// ctx written pre-rounded to tf32 for the o-projection.
// ---------------------------------------------------------------------------
constexpr int QKSTRB = 272;               // bytes per Q/K smem row
constexpr int VSTRB  = 144;               // bytes per V smem row
constexpr int QTILE  = 128 * QKSTRB;      // 34816 B
constexpr int KTILE  = 64 * QKSTRB;       // 17408 B
constexpr int VTILE  = 64 * VSTRB;        // 9216 B
constexpr int KVBUF  = KTILE + VTILE;     // 26624 B
constexpr int SQ  = 0;
constexpr int SKV = QTILE;
constexpr int ATTN_SMEM = QTILE + 2 * KVBUF;   // 88064 B

__global__ __launch_bounds__(256, 2) void attn_tf32(
    const float* __restrict__ qf, const float* __restrict__ kf,
    const __half* __restrict__ vv, const float* __restrict__ maskf,
    const float* __restrict__ bias, float* __restrict__ ctxo)
{
    extern __shared__ char smem[];
    const uint32_t su = smem_to_u32(smem);
    const int tid = threadIdx.x;
    const int wid = tid >> 5;
    const int lane = tid & 31;
    const int g = lane >> 2;
    const int tig = lane & 3;
    const int q0 = blockIdx.x * 128;
    const int h = blockIdx.y;
    const int b = blockIdx.z;

    auto issue_kv = [&](int kt, int buf) {
        const int k0 = kt * 64;
        const uint32_t kbase = su + SKV + buf * KVBUF;
        #pragma unroll
        for (int t = 0; t < 6; t++) {
            const int idx = t * 256 + tid;
            if (idx < 1024) {
                const int row = idx >> 4;
                const int ch = idx & 15;
                cp_async16(kbase + row * QKSTRB + ch * 16,
                           kf + ((size_t)(b * S_ + k0 + row)) * H_ +
                           h * HD_ + ch * 4);
            } else {
                const int w2 = idx - 1024;
                const int row = w2 >> 3;
                const int ch = w2 & 7;
                cp_async16(kbase + KTILE + row * VSTRB + ch * 16,
                           vv + ((size_t)(b * S_ + k0 + row)) * H_ +
                           h * HD_ + ch * 8);
            }
        }
    };

    issue_kv(0, 0);
    CP_COMMIT();

    // Stage Q (pre-rounded tf32 bits, raw copy): 2048 chunks, 8/thread
    #pragma unroll
    for (int t = 0; t < 8; t++) {
        const int idx = t * 256 + tid;
        const int row = idx >> 4;
        const int ch = idx & 15;
        *(uint4*)(smem + SQ + row * QKSTRB + ch * 16) =
            *(const uint4*)
            &qf[((size_t)(b * S_ + q0 + row)) * H_ + h * HD_ + ch * 4];
    }

    float ctx[8][4];
    #pragma unroll
    for (int j = 0; j < 8; j++)
        #pragma unroll
        for (int r = 0; r < 4; r++) ctx[j][r] = 0.0f;
    float m0_ = -1e30f, m1_ = -1e30f, l0_ = 0.0f, l1_ = 0.0f;

    const uint32_t a_rowoff = (uint32_t)(wid * 16 + (lane & 15)) * QKSTRB;
    const uint32_t a_koff   = (uint32_t)(lane >> 4) * 16;
    const uint32_t b_rowoff = (uint32_t)(lane & 7) * QKSTRB;
    const uint32_t b_koff   = (uint32_t)((lane >> 3) & 1) * 16;
    const uint32_t v_rowoff = (uint32_t)(lane & 15) * VSTRB;

    const int qg0 = q0 + wid * 16 + g;
    const size_t bias_row0 = ((size_t)h * S_ + qg0) * S_ + 2 * tig;
    const size_t bias_row1 = bias_row0 + 8 * S_;

    constexpr int NT = S_ / 64;   // 32
    for (int kt = 0; kt < NT; kt++) {
        const int k0 = kt * 64;
        __syncthreads();
        if (kt + 1 < NT) issue_kv(kt + 1, (kt + 1) & 1);
        CP_COMMIT();
        CP_WAIT1();
        __syncthreads();

        const uint32_t sk = su + SKV + (kt & 1) * KVBUF;
        const uint32_t sv = sk + KTILE;

        float c[8][4];
        #pragma unroll
        for (int j = 0; j < 8; j++)
            #pragma unroll
            for (int r = 0; r < 4; r++) c[j][r] = 0.0f;

        #pragma unroll
        for (int ks = 0; ks < 8; ks++) {
            const uint32_t kb = ks * 32;
            uint32_t aq[4];
            ldsm_x4(aq, su + SQ + a_rowoff + kb + a_koff);
            #pragma unroll
            for (int j = 0; j < 8; j++) {
                uint32_t bk[2];
                ldsm_x2(bk, sk + (uint32_t)(j * 8) * QKSTRB +
                            b_rowoff + kb + b_koff);
                mma_tf32(c[j], aq, bk);
            }
        }

        #pragma unroll
        for (int j = 0; j < 8; j++) {
            const float2 mk = *(const float2*)&maskf[b * S_ + k0 + j * 8 + 2 * tig];
            const float2 b0 = *(const float2*)&bias[bias_row0 + k0 + j * 8];
            const float2 b1 = *(const float2*)&bias[bias_row1 + k0 + j * 8];
            c[j][0] += b0.x + mk.x;
            c[j][1] += b0.y + mk.y;
            c[j][2] += b1.x + mk.x;
            c[j][3] += b1.y + mk.y;
        }

        float mx0 = -1e30f, mx1 = -1e30f;
        #pragma unroll
        for (int j = 0; j < 8; j++) {
            mx0 = fmaxf(mx0, fmaxf(c[j][0], c[j][1]));
            mx1 = fmaxf(mx1, fmaxf(c[j][2], c[j][3]));
        }
        mx0 = fmaxf(mx0, __shfl_xor_sync(0xffffffffu, mx0, 1));
        mx0 = fmaxf(mx0, __shfl_xor_sync(0xffffffffu, mx0, 2));
        mx1 = fmaxf(mx1, __shfl_xor_sync(0xffffffffu, mx1, 1));
        mx1 = fmaxf(mx1, __shfl_xor_sync(0xffffffffu, mx1, 2));

        const float mo0 = m0_, mo1 = m1_;
        m0_ = fmaxf(m0_, mx0);
        m1_ = fmaxf(m1_, mx1);
        const float alpha0 = __expf(mo0 - m0_);
        const float alpha1 = __expf(mo1 - m1_);

        float sum0 = 0.0f, sum1 = 0.0f;
        uint32_t ap[4][4];
        #pragma unroll
        for (int j = 0; j < 8; j++) {
            c[j][0] = __expf(c[j][0] - m0_);
            c[j][1] = __expf(c[j][1] - m0_);
            c[j][2] = __expf(c[j][2] - m1_);
            c[j][3] = __expf(c[j][3] - m1_);
            sum0 += c[j][0] + c[j][1];
            sum1 += c[j][2] + c[j][3];
        }
        l0_ = l0_ * alpha0 + sum0;
        l1_ = l1_ * alpha1 + sum1;

        #pragma unroll
        for (int t = 0; t < 4; t++) {
            __half2 h0 = __floats2half2_rn(c[2 * t][0], c[2 * t][1]);
            __half2 h1 = __floats2half2_rn(c[2 * t][2], c[2 * t][3]);
            __half2 h2 = __floats2half2_rn(c[2 * t + 1][0], c[2 * t + 1][1]);
            __half2 h3 = __floats2half2_rn(c[2 * t + 1][2], c[2 * t + 1][3]);
            ap[t][0] = *(uint32_t*)&h0;
            ap[t][1] = *(uint32_t*)&h1;
            ap[t][2] = *(uint32_t*)&h2;
            ap[t][3] = *(uint32_t*)&h3;
        }

        #pragma unroll
        for (int j = 0; j < 8; j++) {
            ctx[j][0] *= alpha0;
            ctx[j][1] *= alpha0;
            ctx[j][2] *= alpha1;
            ctx[j][3] *= alpha1;
        }

        #pragma unroll
        for (int t = 0; t < 4; t++) {
            const uint32_t vbase = sv + (uint32_t)(t * 16) * VSTRB + v_rowoff;
            #pragma unroll
            for (int jd = 0; jd < 8; jd++) {
                uint32_t bv[2];
                ldsm_x2_trans(bv, vbase + jd * 16);
                mma_f16(ctx[jd], ap[t], bv);
            }
        }
    }

    l0_ += __shfl_xor_sync(0xffffffffu, l0_, 1);
    l0_ += __shfl_xor_sync(0xffffffffu, l0_, 2);
    l1_ += __shfl_xor_sync(0xffffffffu, l1_, 1);
    l1_ += __shfl_xor_sync(0xffffffffu, l1_, 2);
    const float inv0 = 1.0f / fmaxf(l0_, 1e-6f);
    const float inv1 = 1.0f / fmaxf(l1_, 1e-6f);

    // ctx written pre-rounded to tf32 (consumed raw by o-projection)
    const size_t orow0 = ((size_t)(b * S_ + qg0)) * H_ + h * HD_ + 2 * tig;
    const size_t orow1 = orow0 + 8 * H_;
    #pragma unroll
    for (int jd = 0; jd < 8; jd++) {
        uint2 o0 = make_uint2(to_tf32(ctx[jd][0] * inv0),
                              to_tf32(ctx[jd][1] * inv0));
        uint2 o1 = make_uint2(to_tf32(ctx[jd][2] * inv1),
                              to_tf32(ctx[jd][3] * inv1));
        *(uint2*)&ctxo[orow0 + jd * 8] = o0;
        *(uint2*)&ctxo[orow1 + jd * 8] = o1;
    }
}

// ---------------------------------------------------------------------------
// Launch
// ---------------------------------------------------------------------------
extern "C" void kernel_launch(void* const* d_in, const int* in_sizes, int n_in,
                              void* d_out, int out_size)
{
    (void)in_sizes; (void)n_in; (void)out_size;

    const float* query = (const float*)d_in[0];
    const float* key_t = (const float*)d_in[1];
    const float* value = (const float*)d_in[2];
    const unsigned int* kpm_raw = (const unsigned int*)d_in[3];
    const float* bias  = (const float*)d_in[4];
    const float* q_w = (const float*)d_in[5];
    const float* q_b = (const float*)d_in[6];
    const float* k_w = (const float*)d_in[7];
    const float* k_b = (const float*)d_in[8];
    const float* v_w = (const float*)d_in[9];
    const float* v_b = (const float*)d_in[10];
    const float* o_w = (const float*)d_in[11];
    const float* o_b = (const float*)d_in[12];
    float* out = (float*)d_out;

    float *gqf, *gkf, *gctx, *gmaskf;
    float *grq, *grk, *grv, *grwq, *grwk, *grwv, *grwo;
    __half* gvh;
    cudaGetSymbolAddress((void**)&gqf, g_qf);
    cudaGetSymbolAddress((void**)&gkf, g_kf);
    cudaGetSymbolAddress((void**)&gvh, g_vh);
    cudaGetSymbolAddress((void**)&gctx, g_ctx);
    cudaGetSymbolAddress((void**)&gmaskf, g_maskf);
    cudaGetSymbolAddress((void**)&grq, g_rq);
    cudaGetSymbolAddress((void**)&grk, g_rk);
    cudaGetSymbolAddress((void**)&grv, g_rv);
    cudaGetSymbolAddress((void**)&grwq, g_rwq);
    cudaGetSymbolAddress((void**)&grwk, g_rwk);
    cudaGetSymbolAddress((void**)&grwv, g_rwv);
    cudaGetSymbolAddress((void**)&grwo, g_rwo);

    cudaFuncSetAttribute(gemm_tf32,
                         cudaFuncAttributeMaxDynamicSharedMemorySize, GEMM_SMEM);
    cudaFuncSetAttribute(attn_tf32,
                         cudaFuncAttributeMaxDynamicSharedMemorySize, ATTN_SMEM);

    mask_normalize<<<1, 1024>>>(kpm_raw);
    round_all<<<16384, 256>>>(query, key_t, value, q_w, k_w, v_w, o_w);

    const dim3 gemm_grid(H_ / 128, M_ / 128);   // (8, 32)

    // Q projection -> tf32-rounded fp32 (scaled by 1/sqrt(HD))
    gemm_tf32<<<gemm_grid, 256, GEMM_SMEM>>>(grq, grwq, q_b, gqf, nullptr,
                                             3, 0.125f, H_);
    // K projection -> tf32-rounded fp32
    gemm_tf32<<<gemm_grid, 256, GEMM_SMEM>>>(grk, grwk, k_b, gkf, nullptr,
                                             3, 1.0f, H_);
    // V projection -> fp16
    gemm_tf32<<<gemm_grid, 256, GEMM_SMEM>>>(grv, grwv, v_b, nullptr, gvh,
                                             2, 1.0f, H_);

    attn_tf32<<<dim3(S_ / 128, NH_, B_), 256, ATTN_SMEM>>>(
        gqf, gkf, gvh, gmaskf, bias, gctx);

    // Output projection (ctx pre-rounded by attention epilogue)
    gemm_tf32<<<gemm_grid, 256, GEMM_SMEM>>>(gctx, grwo, o_b, out, nullptr,
                                             0, 1.0f, H_);
}

// round 11
// speedup vs baseline: 5.8061x; 1.4643x over previous
#include <cuda_runtime.h>
#include <cuda_bf16.h>
#include <cuda_fp16.h>
#include <cstdint>
#include <cstddef>

// Problem constants
constexpr int B_  = 2;
constexpr int S_  = 2048;
constexpr int H_  = 1024;
constexpr int NH_ = 16;
constexpr int HD_ = 64;
constexpr int M_  = B_ * S_;   // 4096

// Scratch (allocation-free: __device__ globals)
__device__ float g_maskf[B_ * S_];
// f16 pre-converted GEMM operands
__device__ __half g_hq[(size_t)M_ * H_];
__device__ __half g_hk[(size_t)M_ * H_];
__device__ __half g_hv[(size_t)M_ * H_];
__device__ __half g_hwq[(size_t)H_ * H_];
__device__ __half g_hwk[(size_t)H_ * H_];
__device__ __half g_hwv[(size_t)H_ * H_];
__device__ __half g_hwo[(size_t)H_ * H_];
// projection outputs (f16) + ctx (f16)
__device__ __half g_qh[(size_t)M_ * H_];
__device__ __half g_kh[(size_t)M_ * H_];
__device__ __half g_vh[(size_t)M_ * H_];
__device__ __half g_ch[(size_t)M_ * H_];

// ---------------------------------------------------------------------------
// Warp-MMA helpers (portable ISA, plain sm_103 target)
// ---------------------------------------------------------------------------
__device__ __forceinline__ uint32_t smem_to_u32(const void* p) {
    uint32_t a;
    asm("{ .reg .u64 t; cvta.to.shared.u64 t, %1; cvt.u32.u64 %0, t; }"
        : "=r"(a) : "l"(p));
    return a;
}
__device__ __forceinline__ void ldsm_x4(uint32_t r[4], uint32_t a) {
    asm volatile("ldmatrix.sync.aligned.m8n8.x4.shared.b16 {%0,%1,%2,%3}, [%4];"
                 : "=r"(r[0]), "=r"(r[1]), "=r"(r[2]), "=r"(r[3]) : "r"(a));
}
__device__ __forceinline__ void ldsm_x2(uint32_t r[2], uint32_t a) {
    asm volatile("ldmatrix.sync.aligned.m8n8.x2.shared.b16 {%0,%1}, [%2];"
                 : "=r"(r[0]), "=r"(r[1]) : "r"(a));
}
__device__ __forceinline__ void ldsm_x2_trans(uint32_t r[2], uint32_t a) {
    asm volatile("ldmatrix.sync.aligned.m8n8.x2.trans.shared.b16 {%0,%1}, [%2];"
                 : "=r"(r[0]), "=r"(r[1]) : "r"(a));
}
__device__ __forceinline__ void mma_f16(float c[4], const uint32_t a[4],
                                        const uint32_t b[2]) {
    asm volatile(
        "mma.sync.aligned.m16n8k16.row.col.f32.f16.f16.f32 "
        "{%0,%1,%2,%3}, {%4,%5,%6,%7}, {%8,%9}, {%0,%1,%2,%3};"
        : "+f"(c[0]), "+f"(c[1]), "+f"(c[2]), "+f"(c[3])
        : "r"(a[0]), "r"(a[1]), "r"(a[2]), "r"(a[3]), "r"(b[0]), "r"(b[1]));
}
__device__ __forceinline__ void cp_async16(uint32_t saddr, const void* gptr) {
    asm volatile("cp.async.cg.shared.global [%0], [%1], 16;"
                 :: "r"(saddr), "l"(gptr));
}
#define CP_COMMIT() asm volatile("cp.async.commit_group;" ::: "memory")
#define CP_WAIT1()  asm volatile("cp.async.wait_group 1;" ::: "memory")
#define CP_WAIT0()  asm volatile("cp.async.wait_group 0;" ::: "memory")

// ---------------------------------------------------------------------------
// Mask normalization -> float (-1e30 / 0) form
// ---------------------------------------------------------------------------
__global__ void mask_normalize(const unsigned int* __restrict__ w)
{
    __shared__ unsigned int flags;
    const int tid = threadIdx.x;
    if (tid == 0) flags = 0u;
    __syncthreads();
    const unsigned int x = w[tid];
    unsigned int f = 0u;
    if (x != 0u && x != 1u && x != 0x3F800000u) f |= 1u;
    if (x == 0x3F800000u) f |= 2u;
    if (f) atomicOr(&flags, f);
    __syncthreads();
    const int byte_mode = (flags & 1u) ? 1 : 0;
    if (byte_mode) {
        const unsigned char* b8 = (const unsigned char*)w;
        for (int i = tid; i < B_ * S_; i += 1024)
            g_maskf[i] = (b8[i] != 0) ? -1e30f : 0.0f;
    } else {
        for (int i = tid; i < B_ * S_; i += 1024)
            g_maskf[i] = (w[i] != 0u) ? -1e30f : 0.0f;
    }
}

// ---------------------------------------------------------------------------
// Convert all GEMM operands fp32 -> f16 (single launch).
// 1024 elems per block: 3 x 4096 blocks (q,k,v) + 4 x 1024 (weights)
// ---------------------------------------------------------------------------
__global__ __launch_bounds__(256) void convert_all(
    const float* __restrict__ q, const float* __restrict__ k,
    const float* __restrict__ v, const float* __restrict__ wq,
    const float* __restrict__ wk, const float* __restrict__ wv,
    const float* __restrict__ wo)
{
    const int blk = blockIdx.x;
    const float* src;
    __half* dst;
    int base;
    if (blk < 4096)        { src = q;  dst = g_hq;  base = blk; }
    else if (blk < 8192)   { src = k;  dst = g_hk;  base = blk - 4096; }
    else if (blk < 12288)  { src = v;  dst = g_hv;  base = blk - 8192; }
    else if (blk < 13312)  { src = wq; dst = g_hwq; base = blk - 12288; }
    else if (blk < 14336)  { src = wk; dst = g_hwk; base = blk - 13312; }
    else if (blk < 15360)  { src = wv; dst = g_hwv; base = blk - 14336; }
    else                   { src = wo; dst = g_hwo; base = blk - 15360; }

    const int i = (base * 256 + threadIdx.x) * 4;
    const float4 x = *(const float4*)&src[i];
    uint2 o;
    __half2 lo = __floats2half2_rn(x.x, x.y);
    __half2 hi = __floats2half2_rn(x.z, x.w);
    o.x = *(uint32_t*)&lo;
    o.y = *(uint32_t*)&hi;
    *(uint2*)&dst[i] = o;
}

// ---------------------------------------------------------------------------
// FP16 HMMA GEMM (NT): C[M,N] = A[M,K] @ W[N,K]^T + bias  (fp32 accumulate)
// Operands f16 in gmem -> cp.async raw staging. 128x128 CTA tile, BK=64,
// 8 warps (2x4), warp tile 64x32 (4 m16 x 4 n8 x 4 k16). Double-buffered.
// Modes: 0 = fp32*scale to C; 2 = f16*scale to Of.
// Rows: 64 halfs = 128 B data, stride 144 B (16B-aligned, conflict-free).
// ---------------------------------------------------------------------------
constexpr int GSTRB  = 144;                   // bytes per smem row
constexpr int GTILEB = 128 * GSTRB;           // 18432 B per tile
constexpr int GBUFB  = 2 * GTILEB;            // A + W per stage
constexpr int GEMM_SMEM = 2 * GBUFB;          // 73728 B

__global__ __launch_bounds__(256, 2) void gemm_f16(
    const __half* __restrict__ A, const __half* __restrict__ W,
    const float* __restrict__ bias, float* __restrict__ C,
    __half* __restrict__ Of, int mode, float scale, int K)
{
    extern __shared__ char smem[];
    const uint32_t smem_u = smem_to_u32(smem);
    const int tid  = threadIdx.x;
    const int wid  = tid >> 5;
    const int lane = tid & 31;
    const int warp_m = wid >> 2;
    const int warp_n = wid & 3;
    const int m0 = blockIdx.y * 128;
    const int n0 = blockIdx.x * 128;

    float c[4][4][4];
    #pragma unroll
    for (int i = 0; i < 4; i++)
        #pragma unroll
        for (int j = 0; j < 4; j++)
            #pragma unroll
            for (int r = 0; r < 4; r++) c[i][j][r] = 0.0f;

    const int NS = K / 64;   // 16 stages

    // cp.async staging: 2 tiles x 128 rows x 8 chunks = 2048, 8 per thread
    auto issue_stage = [&](int s, int buf) {
        const int k0 = s * 64;
        const uint32_t base = smem_u + buf * GBUFB;
        #pragma unroll
        for (int t = 0; t < 8; t++) {
            const int idx = t * 256 + tid;
            const int tile = idx >> 10;            // 0=A, 1=W
            const int within = idx & 1023;
            const int row = within >> 3;
            const int ch = within & 7;
            const __half* src = tile ? (W + (size_t)(n0 + row) * K)
                                     : (A + (size_t)(m0 + row) * K);
            cp_async16(base + tile * GTILEB + row * GSTRB + ch * 16,
                       src + k0 + ch * 8);
        }
    };

    issue_stage(0, 0);
    CP_COMMIT();

    const uint32_t a_rowoff = (uint32_t)(lane & 15) * GSTRB;
    const uint32_t a_koff   = (uint32_t)(lane >> 4) * 16;
    const uint32_t b_rowoff = (uint32_t)(lane & 7) * GSTRB;
    const uint32_t b_koff   = (uint32_t)((lane >> 3) & 1) * 16;

    for (int s = 0; s < NS; s++) {
        if (s + 1 < NS) {
            issue_stage(s + 1, (s + 1) & 1);
            CP_COMMIT();
            CP_WAIT1();
        } else {
            CP_WAIT0();
        }
        __syncthreads();

        const uint32_t base = smem_u + (s & 1) * GBUFB;
        const uint32_t sA = base;
        const uint32_t sW = base + GTILEB;

        #pragma unroll
        for (int ks = 0; ks < 4; ks++) {
            const uint32_t kb = ks * 32;           // 16 halfs = 32 B
            uint32_t a[4][4], b[4][2];
            #pragma unroll
            for (int i = 0; i < 4; i++)
                ldsm_x4(a[i], sA + (warp_m * 64 + i * 16) * GSTRB +
                              a_rowoff + kb + a_koff);
            #pragma unroll
            for (int j = 0; j < 4; j++)
                ldsm_x2(b[j], sW + (warp_n * 32 + j * 8) * GSTRB +
                              b_rowoff + kb + b_koff);
            #pragma unroll
            for (int i = 0; i < 4; i++)
                #pragma unroll
                for (int j = 0; j < 4; j++)
                    mma_f16(c[i][j], a[i], b[j]);
        }
        __syncthreads();
    }

    const int trow = lane >> 2;
    const int tcol = (lane & 3) * 2;
    #pragma unroll
    for (int i = 0; i < 4; i++) {
        const int r0 = m0 + warp_m * 64 + i * 16 + trow;
        #pragma unroll
        for (int j = 0; j < 4; j++) {
            const int cc = n0 + warp_n * 32 + j * 8 + tcol;
            const float b0 = bias[cc];
            const float b1 = bias[cc + 1];
            const float v00 = (c[i][j][0] + b0) * scale;
            const float v01 = (c[i][j][1] + b1) * scale;
            const float v10 = (c[i][j][2] + b0) * scale;
            const float v11 = (c[i][j][3] + b1) * scale;
            const size_t p0 = (size_t)r0 * 1024 + cc;
            const size_t p1 = (size_t)(r0 + 8) * 1024 + cc;
            if (mode == 0) {
                *(float2*)&C[p0] = make_float2(v00, v01);
                *(float2*)&C[p1] = make_float2(v10, v11);
            } else {
                *(__half2*)&Of[p0] = __floats2half2_rn(v00, v01);
                *(__half2*)&Of[p1] = __floats2half2_rn(v10, v11);
            }
        }
    }
}

// ---------------------------------------------------------------------------
// FP16 FlashAttention: BQ=128, BK=64, 8 warps (16 q-rows each).
// Q staged once (f16). K/V double-buffered via cp.async. P in registers.
// All MMAs f16 with fp32 accumulate; softmax fp32; ctx written f16.
// ---------------------------------------------------------------------------
constexpr int ASTRB = 144;                // bytes per smem row (64 halfs + pad)
constexpr int QTILE = 128 * ASTRB;        // 18432 B
constexpr int KTILE = 64 * ASTRB;         // 9216 B
constexpr int VTILE = 64 * ASTRB;         // 9216 B
constexpr int KVBUF = KTILE + VTILE;      // 18432 B
constexpr int SQ  = 0;
constexpr int SKV = QTILE;
constexpr int ATTN_SMEM = QTILE + 2 * KVBUF;   // 55296 B

__global__ __launch_bounds__(256, 2) void attn_f16(
    const __half* __restrict__ qh, const __half* __restrict__ kh,
    const __half* __restrict__ vh, const float* __restrict__ maskf,
    const float* __restrict__ bias, __half* __restrict__ ctxo)
{
    extern __shared__ char smem[];
    const uint32_t su = smem_to_u32(smem);
    const int tid = threadIdx.x;
    const int wid = tid >> 5;
    const int lane = tid & 31;
    const int g = lane >> 2;
    const int tig = lane & 3;
    const int q0 = blockIdx.x * 128;
    const int h = blockIdx.y;
    const int b = blockIdx.z;

    // K/V stage: 2 x 64 rows x 8 chunks = 1024 chunks, 4 per thread
    auto issue_kv = [&](int kt, int buf) {
        const int k0 = kt * 64;
        const uint32_t kbase = su + SKV + buf * KVBUF;
        #pragma unroll
        for (int t = 0; t < 4; t++) {
            const int idx = t * 256 + tid;
            const int tile = idx >> 9;             // 0=K, 1=V
            const int within = idx & 511;
            const int row = within >> 3;
            const int ch = within & 7;
            const __half* src = (tile ? vh : kh) +
                ((size_t)(b * S_ + k0 + row)) * H_ + h * HD_ + ch * 8;
            cp_async16(kbase + tile * KTILE + row * ASTRB + ch * 16, src);
        }
    };

    issue_kv(0, 0);
    CP_COMMIT();

    // Stage Q (f16 raw copy): 128 rows x 8 chunks = 1024, 4/thread
    #pragma unroll
    for (int t = 0; t < 4; t++) {
        const int idx = t * 256 + tid;
        const int row = idx >> 3;
        const int ch = idx & 7;
        *(uint4*)(smem + SQ + row * ASTRB + ch * 16) =
            *(const uint4*)
            &qh[((size_t)(b * S_ + q0 + row)) * H_ + h * HD_ + ch * 8];
    }

    float ctx[8][4];
    #pragma unroll
    for (int j = 0; j < 8; j++)
        #pragma unroll
        for (int r = 0; r < 4; r++) ctx[j][r] = 0.0f;
    float m0_ = -1e30f, m1_ = -1e30f, l0_ = 0.0f, l1_ = 0.0f;

    const uint32_t a_rowoff = (uint32_t)(wid * 16 + (lane & 15)) * ASTRB;
    const uint32_t a_koff   = (uint32_t)(lane >> 4) * 16;
    const uint32_t b_rowoff = (uint32_t)(lane & 7) * ASTRB;
    const uint32_t b_koff   = (uint32_t)((lane >> 3) & 1) * 16;
    const uint32_t v_rowoff = (uint32_t)(lane & 15) * ASTRB;

    const int qg0 = q0 + wid * 16 + g;
    const size_t bias_row0 = ((size_t)h * S_ + qg0) * S_ + 2 * tig;
    const size_t bias_row1 = bias_row0 + 8 * S_;

    constexpr int NT = S_ / 64;   // 32
    for (int kt = 0; kt < NT; kt++) {
        const int k0 = kt * 64;
        __syncthreads();
        if (kt + 1 < NT) issue_kv(kt + 1, (kt + 1) & 1);
        CP_COMMIT();
        CP_WAIT1();
        __syncthreads();

        const uint32_t sk = su + SKV + (kt & 1) * KVBUF;
        const uint32_t sv = sk + KTILE;

        // ---- S = Q·K^T (f16, fp32 accum) ----
        float c[8][4];
        #pragma unroll
        for (int j = 0; j < 8; j++)
            #pragma unroll
            for (int r = 0; r < 4; r++) c[j][r] = 0.0f;

        #pragma unroll
        for (int ks = 0; ks < 4; ks++) {
            const uint32_t kb = ks * 32;
            uint32_t aq[4];
            ldsm_x4(aq, su + SQ + a_rowoff + kb + a_koff);
            #pragma unroll
            for (int j = 0; j < 8; j++) {
                uint32_t bk[2];
                ldsm_x2(bk, sk + (uint32_t)(j * 8) * ASTRB +
                            b_rowoff + kb + b_koff);
                mma_f16(c[j], aq, bk);
            }
        }

        // ---- bias + mask ----
        #pragma unroll
        for (int j = 0; j < 8; j++) {
            const float2 mk = *(const float2*)&maskf[b * S_ + k0 + j * 8 + 2 * tig];
            const float2 b0 = *(const float2*)&bias[bias_row0 + k0 + j * 8];
            const float2 b1 = *(const float2*)&bias[bias_row1 + k0 + j * 8];
            c[j][0] += b0.x + mk.x;
            c[j][1] += b0.y + mk.y;
            c[j][2] += b1.x + mk.x;
            c[j][3] += b1.y + mk.y;
        }

        // ---- online softmax ----
        float mx0 = -1e30f, mx1 = -1e30f;
        #pragma unroll
        for (int j = 0; j < 8; j++) {
            mx0 = fmaxf(mx0, fmaxf(c[j][0], c[j][1]));
            mx1 = fmaxf(mx1, fmaxf(c[j][2], c[j][3]));
        }
        mx0 = fmaxf(mx0, __shfl_xor_sync(0xffffffffu, mx0, 1));
        mx0 = fmaxf(mx0, __shfl_xor_sync(0xffffffffu, mx0, 2));
        mx1 = fmaxf(mx1, __shfl_xor_sync(0xffffffffu, mx1, 1));
        mx1 = fmaxf(mx1, __shfl_xor_sync(0xffffffffu, mx1, 2));

        const float mo0 = m0_, mo1 = m1_;
        m0_ = fmaxf(m0_, mx0);
        m1_ = fmaxf(m1_, mx1);
        const float alpha0 = __expf(mo0 - m0_);
        const float alpha1 = __expf(mo1 - m1_);

        float sum0 = 0.0f, sum1 = 0.0f;
        uint32_t ap[4][4];
        #pragma unroll
        for (int j = 0; j < 8; j++) {
            c[j][0] = __expf(c[j][0] - m0_);
            c[j][1] = __expf(c[j][1] - m0_);
            c[j][2] = __expf(c[j][2] - m1_);
            c[j][3] = __expf(c[j][3] - m1_);
            sum0 += c[j][0] + c[j][1];
            sum1 += c[j][2] + c[j][3];
        }
        l0_ = l0_ * alpha0 + sum0;
        l1_ = l1_ * alpha1 + sum1;

        #pragma unroll
        for (int t = 0; t < 4; t++) {
            __half2 h0 = __floats2half2_rn(c[2 * t][0], c[2 * t][1]);
            __half2 h1 = __floats2half2_rn(c[2 * t][2], c[2 * t][3]);
            __half2 h2 = __floats2half2_rn(c[2 * t + 1][0], c[2 * t + 1][1]);
            __half2 h3 = __floats2half2_rn(c[2 * t + 1][2], c[2 * t + 1][3]);
            ap[t][0] = *(uint32_t*)&h0;
            ap[t][1] = *(uint32_t*)&h1;
            ap[t][2] = *(uint32_t*)&h2;
            ap[t][3] = *(uint32_t*)&h3;
        }

        #pragma unroll
        for (int j = 0; j < 8; j++) {
            ctx[j][0] *= alpha0;
            ctx[j][1] *= alpha0;
            ctx[j][2] *= alpha1;
            ctx[j][3] *= alpha1;
        }

        // ---- ctx += P·V (f16) ----
        #pragma unroll
        for (int t = 0; t < 4; t++) {
            const uint32_t vbase = sv + (uint32_t)(t * 16) * ASTRB + v_rowoff;
            #pragma unroll
            for (int jd = 0; jd < 8; jd++) {
                uint32_t bv[2];
                ldsm_x2_trans(bv, vbase + jd * 16);
                mma_f16(ctx[jd], ap[t], bv);
            }
        }
    }

    l0_ += __shfl_xor_sync(0xffffffffu, l0_, 1);
    l0_ += __shfl_xor_sync(0xffffffffu, l0_, 2);
    l1_ += __shfl_xor_sync(0xffffffffu, l1_, 1);
    l1_ += __shfl_xor_sync(0xffffffffu, l1_, 2);
    const float inv0 = 1.0f / fmaxf(l0_, 1e-6f);
    const float inv1 = 1.0f / fmaxf(l1_, 1e-6f);

    // ctx written as f16 (consumed directly by o-projection)
    const size_t orow0 = ((size_t)(b * S_ + qg0)) * H_ + h * HD_ + 2 * tig;
    const size_t orow1 = orow0 + 8 * H_;
    #pragma unroll
    for (int jd = 0; jd < 8; jd++) {
        *(__half2*)&ctxo[orow0 + jd * 8] =
            __floats2half2_rn(ctx[jd][0] * inv0, ctx[jd][1] * inv0);
        *(__half2*)&ctxo[orow1 + jd * 8] =
            __floats2half2_rn(ctx[jd][2] * inv1, ctx[jd][3] * inv1);
    }
}

// ---------------------------------------------------------------------------
// Launch
// ---------------------------------------------------------------------------
extern "C" void kernel_launch(void* const* d_in, const int* in_sizes, int n_in,
                              void* d_out, int out_size)
{
    (void)in_sizes; (void)n_in; (void)out_size;

    const float* query = (const float*)d_in[0];
    const float* key_t = (const float*)d_in[1];
    const float* value = (const float*)d_in[2];
    const unsigned int* kpm_raw = (const unsigned int*)d_in[3];
    const float* bias  = (const float*)d_in[4];
    const float* q_w = (const float*)d_in[5];
    const float* q_b = (const float*)d_in[6];
    const float* k_w = (const float*)d_in[7];
    const float* k_b = (const float*)d_in[8];
    const float* v_w = (const float*)d_in[9];
    const float* v_b = (const float*)d_in[10];
    const float* o_w = (const float*)d_in[11];
    const float* o_b = (const float*)d_in[12];
    float* out = (float*)d_out;

    float* gmaskf;
    __half *ghq, *ghk, *ghv, *ghwq, *ghwk, *ghwv, *ghwo;
    __half *gqh, *gkh, *gvh, *gch;
    cudaGetSymbolAddress((void**)&gmaskf, g_maskf);
    cudaGetSymbolAddress((void**)&ghq, g_hq);
    cudaGetSymbolAddress((void**)&ghk, g_hk);
    cudaGetSymbolAddress((void**)&ghv, g_hv);
    cudaGetSymbolAddress((void**)&ghwq, g_hwq);
    cudaGetSymbolAddress((void**)&ghwk, g_hwk);
    cudaGetSymbolAddress((void**)&ghwv, g_hwv);
    cudaGetSymbolAddress((void**)&ghwo, g_hwo);
    cudaGetSymbolAddress((void**)&gqh, g_qh);
    cudaGetSymbolAddress((void**)&gkh, g_kh);
    cudaGetSymbolAddress((void**)&gvh, g_vh);
    cudaGetSymbolAddress((void**)&gch, g_ch);

    cudaFuncSetAttribute(gemm_f16,
                         cudaFuncAttributeMaxDynamicSharedMemorySize, GEMM_SMEM);
    cudaFuncSetAttribute(attn_f16,
                         cudaFuncAttributeMaxDynamicSharedMemorySize, ATTN_SMEM);

    mask_normalize<<<1, 1024>>>(kpm_raw);
    convert_all<<<16384, 256>>>(query, key_t, value, q_w, k_w, v_w, o_w);

    const dim3 gemm_grid(H_ / 128, M_ / 128);   // (8, 32)

    // Q projection -> f16 (pre-scaled by 1/sqrt(HD))
    gemm_f16<<<gemm_grid, 256, GEMM_SMEM>>>(ghq, ghwq, q_b, nullptr, gqh,
                                            2, 0.125f, H_);
    // K projection -> f16
    gemm_f16<<<gemm_grid, 256, GEMM_SMEM>>>(ghk, ghwk, k_b, nullptr, gkh,
                                            2, 1.0f, H_);
    // V projection -> f16
    gemm_f16<<<gemm_grid, 256, GEMM_SMEM>>>(ghv, ghwv, v_b, nullptr, gvh,
                                            2, 1.0f, H_);

    attn_f16<<<dim3(S_ / 128, NH_, B_), 256, ATTN_SMEM>>>(
        gqh, gkh, gvh, gmaskf, bias, gch);

    // Output projection (ctx f16 from attention epilogue) -> fp32 out
    gemm_f16<<<gemm_grid, 256, GEMM_SMEM>>>(gch, ghwo, o_b, out, nullptr,
                                            0, 1.0f, H_);
}

// round 12
// speedup vs baseline: 6.0416x; 1.0406x over previous
#include <cuda_runtime.h>
#include <cuda_bf16.h>
#include <cuda_fp16.h>
#include <cstdint>
#include <cstddef>

// Problem constants
constexpr int B_  = 2;
constexpr int S_  = 2048;
constexpr int H_  = 1024;
constexpr int NH_ = 16;
constexpr int HD_ = 64;
constexpr int M_  = B_ * S_;   // 4096

// Scratch (allocation-free: __device__ globals)
__device__ float g_maskf[B_ * S_];
__device__ __half g_hq[(size_t)M_ * H_];
__device__ __half g_hk[(size_t)M_ * H_];
__device__ __half g_hv[(size_t)M_ * H_];
__device__ __half g_hwq[(size_t)H_ * H_];
__device__ __half g_hwk[(size_t)H_ * H_];
__device__ __half g_hwv[(size_t)H_ * H_];
__device__ __half g_hwo[(size_t)H_ * H_];
__device__ __half g_qh[(size_t)M_ * H_];
__device__ __half g_kh[(size_t)M_ * H_];
__device__ __half g_vh[(size_t)M_ * H_];
__device__ __half g_ch[(size_t)M_ * H_];

// ---------------------------------------------------------------------------
// Warp-MMA helpers (portable ISA, plain sm_103 target)
// ---------------------------------------------------------------------------
__device__ __forceinline__ uint32_t smem_to_u32(const void* p) {
    uint32_t a;
    asm("{ .reg .u64 t; cvta.to.shared.u64 t, %1; cvt.u32.u64 %0, t; }"
        : "=r"(a) : "l"(p));
    return a;
}
__device__ __forceinline__ void ldsm_x4(uint32_t r[4], uint32_t a) {
    asm volatile("ldmatrix.sync.aligned.m8n8.x4.shared.b16 {%0,%1,%2,%3}, [%4];"
                 : "=r"(r[0]), "=r"(r[1]), "=r"(r[2]), "=r"(r[3]) : "r"(a));
}
__device__ __forceinline__ void ldsm_x2(uint32_t r[2], uint32_t a) {
    asm volatile("ldmatrix.sync.aligned.m8n8.x2.shared.b16 {%0,%1}, [%2];"
                 : "=r"(r[0]), "=r"(r[1]) : "r"(a));
}
__device__ __forceinline__ void ldsm_x2_trans(uint32_t r[2], uint32_t a) {
    asm volatile("ldmatrix.sync.aligned.m8n8.x2.trans.shared.b16 {%0,%1}, [%2];"
                 : "=r"(r[0]), "=r"(r[1]) : "r"(a));
}
__device__ __forceinline__ void mma_f16(float c[4], const uint32_t a[4],
                                        const uint32_t b[2]) {
    asm volatile(
        "mma.sync.aligned.m16n8k16.row.col.f32.f16.f16.f32 "
        "{%0,%1,%2,%3}, {%4,%5,%6,%7}, {%8,%9}, {%0,%1,%2,%3};"
        : "+f"(c[0]), "+f"(c[1]), "+f"(c[2]), "+f"(c[3])
        : "r"(a[0]), "r"(a[1]), "r"(a[2]), "r"(a[3]), "r"(b[0]), "r"(b[1]));
}
__device__ __forceinline__ void cp_async16(uint32_t saddr, const void* gptr) {
    asm volatile("cp.async.cg.shared.global [%0], [%1], 16;"
                 :: "r"(saddr), "l"(gptr));
}
#define CP_COMMIT() asm volatile("cp.async.commit_group;" ::: "memory")
#define CP_WAIT1()  asm volatile("cp.async.wait_group 1;" ::: "memory")
#define CP_WAIT0()  asm volatile("cp.async.wait_group 0;" ::: "memory")

// ---------------------------------------------------------------------------
// Mask normalization -> float (-1e30 / 0) form
// ---------------------------------------------------------------------------
__global__ void mask_normalize(const unsigned int* __restrict__ w)
{
    __shared__ unsigned int flags;
    const int tid = threadIdx.x;
    if (tid == 0) flags = 0u;
    __syncthreads();
    const unsigned int x = w[tid];
    unsigned int f = 0u;
    if (x != 0u && x != 1u && x != 0x3F800000u) f |= 1u;
    if (x == 0x3F800000u) f |= 2u;
    if (f) atomicOr(&flags, f);
    __syncthreads();
    const int byte_mode = (flags & 1u) ? 1 : 0;
    if (byte_mode) {
        const unsigned char* b8 = (const unsigned char*)w;
        for (int i = tid; i < B_ * S_; i += 1024)
            g_maskf[i] = (b8[i] != 0) ? -1e30f : 0.0f;
    } else {
        for (int i = tid; i < B_ * S_; i += 1024)
            g_maskf[i] = (w[i] != 0u) ? -1e30f : 0.0f;
    }
}

// ---------------------------------------------------------------------------
// Convert all GEMM operands fp32 -> f16 (single launch).
// ---------------------------------------------------------------------------
__global__ __launch_bounds__(256) void convert_all(
    const float* __restrict__ q, const float* __restrict__ k,
    const float* __restrict__ v, const float* __restrict__ wq,
    const float* __restrict__ wk, const float* __restrict__ wv,
    const float* __restrict__ wo)
{
    const int blk = blockIdx.x;
    const float* src;
    __half* dst;
    int base;
    if (blk < 4096)        { src = q;  dst = g_hq;  base = blk; }
    else if (blk < 8192)   { src = k;  dst = g_hk;  base = blk - 4096; }
    else if (blk < 12288)  { src = v;  dst = g_hv;  base = blk - 8192; }
    else if (blk < 13312)  { src = wq; dst = g_hwq; base = blk - 12288; }
    else if (blk < 14336)  { src = wk; dst = g_hwk; base = blk - 13312; }
    else if (blk < 15360)  { src = wv; dst = g_hwv; base = blk - 14336; }
    else                   { src = wo; dst = g_hwo; base = blk - 15360; }

    const int i = (base * 256 + threadIdx.x) * 4;
    const float4 x = *(const float4*)&src[i];
    uint2 o;
    __half2 lo = __floats2half2_rn(x.x, x.y);
    __half2 hi = __floats2half2_rn(x.z, x.w);
    o.x = *(uint32_t*)&lo;
    o.y = *(uint32_t*)&hi;
    *(uint2*)&dst[i] = o;
}

// ---------------------------------------------------------------------------
// FP16 HMMA GEMM (NT): C[M,N] = A[M,K] @ W[N,K]^T + bias  (fp32 accumulate)
// 3-stage cp.async pipeline, ONE __syncthreads per stage.
// Safety: at iter s, the post-wait barrier proves all warps finished
// compute(s-1) (readers of buf (s-1)%3 == (s+2)%3) before issue(s+2).
// ---------------------------------------------------------------------------
constexpr int GSTRB  = 144;                   // bytes per smem row
constexpr int GTILEB = 128 * GSTRB;           // 18432 B per tile
constexpr int GBUFB  = 2 * GTILEB;            // A + W per stage (36864)
constexpr int GEMM_SMEM = 3 * GBUFB;          // 110592 B

__global__ __launch_bounds__(256, 2) void gemm_f16(
    const __half* __restrict__ A, const __half* __restrict__ W,
    const float* __restrict__ bias, float* __restrict__ C,
    __half* __restrict__ Of, int mode, float scale, int K)
{
    extern __shared__ char smem[];
    const uint32_t smem_u = smem_to_u32(smem);
    const int tid  = threadIdx.x;
    const int wid  = tid >> 5;
    const int lane = tid & 31;
    const int warp_m = wid >> 2;
    const int warp_n = wid & 3;
    const int m0 = blockIdx.y * 128;
    const int n0 = blockIdx.x * 128;

    float c[4][4][4];
    #pragma unroll
    for (int i = 0; i < 4; i++)
        #pragma unroll
        for (int j = 0; j < 4; j++)
            #pragma unroll
            for (int r = 0; r < 4; r++) c[i][j][r] = 0.0f;

    const int NS = K / 64;   // 16 stages

    auto issue_stage = [&](int s, int buf) {
        const int k0 = s * 64;
        const uint32_t base = smem_u + buf * GBUFB;
        #pragma unroll
        for (int t = 0; t < 8; t++) {
            const int idx = t * 256 + tid;
            const int tile = idx >> 10;            // 0=A, 1=W
            const int within = idx & 1023;
            const int row = within >> 3;
            const int ch = within & 7;
            const __half* src = tile ? (W + (size_t)(n0 + row) * K)
                                     : (A + (size_t)(m0 + row) * K);
            cp_async16(base + tile * GTILEB + row * GSTRB + ch * 16,
                       src + k0 + ch * 8);
        }
    };

    issue_stage(0, 0); CP_COMMIT();
    issue_stage(1, 1); CP_COMMIT();

    const uint32_t a_rowoff = (uint32_t)(lane & 15) * GSTRB;
    const uint32_t a_koff   = (uint32_t)(lane >> 4) * 16;
    const uint32_t b_rowoff = (uint32_t)(lane & 7) * GSTRB;
    const uint32_t b_koff   = (uint32_t)((lane >> 3) & 1) * 16;

    for (int s = 0; s < NS; s++) {
        if (s < NS - 1) { CP_WAIT1(); } else { CP_WAIT0(); }
        __syncthreads();
        if (s + 2 < NS) {
            issue_stage(s + 2, (s + 2) % 3);
            CP_COMMIT();
        }

        const uint32_t base = smem_u + (s % 3) * GBUFB;
        const uint32_t sA = base;
        const uint32_t sW = base + GTILEB;

        #pragma unroll
        for (int ks = 0; ks < 4; ks++) {
            const uint32_t kb = ks * 32;           // 16 halfs = 32 B
            uint32_t a[4][4], b[4][2];
            #pragma unroll
            for (int i = 0; i < 4; i++)
                ldsm_x4(a[i], sA + (warp_m * 64 + i * 16) * GSTRB +
                              a_rowoff + kb + a_koff);
            #pragma unroll
            for (int j = 0; j < 4; j++)
                ldsm_x2(b[j], sW + (warp_n * 32 + j * 8) * GSTRB +
                              b_rowoff + kb + b_koff);
            #pragma unroll
            for (int i = 0; i < 4; i++)
                #pragma unroll
                for (int j = 0; j < 4; j++)
                    mma_f16(c[i][j], a[i], b[j]);
        }
    }

    const int trow = lane >> 2;
    const int tcol = (lane & 3) * 2;
    #pragma unroll
    for (int i = 0; i < 4; i++) {
        const int r0 = m0 + warp_m * 64 + i * 16 + trow;
        #pragma unroll
        for (int j = 0; j < 4; j++) {
            const int cc = n0 + warp_n * 32 + j * 8 + tcol;
            const float b0 = bias[cc];
            const float b1 = bias[cc + 1];
            const float v00 = (c[i][j][0] + b0) * scale;
            const float v01 = (c[i][j][1] + b1) * scale;
            const float v10 = (c[i][j][2] + b0) * scale;
            const float v11 = (c[i][j][3] + b1) * scale;
            const size_t p0 = (size_t)r0 * 1024 + cc;
            const size_t p1 = (size_t)(r0 + 8) * 1024 + cc;
            if (mode == 0) {
                *(float2*)&C[p0] = make_float2(v00, v01);
                *(float2*)&C[p1] = make_float2(v10, v11);
            } else {
                *(__half2*)&Of[p0] = __floats2half2_rn(v00, v01);
                *(__half2*)&Of[p1] = __floats2half2_rn(v10, v11);
            }
        }
    }
}

// ---------------------------------------------------------------------------
// FP16 FlashAttention: BQ=128, BK=64, 8 warps (16 q-rows each).
// Grid = (B, NH, S/128): batch pairs are adjacent bids -> bias L2 reuse.
// 3-stage cp.async K/V pipeline, one __syncthreads per stage.
// ---------------------------------------------------------------------------
constexpr int ASTRB = 144;                // bytes per smem row (64 halfs + pad)
constexpr int QTILE = 128 * ASTRB;        // 18432 B
constexpr int KTILE = 64 * ASTRB;         // 9216 B
constexpr int VTILE = 64 * ASTRB;         // 9216 B
constexpr int KVBUF = KTILE + VTILE;      // 18432 B
constexpr int SQ  = 0;
constexpr int SKV = QTILE;
constexpr int ATTN_SMEM = QTILE + 3 * KVBUF;   // 73728 B

__global__ __launch_bounds__(256, 2) void attn_f16(
    const __half* __restrict__ qh, const __half* __restrict__ kh,
    const __half* __restrict__ vh, const float* __restrict__ maskf,
    const float* __restrict__ bias, __half* __restrict__ ctxo)
{
    extern __shared__ char smem[];
    const uint32_t su = smem_to_u32(smem);
    const int tid = threadIdx.x;
    const int wid = tid >> 5;
    const int lane = tid & 31;
    const int g = lane >> 2;
    const int tig = lane & 3;
    const int b  = blockIdx.x;           // batch innermost: bias L2 sharing
    const int h  = blockIdx.y;
    const int q0 = blockIdx.z * 128;

    auto issue_kv = [&](int kt, int buf) {
        const int k0 = kt * 64;
        const uint32_t kbase = su + SKV + buf * KVBUF;
        #pragma unroll
        for (int t = 0; t < 4; t++) {
            const int idx = t * 256 + tid;
            const int tile = idx >> 9;             // 0=K, 1=V
            const int within = idx & 511;
            const int row = within >> 3;
            const int ch = within & 7;
            const __half* src = (tile ? vh : kh) +
                ((size_t)(b * S_ + k0 + row)) * H_ + h * HD_ + ch * 8;
            cp_async16(kbase + tile * KTILE + row * ASTRB + ch * 16, src);
        }
    };

    issue_kv(0, 0); CP_COMMIT();
    issue_kv(1, 1); CP_COMMIT();

    // Stage Q (f16 raw copy): 128 rows x 8 chunks = 1024, 4/thread
    #pragma unroll
    for (int t = 0; t < 4; t++) {
        const int idx = t * 256 + tid;
        const int row = idx >> 3;
        const int ch = idx & 7;
        *(uint4*)(smem + SQ + row * ASTRB + ch * 16) =
            *(const uint4*)
            &qh[((size_t)(b * S_ + q0 + row)) * H_ + h * HD_ + ch * 8];
    }

    float ctx[8][4];
    #pragma unroll
    for (int j = 0; j < 8; j++)
        #pragma unroll
        for (int r = 0; r < 4; r++) ctx[j][r] = 0.0f;
    float m0_ = -1e30f, m1_ = -1e30f, l0_ = 0.0f, l1_ = 0.0f;

    const uint32_t a_rowoff = (uint32_t)(wid * 16 + (lane & 15)) * ASTRB;
    const uint32_t a_koff   = (uint32_t)(lane >> 4) * 16;
    const uint32_t b_rowoff = (uint32_t)(lane & 7) * ASTRB;
    const uint32_t b_koff   = (uint32_t)((lane >> 3) & 1) * 16;
    const uint32_t v_rowoff = (uint32_t)(lane & 15) * ASTRB;

    const int qg0 = q0 + wid * 16 + g;
    const size_t bias_row0 = ((size_t)h * S_ + qg0) * S_ + 2 * tig;
    const size_t bias_row1 = bias_row0 + 8 * S_;

    constexpr int NT = S_ / 64;   // 32
    for (int kt = 0; kt < NT; kt++) {
        const int k0 = kt * 64;
        if (kt < NT - 1) { CP_WAIT1(); } else { CP_WAIT0(); }
        __syncthreads();
        if (kt + 2 < NT) {
            issue_kv(kt + 2, (kt + 2) % 3);
            CP_COMMIT();
        }

        const uint32_t sk = su + SKV + (kt % 3) * KVBUF;
        const uint32_t sv = sk + KTILE;

        // ---- S = Q·K^T (f16, fp32 accum) ----
        float c[8][4];
        #pragma unroll
        for (int j = 0; j < 8; j++)
            #pragma unroll
            for (int r = 0; r < 4; r++) c[j][r] = 0.0f;

        #pragma unroll
        for (int ks = 0; ks < 4; ks++) {
            const uint32_t kb = ks * 32;
            uint32_t aq[4];
            ldsm_x4(aq, su + SQ + a_rowoff + kb + a_koff);
            #pragma unroll
            for (int j = 0; j < 8; j++) {
                uint32_t bk[2];
                ldsm_x2(bk, sk + (uint32_t)(j * 8) * ASTRB +
                            b_rowoff + kb + b_koff);
                mma_f16(c[j], aq, bk);
            }
        }

        // ---- bias + mask ----
        #pragma unroll
        for (int j = 0; j < 8; j++) {
            const float2 mk = *(const float2*)&maskf[b * S_ + k0 + j * 8 + 2 * tig];
            const float2 b0 = *(const float2*)&bias[bias_row0 + k0 + j * 8];
            const float2 b1 = *(const float2*)&bias[bias_row1 + k0 + j * 8];
            c[j][0] += b0.x + mk.x;
            c[j][1] += b0.y + mk.y;
            c[j][2] += b1.x + mk.x;
            c[j][3] += b1.y + mk.y;
        }

        // ---- online softmax ----
        float mx0 = -1e30f, mx1 = -1e30f;
        #pragma unroll
        for (int j = 0; j < 8; j++) {
            mx0 = fmaxf(mx0, fmaxf(c[j][0], c[j][1]));
            mx1 = fmaxf(mx1, fmaxf(c[j][2], c[j][3]));
        }
        mx0 = fmaxf(mx0, __shfl_xor_sync(0xffffffffu, mx0, 1));
        mx0 = fmaxf(mx0, __shfl_xor_sync(0xffffffffu, mx0, 2));
        mx1 = fmaxf(mx1, __shfl_xor_sync(0xffffffffu, mx1, 1));
        mx1 = fmaxf(mx1, __shfl_xor_sync(0xffffffffu, mx1, 2));

        const float mo0 = m0_, mo1 = m1_;
        m0_ = fmaxf(m0_, mx0);
        m1_ = fmaxf(m1_, mx1);
        const float alpha0 = __expf(mo0 - m0_);
        const float alpha1 = __expf(mo1 - m1_);

        float sum0 = 0.0f, sum1 = 0.0f;
        uint32_t ap[4][4];
        #pragma unroll
        for (int j = 0; j < 8; j++) {
            c[j][0] = __expf(c[j][0] - m0_);
            c[j][1] = __expf(c[j][1] - m0_);
            c[j][2] = __expf(c[j][2] - m1_);
            c[j][3] = __expf(c[j][3] - m1_);
            sum0 += c[j][0] + c[j][1];
            sum1 += c[j][2] + c[j][3];
        }
        l0_ = l0_ * alpha0 + sum0;
        l1_ = l1_ * alpha1 + sum1;

        #pragma unroll
        for (int t = 0; t < 4; t++) {
            __half2 h0 = __floats2half2_rn(c[2 * t][0], c[2 * t][1]);
            __half2 h1 = __floats2half2_rn(c[2 * t][2], c[2 * t][3]);
            __half2 h2 = __floats2half2_rn(c[2 * t + 1][0], c[2 * t + 1][1]);
            __half2 h3 = __floats2half2_rn(c[2 * t + 1][2], c[2 * t + 1][3]);
            ap[t][0] = *(uint32_t*)&h0;
            ap[t][1] = *(uint32_t*)&h1;
            ap[t][2] = *(uint32_t*)&h2;
            ap[t][3] = *(uint32_t*)&h3;
        }

        #pragma unroll
        for (int j = 0; j < 8; j++) {
            ctx[j][0] *= alpha0;
            ctx[j][1] *= alpha0;
            ctx[j][2] *= alpha1;
            ctx[j][3] *= alpha1;
        }

        // ---- ctx += P·V (f16) ----
        #pragma unroll
        for (int t = 0; t < 4; t++) {
            const uint32_t vbase = sv + (uint32_t)(t * 16) * ASTRB + v_rowoff;
            #pragma unroll
            for (int jd = 0; jd < 8; jd++) {
                uint32_t bv[2];
                ldsm_x2_trans(bv, vbase + jd * 16);
                mma_f16(ctx[jd], ap[t], bv);
            }
        }
    }

    l0_ += __shfl_xor_sync(0xffffffffu, l0_, 1);
    l0_ += __shfl_xor_sync(0xffffffffu, l0_, 2);
    l1_ += __shfl_xor_sync(0xffffffffu, l1_, 1);
    l1_ += __shfl_xor_sync(0xffffffffu, l1_, 2);
    const float inv0 = 1.0f / fmaxf(l0_, 1e-6f);
    const float inv1 = 1.0f / fmaxf(l1_, 1e-6f);

    const size_t orow0 = ((size_t)(b * S_ + qg0)) * H_ + h * HD_ + 2 * tig;
    const size_t orow1 = orow0 + 8 * H_;
    #pragma unroll
    for (int jd = 0; jd < 8; jd++) {
        *(__half2*)&ctxo[orow0 + jd * 8] =
            __floats2half2_rn(ctx[jd][0] * inv0, ctx[jd][1] * inv0);
        *(__half2*)&ctxo[orow1 + jd * 8] =
            __floats2half2_rn(ctx[jd][2] * inv1, ctx[jd][3] * inv1);
    }
}

// ---------------------------------------------------------------------------
// Launch
// ---------------------------------------------------------------------------
extern "C" void kernel_launch(void* const* d_in, const int* in_sizes, int n_in,
                              void* d_out, int out_size)
{
    (void)in_sizes; (void)n_in; (void)out_size;

    const float* query = (const float*)d_in[0];
    const float* key_t = (const float*)d_in[1];
    const float* value = (const float*)d_in[2];
    const unsigned int* kpm_raw = (const unsigned int*)d_in[3];
    const float* bias  = (const float*)d_in[4];
    const float* q_w = (const float*)d_in[5];
    const float* q_b = (const float*)d_in[6];
    const float* k_w = (const float*)d_in[7];
    const float* k_b = (const float*)d_in[8];
    const float* v_w = (const float*)d_in[9];
    const float* v_b = (const float*)d_in[10];
    const float* o_w = (const float*)d_in[11];
    const float* o_b = (const float*)d_in[12];
    float* out = (float*)d_out;

    float* gmaskf;
    __half *ghq, *ghk, *ghv, *ghwq, *ghwk, *ghwv, *ghwo;
    __half *gqh, *gkh, *gvh, *gch;
    cudaGetSymbolAddress((void**)&gmaskf, g_maskf);
    cudaGetSymbolAddress((void**)&ghq, g_hq);
    cudaGetSymbolAddress((void**)&ghk, g_hk);
    cudaGetSymbolAddress((void**)&ghv, g_hv);
    cudaGetSymbolAddress((void**)&ghwq, g_hwq);
    cudaGetSymbolAddress((void**)&ghwk, g_hwk);
    cudaGetSymbolAddress((void**)&ghwv, g_hwv);
    cudaGetSymbolAddress((void**)&ghwo, g_hwo);
    cudaGetSymbolAddress((void**)&gqh, g_qh);
    cudaGetSymbolAddress((void**)&gkh, g_kh);
    cudaGetSymbolAddress((void**)&gvh, g_vh);
    cudaGetSymbolAddress((void**)&gch, g_ch);

    cudaFuncSetAttribute(gemm_f16,
                         cudaFuncAttributeMaxDynamicSharedMemorySize, GEMM_SMEM);
    cudaFuncSetAttribute(attn_f16,
                         cudaFuncAttributeMaxDynamicSharedMemorySize, ATTN_SMEM);

    mask_normalize<<<1, 1024>>>(kpm_raw);
    convert_all<<<16384, 256>>>(query, key_t, value, q_w, k_w, v_w, o_w);

    const dim3 gemm_grid(H_ / 128, M_ / 128);   // (8, 32)

    // Q projection -> f16 (pre-scaled by 1/sqrt(HD))
    gemm_f16<<<gemm_grid, 256, GEMM_SMEM>>>(ghq, ghwq, q_b, nullptr, gqh,
                                            2, 0.125f, H_);
    // K projection -> f16
    gemm_f16<<<gemm_grid, 256, GEMM_SMEM>>>(ghk, ghwk, k_b, nullptr, gkh,
                                            2, 1.0f, H_);
    // V projection -> f16
    gemm_f16<<<gemm_grid, 256, GEMM_SMEM>>>(ghv, ghwv, v_b, nullptr, gvh,
                                            2, 1.0f, H_);

    // Grid (B, NH, S/128): batch pairs adjacent -> bias read hits L2 on 2nd
    attn_f16<<<dim3(B_, NH_, S_ / 128), 256, ATTN_SMEM>>>(
        gqh, gkh, gvh, gmaskf, bias, gch);

    // Output projection (ctx f16 from attention epilogue) -> fp32 out
    gemm_f16<<<gemm_grid, 256, GEMM_SMEM>>>(gch, ghwo, o_b, out, nullptr,
                                            0, 1.0f, H_);
}